// round 4
// baseline (speedup 1.0000x reference)
#include <cuda_runtime.h>
#include <math.h>
#include <stdint.h>

// ---------------- Problem constants ----------------
#define NHEADS   128
#define DNOPE    128
#define DROPE    64
#define DQK      576
#define RKV      512
#define RQ       1536
#define HID      5120
#define QLEN     256
#define SLEN     4096
#define QB_COLS  24576
#define AO_COLS  16384
#define EPSF     1e-6f

// ---------------- Scratch (device globals) ----------------
__device__ __align__(128) float g_qa_buf [QLEN * RQ];
__device__ __align__(128) float g_qfull  [QLEN * QB_COLS];
__device__ __align__(128) float g_ckvraw [SLEN * DQK];
__device__ __align__(128) float g_Kc     [SLEN * DQK];
__device__ __align__(128) float g_Qc     [(size_t)NHEADS * QLEN * DQK];
__device__ __align__(128) float g_logits [(size_t)NHEADS * QLEN * SLEN];   // 512 MB
__device__ __align__(128) float g_oc     [(size_t)NHEADS * QLEN * RKV];
__device__ __align__(128) float g_ao     [QLEN * AO_COLS];

// ---------------- helpers ----------------
__device__ __forceinline__ uint32_t smem_u32(const void* p) {
    uint32_t a;
    asm("{ .reg .u64 t; cvta.to.shared.u64 t, %1; cvt.u32.u64 %0, t; }" : "=r"(a) : "l"(p));
    return a;
}
__device__ __forceinline__ uint32_t f2tf(float x) {
    uint32_t r;
    asm("cvt.rna.tf32.f32 %0, %1;" : "=r"(r) : "f"(x));
    return r;
}
__device__ __forceinline__ void mma8(float* d, const uint32_t* a, uint32_t b0, uint32_t b1) {
    asm volatile(
        "mma.sync.aligned.m16n8k8.row.col.f32.tf32.tf32.f32 "
        "{%0,%1,%2,%3},{%4,%5,%6,%7},{%8,%9},{%0,%1,%2,%3};"
        : "+f"(d[0]), "+f"(d[1]), "+f"(d[2]), "+f"(d[3])
        : "r"(a[0]), "r"(a[1]), "r"(a[2]), "r"(a[3]), "r"(b0), "r"(b1));
}
__device__ __forceinline__ void cp16(uint32_t dst, const void* src) {
    asm volatile("cp.async.cg.shared.global [%0], [%1], 16;" :: "r"(dst), "l"(src) : "memory");
}

// ---------------- tf32 mma.sync GEMM ----------------
// TRANSB=1: C = A @ B^T with B:[N,K] K-major (ldb over K).
// TRANSB=0: C = A @ B    with B:[K,N] N-major (ldb over N).
// A:[M,K] lda. BN = NT*32. K % 32 == 0. 8 warps: 2(m) x 4(n), warp tile 64 x BN/4.
// SPLIT=1: 3xTF32 error compensation (hi/lo), near-fp32 accuracy.
template<int NT, bool TRANSB, bool SPLIT>
__global__ void __launch_bounds__(256)
mma_gemm(const float* __restrict__ A, const float* __restrict__ B, float* __restrict__ C,
         int K, int lda, int ldb, int ldc, long sA, long sB, long sC)
{
    constexpr int BN = NT * 32;
    constexpr int APAD = 36;
    constexpr int A_STAGE = 128 * APAD;
    constexpr int BPADN = BN + 8;                       // NN smem row stride (BPADN%32==8)
    constexpr int B_STAGE = TRANSB ? BN * APAD : 32 * BPADN;
    constexpr int STAGES = 3;

    extern __shared__ float smf[];
    float* sAb = smf;
    float* sBb = smf + STAGES * A_STAGE;

    const int tid  = threadIdx.x;
    const int warp = tid >> 5;
    const int lane = tid & 31;
    const int wm = (warp >> 2) * 64;
    const int wn = (warp & 3) * (BN / 4);
    const int g  = lane >> 2;
    const int tq = lane & 3;

    const int bm = blockIdx.y * 128;
    const int bn = blockIdx.x * BN;
    A += (long)blockIdx.z * sA + (long)bm * lda;
    if (TRANSB) B += (long)blockIdx.z * sB + (long)bn * ldb;
    else        B += (long)blockIdx.z * sB + bn;
    C += (long)blockIdx.z * sC + (long)bm * ldc + bn;

    const int NC = K >> 5;

    float acc[4][NT][4];
#pragma unroll
    for (int i = 0; i < 4; i++)
#pragma unroll
        for (int j = 0; j < NT; j++)
#pragma unroll
            for (int l = 0; l < 4; l++) acc[i][j][l] = 0.f;

    auto load_stage = [&](int s, int stg) {
        const float* ga = A + s * 32;
        uint32_t da = smem_u32(sAb + stg * A_STAGE);
#pragma unroll
        for (int i = 0; i < 4; i++) {
            int idx = tid + i * 256;
            int r = idx >> 3, c4 = (idx & 7) << 2;
            cp16(da + (uint32_t)(r * APAD + c4) * 4, ga + (long)r * lda + c4);
        }
        uint32_t db = smem_u32(sBb + stg * B_STAGE);
        if (TRANSB) {
            const float* gb = B + s * 32;
#pragma unroll
            for (int i = 0; i < BN / 32; i++) {
                int idx = tid + i * 256;
                int r = idx >> 3, c4 = (idx & 7) << 2;
                cp16(db + (uint32_t)(r * APAD + c4) * 4, gb + (long)r * ldb + c4);
            }
        } else {
            const float* gb = B + (long)(s * 32) * ldb;
#pragma unroll
            for (int i = 0; i < BN / 32; i++) {
                int idx = tid + i * 256;
                int r = idx / (BN / 4), c4 = (idx % (BN / 4)) << 2;
                cp16(db + (uint32_t)(r * BPADN + c4) * 4, gb + (long)r * ldb + c4);
            }
        }
    };

#pragma unroll
    for (int s = 0; s < STAGES - 1; s++) {
        if (s < NC) load_stage(s, s);
        asm volatile("cp.async.commit_group;" ::: "memory");
    }

    for (int c = 0; c < NC; c++) {
        const int stg = c % STAGES;
        asm volatile("cp.async.wait_group %0;" :: "n"(STAGES - 2) : "memory");
        __syncthreads();

        const int pc = c + STAGES - 1;
        if (pc < NC) load_stage(pc, pc % STAGES);
        asm volatile("cp.async.commit_group;" ::: "memory");

        const float* As = sAb + stg * A_STAGE;
        const float* Bs = sBb + stg * B_STAGE;

#pragma unroll
        for (int kk = 0; kk < 4; kk++) {
            const int kc = kk * 8;
            uint32_t afh[4][4], afl[4][4];
#pragma unroll
            for (int mt = 0; mt < 4; mt++) {
                const int r0 = wm + mt * 16 + g;
                float x0 = As[r0 * APAD + kc + tq];
                float x1 = As[(r0 + 8) * APAD + kc + tq];
                float x2 = As[r0 * APAD + kc + tq + 4];
                float x3 = As[(r0 + 8) * APAD + kc + tq + 4];
                afh[mt][0] = f2tf(x0); afh[mt][1] = f2tf(x1);
                afh[mt][2] = f2tf(x2); afh[mt][3] = f2tf(x3);
                if (SPLIT) {
                    afl[mt][0] = f2tf(x0 - __uint_as_float(afh[mt][0]));
                    afl[mt][1] = f2tf(x1 - __uint_as_float(afh[mt][1]));
                    afl[mt][2] = f2tf(x2 - __uint_as_float(afh[mt][2]));
                    afl[mt][3] = f2tf(x3 - __uint_as_float(afh[mt][3]));
                }
            }
#pragma unroll
            for (int nt = 0; nt < NT; nt++) {
                const int n0 = wn + nt * 8 + g;
                float y0, y1;
                if (TRANSB) {
                    y0 = Bs[n0 * APAD + kc + tq];
                    y1 = Bs[n0 * APAD + kc + tq + 4];
                } else {
                    y0 = Bs[(kc + tq) * BPADN + n0];
                    y1 = Bs[(kc + tq + 4) * BPADN + n0];
                }
                uint32_t b0h = f2tf(y0), b1h = f2tf(y1);
                if (SPLIT) {
                    uint32_t b0l = f2tf(y0 - __uint_as_float(b0h));
                    uint32_t b1l = f2tf(y1 - __uint_as_float(b1h));
#pragma unroll
                    for (int mt = 0; mt < 4; mt++) {
                        mma8(acc[mt][nt], afh[mt], b0h, b1h);
                        mma8(acc[mt][nt], afl[mt], b0h, b1h);
                        mma8(acc[mt][nt], afh[mt], b0l, b1l);
                    }
                } else {
#pragma unroll
                    for (int mt = 0; mt < 4; mt++)
                        mma8(acc[mt][nt], afh[mt], b0h, b1h);
                }
            }
        }
    }

#pragma unroll
    for (int mt = 0; mt < 4; mt++) {
        const int r0 = wm + mt * 16 + g;
#pragma unroll
        for (int nt = 0; nt < NT; nt++) {
            const int c0 = wn + nt * 8 + tq * 2;
            *(float2*)&C[(long)r0 * ldc + c0]       = make_float2(acc[mt][nt][0], acc[mt][nt][1]);
            *(float2*)&C[(long)(r0 + 8) * ldc + c0] = make_float2(acc[mt][nt][2], acc[mt][nt][3]);
        }
    }
}

// ---------------- RMSNorm (in place) ----------------
__global__ void rmsnorm_rows(float* __restrict__ X, const float* __restrict__ g, int cols)
{
    const long row = blockIdx.x;
    float* x = X + row * (long)cols;
    const int tid = threadIdx.x;
    const int n4 = cols >> 2;
    float ss = 0.f;
    for (int c = tid; c < n4; c += blockDim.x) {
        float4 v = ((const float4*)x)[c];
        ss += v.x * v.x + v.y * v.y + v.z * v.z + v.w * v.w;
    }
    __shared__ float red[256];
    red[tid] = ss; __syncthreads();
    for (int s = 128; s > 0; s >>= 1) { if (tid < s) red[tid] += red[tid + s]; __syncthreads(); }
    const float inv = rsqrtf(red[0] / (float)cols + EPSF);
    for (int c = tid; c < n4; c += blockDim.x) {
        float4 v = ((const float4*)x)[c];
        float4 w = ((const float4*)g)[c];
        v.x *= inv * w.x; v.y *= inv * w.y; v.z *= inv * w.z; v.w *= inv * w.w;
        ((float4*)x)[c] = v;
    }
}

// ---------------- Build K_comb ----------------
__global__ void build_K(const float* __restrict__ raw, const float* __restrict__ g,
                        const int* __restrict__ kvpos, float* __restrict__ Kc)
{
    const int s = blockIdx.x;
    const float* r = raw + (long)s * DQK;
    float* k = Kc + (long)s * DQK;
    const int tid = threadIdx.x;   // 128

    float ss = 0.f;
    for (int c = tid; c < RKV / 4; c += 128) {
        float4 v = ((const float4*)r)[c];
        ss += v.x * v.x + v.y * v.y + v.z * v.z + v.w * v.w;
    }
    __shared__ float red[128];
    red[tid] = ss; __syncthreads();
    for (int st = 64; st > 0; st >>= 1) { if (tid < st) red[tid] += red[tid + st]; __syncthreads(); }
    const float inv = rsqrtf(red[0] / (float)RKV + EPSF);
    for (int c = tid; c < RKV / 4; c += 128) {
        float4 v = ((const float4*)r)[c];
        float4 w = ((const float4*)g)[c];
        v.x *= inv * w.x; v.y *= inv * w.y; v.z *= inv * w.z; v.w *= inv * w.w;
        ((float4*)k)[c] = v;
    }

    if (tid < 32) {
        const int j = tid;
        const float x0 = r[RKV + 2 * j];
        const float x1 = r[RKV + 2 * j + 1];
        const float pos = (float)kvpos[s];
        const float invf = powf(10000.f, -(float)j / 32.f);
        float cs, sn; sincosf(pos * invf, &sn, &cs);
        k[RKV + j]      = x0 * cs - x1 * sn;
        k[RKV + 32 + j] = x0 * sn + x1 * cs;
    }
}

// ---------------- RoPE for q_pe ----------------
__global__ void rope_Q(const float* __restrict__ qfull, const int* __restrict__ qpos,
                       float* __restrict__ Qc)
{
    const int t = blockIdx.x;
    const int h = blockIdx.y;
    const int j = threadIdx.x;   // 32
    const float* src = qfull + (long)t * QB_COLS + h * (DNOPE + DROPE) + DNOPE;
    const float x0 = src[2 * j];
    const float x1 = src[2 * j + 1];
    const float pos = (float)qpos[t];
    const float invf = powf(10000.f, -(float)j / 32.f);
    float cs, sn; sincosf(pos * invf, &sn, &cs);
    float* dst = Qc + ((long)h * QLEN + t) * DQK + RKV;
    dst[j]      = x0 * cs - x1 * sn;
    dst[32 + j] = x0 * sn + x1 * cs;
}

// ---------------- Row softmax (float4) ----------------
__global__ void softmax_rows(float* __restrict__ X, int cols, float scale)
{
    const long row = blockIdx.x;
    float4* x = (float4*)(X + row * (long)cols);
    const int n4 = cols >> 2;
    const int tid = threadIdx.x;   // 256
    __shared__ float red[256];

    float m = -INFINITY;
    for (int c = tid; c < n4; c += 256) {
        float4 v = x[c];
        m = fmaxf(m, fmaxf(fmaxf(v.x, v.y), fmaxf(v.z, v.w)));
    }
    red[tid] = m; __syncthreads();
    for (int s = 128; s > 0; s >>= 1) { if (tid < s) red[tid] = fmaxf(red[tid], red[tid + s]); __syncthreads(); }
    m = red[0]; __syncthreads();

    float sum = 0.f;
    for (int c = tid; c < n4; c += 256) {
        float4 v = x[c];
        v.x = __expf((v.x - m) * scale);
        v.y = __expf((v.y - m) * scale);
        v.z = __expf((v.z - m) * scale);
        v.w = __expf((v.w - m) * scale);
        x[c] = v;
        sum += v.x + v.y + v.z + v.w;
    }
    red[tid] = sum; __syncthreads();
    for (int s = 128; s > 0; s >>= 1) { if (tid < s) red[tid] += red[tid + s]; __syncthreads(); }
    const float invs = 1.f / red[0];
    for (int c = tid; c < n4; c += 256) {
        float4 v = x[c];
        v.x *= invs; v.y *= invs; v.z *= invs; v.w *= invs;
        x[c] = v;
    }
}

// ---------------- Launch ----------------
static inline float* sym(const void* s)
{
    void* p = nullptr;
    cudaGetSymbolAddress(&p, s);
    return (float*)p;
}

static inline int smem_bytes(int NT, bool transb) {
    int a = 128 * 36;
    int b = transb ? NT * 32 * 36 : 32 * (NT * 32 + 8);
    return 3 * (a + b) * 4;
}

extern "C" void kernel_launch(void* const* d_in, const int* in_sizes, int n_in,
                              void* d_out, int out_size)
{
    const float* hq    = (const float*)d_in[0];
    const float* hkv   = (const float*)d_in[1];
    const float* W_qa  = (const float*)d_in[2];
    const float* gqa   = (const float*)d_in[3];
    const float* W_qb  = (const float*)d_in[4];
    const float* W_kva = (const float*)d_in[5];
    const float* gkva  = (const float*)d_in[6];
    const float* W_kvb = (const float*)d_in[7];
    const float* W_o   = (const float*)d_in[8];
    const int*   qpos  = (const int*)d_in[9];
    const int*   kvpos = (const int*)d_in[10];
    float*       out   = (float*)d_out;

    float* qa     = sym(g_qa_buf);
    float* qfull  = sym(g_qfull);
    float* ckvraw = sym(g_ckvraw);
    float* Kc     = sym(g_Kc);
    float* Qc     = sym(g_Qc);
    float* logits = sym(g_logits);
    float* oc     = sym(g_oc);
    float* ao     = sym(g_ao);

    cudaFuncSetAttribute(mma_gemm<4, false, true>,  cudaFuncAttributeMaxDynamicSharedMemorySize, smem_bytes(4, false));
    cudaFuncSetAttribute(mma_gemm<6, false, true>,  cudaFuncAttributeMaxDynamicSharedMemorySize, smem_bytes(6, false));
    cudaFuncSetAttribute(mma_gemm<4, true,  true>,  cudaFuncAttributeMaxDynamicSharedMemorySize, smem_bytes(4, true));
    cudaFuncSetAttribute(mma_gemm<8, true,  false>, cudaFuncAttributeMaxDynamicSharedMemorySize, smem_bytes(8, true));
    cudaFuncSetAttribute(mma_gemm<8, false, false>, cudaFuncAttributeMaxDynamicSharedMemorySize, smem_bytes(8, false));

    // 1) qa = hq @ W_qa : (256,1536), K=5120  [NN split]
    mma_gemm<4, false, true><<<dim3(RQ / 128, 2, 1), 256, smem_bytes(4, false)>>>(
        hq, W_qa, qa, HID, HID, RQ, RQ, 0, 0, 0);

    // 2) rmsnorm(qa)
    rmsnorm_rows<<<QLEN, 256>>>(qa, gqa, RQ);

    // 3) qfull = qa @ W_qb : (256,24576), K=1536  [NN split]
    mma_gemm<4, false, true><<<dim3(QB_COLS / 128, 2, 1), 256, smem_bytes(4, false)>>>(
        qa, W_qb, qfull, RQ, RQ, QB_COLS, QB_COLS, 0, 0, 0);

    // 4) ckvraw = hkv @ W_kva : (4096,576), K=5120  [NN split]
    mma_gemm<6, false, true><<<dim3(DQK / 192, SLEN / 128, 1), 256, smem_bytes(6, false)>>>(
        hkv, W_kva, ckvraw, HID, HID, DQK, DQK, 0, 0, 0);

    // 5) K_comb
    build_K<<<SLEN, 128>>>(ckvraw, gkva, kvpos, Kc);

    // 6) q_c[h] = q_nope[h] @ q_absorb[h] : batched (256,512), K=128  [NN split]
    mma_gemm<4, false, true><<<dim3(RKV / 128, 2, NHEADS), 256, smem_bytes(4, false)>>>(
        qfull, W_kvb, Qc, DNOPE,
        QB_COLS, RKV, DQK,
        (long)(DNOPE + DROPE), (long)(DNOPE + DNOPE) * RKV, (long)QLEN * DQK);

    // 7) rope q_pe
    rope_Q<<<dim3(QLEN, NHEADS), 32>>>(qfull, qpos, Qc);

    // 8) logits[h] = Q_comb[h] @ K_comb^T : batched (256,4096), K=576  [NT single]
    mma_gemm<8, true, false><<<dim3(SLEN / 256, 2, NHEADS), 256, smem_bytes(8, true)>>>(
        Qc, Kc, logits, DQK,
        DQK, DQK, SLEN,
        (long)QLEN * DQK, 0, (long)QLEN * SLEN);

    // 9) softmax
    softmax_rows<<<NHEADS * QLEN, 256>>>(logits, SLEN, 1.0f / sqrtf(192.0f));

    // 10) oc[h] = P[h] @ ckv : batched (256,512), K=4096  [NN single; B=Kc cols 0..511]
    mma_gemm<8, false, false><<<dim3(RKV / 256, 2, NHEADS), 256, smem_bytes(8, false)>>>(
        logits, Kc, oc, SLEN,
        SLEN, DQK, RKV,
        (long)QLEN * SLEN, 0, (long)QLEN * RKV);

    // 11) ao[:, h*128:] = oc[h] @ out_absorb[h]^T : batched (256,128), K=512  [NT split]
    mma_gemm<4, true, true><<<dim3(1, 2, NHEADS), 256, smem_bytes(4, true)>>>(
        oc, W_kvb + (long)DNOPE * RKV, ao, RKV,
        RKV, RKV, AO_COLS,
        (long)QLEN * RKV, (long)(DNOPE + DNOPE) * RKV, (long)DNOPE);

    // 12) out = ao @ W_o : (256,5120), K=16384  [NN split]
    mma_gemm<4, false, true><<<dim3(HID / 128, 2, 1), 256, smem_bytes(4, false)>>>(
        ao, W_o, out, AO_COLS, AO_COLS, HID, HID, 0, 0, 0);
}

// round 5
// speedup vs baseline: 1.4002x; 1.4002x over previous
#include <cuda_runtime.h>
#include <math.h>
#include <stdint.h>

// ---------------- Problem constants ----------------
#define NHEADS   128
#define DNOPE    128
#define DROPE    64
#define DQK      576
#define RKV      512
#define RQ       1536
#define HID      5120
#define QLEN     256
#define SLEN     4096
#define QB_COLS  24576
#define AO_COLS  16384
#define EPSF     1e-6f

// ---------------- Scratch (device globals) ----------------
__device__ __align__(128) float g_qa_buf [QLEN * RQ];
__device__ __align__(128) float g_qfull  [QLEN * QB_COLS];
__device__ __align__(128) float g_ckvraw [SLEN * DQK];
__device__ __align__(128) float g_Kc     [SLEN * DQK];
__device__ __align__(128) float g_Qc     [(size_t)NHEADS * QLEN * DQK];
__device__ __align__(128) float g_logits [(size_t)NHEADS * QLEN * SLEN];   // 512 MB
__device__ __align__(128) float g_oc     [(size_t)NHEADS * QLEN * RKV];
__device__ __align__(128) float g_ao     [QLEN * AO_COLS];
__device__ __align__(128) float g_part   [8 * QLEN * HID];                  // split-K partials

// ---------------- helpers ----------------
__device__ __forceinline__ uint32_t smem_u32(const void* p) {
    uint32_t a;
    asm("{ .reg .u64 t; cvta.to.shared.u64 t, %1; cvt.u32.u64 %0, t; }" : "=r"(a) : "l"(p));
    return a;
}
__device__ __forceinline__ uint32_t f2tf(float x) {
    uint32_t r;
    asm("cvt.rna.tf32.f32 %0, %1;" : "=r"(r) : "f"(x));
    return r;
}
__device__ __forceinline__ uint32_t pack_bf16(float lo, float hi) {
    uint32_t r;
    asm("cvt.rn.bf16x2.f32 %0, %1, %2;" : "=r"(r) : "f"(hi), "f"(lo));
    return r;
}
__device__ __forceinline__ float bflo(uint32_t p) { return __uint_as_float(p << 16); }
__device__ __forceinline__ float bfhi(uint32_t p) { return __uint_as_float(p & 0xffff0000u); }

__device__ __forceinline__ void mma8(float* d, const uint32_t* a, uint32_t b0, uint32_t b1) {
    asm volatile(
        "mma.sync.aligned.m16n8k8.row.col.f32.tf32.tf32.f32 "
        "{%0,%1,%2,%3},{%4,%5,%6,%7},{%8,%9},{%0,%1,%2,%3};"
        : "+f"(d[0]), "+f"(d[1]), "+f"(d[2]), "+f"(d[3])
        : "r"(a[0]), "r"(a[1]), "r"(a[2]), "r"(a[3]), "r"(b0), "r"(b1));
}
__device__ __forceinline__ void mma16(float* d, const uint32_t* a, uint32_t b0, uint32_t b1) {
    asm volatile(
        "mma.sync.aligned.m16n8k16.row.col.f32.bf16.bf16.f32 "
        "{%0,%1,%2,%3},{%4,%5,%6,%7},{%8,%9},{%0,%1,%2,%3};"
        : "+f"(d[0]), "+f"(d[1]), "+f"(d[2]), "+f"(d[3])
        : "r"(a[0]), "r"(a[1]), "r"(a[2]), "r"(a[3]), "r"(b0), "r"(b1));
}
__device__ __forceinline__ void cp16(uint32_t dst, const void* src) {
    asm volatile("cp.async.cg.shared.global [%0], [%1], 16;" :: "r"(dst), "l"(src) : "memory");
}

// ---------------- mma.sync GEMM ----------------
// TRANSB=1: C = A @ B^T, B:[N,K] K-major (ldb over K).
// TRANSB=0: C = A @ B,   B:[K,N] N-major (ldb over N).
// A:[M,K] lda. BN = NT*32. K % 32 == 0. 8 warps: 2(m) x 4(n), warp tile 64 x BN/4.
// PREC=0: tf32 single pass. PREC=1: bf16 3-term hi/lo split (near-16-bit mantissa).
template<int NT, bool TRANSB, int PREC>
__global__ void __launch_bounds__(256)
mma_gemm(const float* __restrict__ A, const float* __restrict__ B, float* __restrict__ C,
         int K, int lda, int ldb, int ldc, long sA, long sB, long sC)
{
    constexpr int BN = NT * 32;
    constexpr int APAD = 36;
    constexpr int A_STAGE = 128 * APAD;
    constexpr int BPADN = BN + 8;
    constexpr int B_STAGE = TRANSB ? BN * APAD : 32 * BPADN;
    constexpr int STAGES = 3;

    extern __shared__ float smf[];
    float* sAb = smf;
    float* sBb = smf + STAGES * A_STAGE;

    const int tid  = threadIdx.x;
    const int warp = tid >> 5;
    const int lane = tid & 31;
    const int wm = (warp >> 2) * 64;
    const int wn = (warp & 3) * (BN / 4);
    const int g  = lane >> 2;
    const int tq = lane & 3;

    const int bm = blockIdx.y * 128;
    const int bn = blockIdx.x * BN;
    A += (long)blockIdx.z * sA + (long)bm * lda;
    if (TRANSB) B += (long)blockIdx.z * sB + (long)bn * ldb;
    else        B += (long)blockIdx.z * sB + bn;
    C += (long)blockIdx.z * sC + (long)bm * ldc + bn;

    const int NC = K >> 5;

    float acc[4][NT][4];
#pragma unroll
    for (int i = 0; i < 4; i++)
#pragma unroll
        for (int j = 0; j < NT; j++)
#pragma unroll
            for (int l = 0; l < 4; l++) acc[i][j][l] = 0.f;

    auto load_stage = [&](int s, int stg) {
        const float* ga = A + s * 32;
        uint32_t da = smem_u32(sAb + stg * A_STAGE);
#pragma unroll
        for (int i = 0; i < 4; i++) {
            int idx = tid + i * 256;
            int r = idx >> 3, c4 = (idx & 7) << 2;
            cp16(da + (uint32_t)(r * APAD + c4) * 4, ga + (long)r * lda + c4);
        }
        uint32_t db = smem_u32(sBb + stg * B_STAGE);
        if (TRANSB) {
            const float* gb = B + s * 32;
#pragma unroll
            for (int i = 0; i < BN / 32; i++) {
                int idx = tid + i * 256;
                int r = idx >> 3, c4 = (idx & 7) << 2;
                cp16(db + (uint32_t)(r * APAD + c4) * 4, gb + (long)r * ldb + c4);
            }
        } else {
            const float* gb = B + (long)(s * 32) * ldb;
#pragma unroll
            for (int i = 0; i < BN / 32; i++) {
                int idx = tid + i * 256;
                int r = idx / (BN / 4), c4 = (idx % (BN / 4)) << 2;
                cp16(db + (uint32_t)(r * BPADN + c4) * 4, gb + (long)r * ldb + c4);
            }
        }
    };

#pragma unroll
    for (int s = 0; s < STAGES - 1; s++) {
        if (s < NC) load_stage(s, s);
        asm volatile("cp.async.commit_group;" ::: "memory");
    }

    for (int c = 0; c < NC; c++) {
        const int stg = c % STAGES;
        asm volatile("cp.async.wait_group %0;" :: "n"(STAGES - 2) : "memory");
        __syncthreads();

        const int pc = c + STAGES - 1;
        if (pc < NC) load_stage(pc, pc % STAGES);
        asm volatile("cp.async.commit_group;" ::: "memory");

        const float* As = sAb + stg * A_STAGE;
        const float* Bs = sBb + stg * B_STAGE;

        if (PREC == 0) {
            // tf32 single pass: 4 x k8
#pragma unroll
            for (int kk = 0; kk < 4; kk++) {
                const int kc = kk * 8;
                uint32_t af[4][4];
#pragma unroll
                for (int mt = 0; mt < 4; mt++) {
                    const int r0 = wm + mt * 16 + g;
                    af[mt][0] = f2tf(As[r0 * APAD + kc + tq]);
                    af[mt][1] = f2tf(As[(r0 + 8) * APAD + kc + tq]);
                    af[mt][2] = f2tf(As[r0 * APAD + kc + tq + 4]);
                    af[mt][3] = f2tf(As[(r0 + 8) * APAD + kc + tq + 4]);
                }
#pragma unroll
                for (int nt = 0; nt < NT; nt++) {
                    const int n0 = wn + nt * 8 + g;
                    float y0, y1;
                    if (TRANSB) {
                        y0 = Bs[n0 * APAD + kc + tq];
                        y1 = Bs[n0 * APAD + kc + tq + 4];
                    } else {
                        y0 = Bs[(kc + tq) * BPADN + n0];
                        y1 = Bs[(kc + tq + 4) * BPADN + n0];
                    }
                    uint32_t b0 = f2tf(y0), b1 = f2tf(y1);
#pragma unroll
                    for (int mt = 0; mt < 4; mt++)
                        mma8(acc[mt][nt], af[mt], b0, b1);
                }
            }
        } else {
            // bf16 3-term split: 2 x k16
#pragma unroll
            for (int kk = 0; kk < 2; kk++) {
                const int kc = kk * 16;
                uint32_t ah[4][4], al[4][4];
#pragma unroll
                for (int mt = 0; mt < 4; mt++) {
                    const int r0 = wm + mt * 16 + g;
                    const float* pa = As + r0 * APAD + kc + 2 * tq;
                    const float* pb = As + (r0 + 8) * APAD + kc + 2 * tq;
                    float x00 = pa[0], x01 = pa[1];
                    float x10 = pb[0], x11 = pb[1];
                    float x20 = pa[8], x21 = pa[9];
                    float x30 = pb[8], x31 = pb[9];
                    ah[mt][0] = pack_bf16(x00, x01);
                    ah[mt][1] = pack_bf16(x10, x11);
                    ah[mt][2] = pack_bf16(x20, x21);
                    ah[mt][3] = pack_bf16(x30, x31);
                    al[mt][0] = pack_bf16(x00 - bflo(ah[mt][0]), x01 - bfhi(ah[mt][0]));
                    al[mt][1] = pack_bf16(x10 - bflo(ah[mt][1]), x11 - bfhi(ah[mt][1]));
                    al[mt][2] = pack_bf16(x20 - bflo(ah[mt][2]), x21 - bfhi(ah[mt][2]));
                    al[mt][3] = pack_bf16(x30 - bflo(ah[mt][3]), x31 - bfhi(ah[mt][3]));
                }
#pragma unroll
                for (int nt = 0; nt < NT; nt++) {
                    const int n0 = wn + nt * 8 + g;
                    float y00, y01, y10, y11;
                    if (TRANSB) {
                        const float* pb = Bs + n0 * APAD + kc + 2 * tq;
                        y00 = pb[0]; y01 = pb[1]; y10 = pb[8]; y11 = pb[9];
                    } else {
                        const float* pb = Bs + (kc + 2 * tq) * BPADN + n0;
                        y00 = pb[0]; y01 = pb[BPADN];
                        y10 = pb[8 * BPADN]; y11 = pb[9 * BPADN];
                    }
                    uint32_t b0h = pack_bf16(y00, y01);
                    uint32_t b1h = pack_bf16(y10, y11);
                    uint32_t b0l = pack_bf16(y00 - bflo(b0h), y01 - bfhi(b0h));
                    uint32_t b1l = pack_bf16(y10 - bflo(b1h), y11 - bfhi(b1h));
#pragma unroll
                    for (int mt = 0; mt < 4; mt++) {
                        mma16(acc[mt][nt], ah[mt], b0h, b1h);
                        mma16(acc[mt][nt], al[mt], b0h, b1h);
                        mma16(acc[mt][nt], ah[mt], b0l, b1l);
                    }
                }
            }
        }
    }

#pragma unroll
    for (int mt = 0; mt < 4; mt++) {
        const int r0 = wm + mt * 16 + g;
#pragma unroll
        for (int nt = 0; nt < NT; nt++) {
            const int c0 = wn + nt * 8 + tq * 2;
            *(float2*)&C[(long)r0 * ldc + c0]       = make_float2(acc[mt][nt][0], acc[mt][nt][1]);
            *(float2*)&C[(long)(r0 + 8) * ldc + c0] = make_float2(acc[mt][nt][2], acc[mt][nt][3]);
        }
    }
}

// ---------------- Split-K reduction: out[i] = sum_s in[s*n + i] ----------------
__global__ void reduce_slices(const float4* __restrict__ in, float4* __restrict__ out,
                              int n4, int S)
{
    int i = blockIdx.x * 256 + threadIdx.x;
    if (i >= n4) return;
    float4 a = in[i];
    for (int s = 1; s < S; s++) {
        float4 b = in[i + (long)s * n4];
        a.x += b.x; a.y += b.y; a.z += b.z; a.w += b.w;
    }
    out[i] = a;
}

// ---------------- RMSNorm (in place) ----------------
__global__ void rmsnorm_rows(float* __restrict__ X, const float* __restrict__ g, int cols)
{
    const long row = blockIdx.x;
    float* x = X + row * (long)cols;
    const int tid = threadIdx.x;
    const int n4 = cols >> 2;
    float ss = 0.f;
    for (int c = tid; c < n4; c += blockDim.x) {
        float4 v = ((const float4*)x)[c];
        ss += v.x * v.x + v.y * v.y + v.z * v.z + v.w * v.w;
    }
    __shared__ float red[256];
    red[tid] = ss; __syncthreads();
    for (int s = 128; s > 0; s >>= 1) { if (tid < s) red[tid] += red[tid + s]; __syncthreads(); }
    const float inv = rsqrtf(red[0] / (float)cols + EPSF);
    for (int c = tid; c < n4; c += blockDim.x) {
        float4 v = ((const float4*)x)[c];
        float4 w = ((const float4*)g)[c];
        v.x *= inv * w.x; v.y *= inv * w.y; v.z *= inv * w.z; v.w *= inv * w.w;
        ((float4*)x)[c] = v;
    }
}

// ---------------- Build K_comb ----------------
__global__ void build_K(const float* __restrict__ raw, const float* __restrict__ g,
                        const int* __restrict__ kvpos, float* __restrict__ Kc)
{
    const int s = blockIdx.x;
    const float* r = raw + (long)s * DQK;
    float* k = Kc + (long)s * DQK;
    const int tid = threadIdx.x;   // 128

    float ss = 0.f;
    for (int c = tid; c < RKV / 4; c += 128) {
        float4 v = ((const float4*)r)[c];
        ss += v.x * v.x + v.y * v.y + v.z * v.z + v.w * v.w;
    }
    __shared__ float red[128];
    red[tid] = ss; __syncthreads();
    for (int st = 64; st > 0; st >>= 1) { if (tid < st) red[tid] += red[tid + st]; __syncthreads(); }
    const float inv = rsqrtf(red[0] / (float)RKV + EPSF);
    for (int c = tid; c < RKV / 4; c += 128) {
        float4 v = ((const float4*)r)[c];
        float4 w = ((const float4*)g)[c];
        v.x *= inv * w.x; v.y *= inv * w.y; v.z *= inv * w.z; v.w *= inv * w.w;
        ((float4*)k)[c] = v;
    }

    if (tid < 32) {
        const int j = tid;
        const float x0 = r[RKV + 2 * j];
        const float x1 = r[RKV + 2 * j + 1];
        const float pos = (float)kvpos[s];
        const float invf = powf(10000.f, -(float)j / 32.f);
        float cs, sn; sincosf(pos * invf, &sn, &cs);
        k[RKV + j]      = x0 * cs - x1 * sn;
        k[RKV + 32 + j] = x0 * sn + x1 * cs;
    }
}

// ---------------- RoPE for q_pe ----------------
__global__ void rope_Q(const float* __restrict__ qfull, const int* __restrict__ qpos,
                       float* __restrict__ Qc)
{
    const int t = blockIdx.x;
    const int h = blockIdx.y;
    const int j = threadIdx.x;   // 32
    const float* src = qfull + (long)t * QB_COLS + h * (DNOPE + DROPE) + DNOPE;
    const float x0 = src[2 * j];
    const float x1 = src[2 * j + 1];
    const float pos = (float)qpos[t];
    const float invf = powf(10000.f, -(float)j / 32.f);
    float cs, sn; sincosf(pos * invf, &sn, &cs);
    float* dst = Qc + ((long)h * QLEN + t) * DQK + RKV;
    dst[j]      = x0 * cs - x1 * sn;
    dst[32 + j] = x0 * sn + x1 * cs;
}

// ---------------- Row softmax (float4) ----------------
__global__ void softmax_rows(float* __restrict__ X, int cols, float scale)
{
    const long row = blockIdx.x;
    float4* x = (float4*)(X + row * (long)cols);
    const int n4 = cols >> 2;
    const int tid = threadIdx.x;   // 256
    __shared__ float red[256];

    float m = -INFINITY;
    for (int c = tid; c < n4; c += 256) {
        float4 v = x[c];
        m = fmaxf(m, fmaxf(fmaxf(v.x, v.y), fmaxf(v.z, v.w)));
    }
    red[tid] = m; __syncthreads();
    for (int s = 128; s > 0; s >>= 1) { if (tid < s) red[tid] = fmaxf(red[tid], red[tid + s]); __syncthreads(); }
    m = red[0]; __syncthreads();

    float sum = 0.f;
    for (int c = tid; c < n4; c += 256) {
        float4 v = x[c];
        v.x = __expf((v.x - m) * scale);
        v.y = __expf((v.y - m) * scale);
        v.z = __expf((v.z - m) * scale);
        v.w = __expf((v.w - m) * scale);
        x[c] = v;
        sum += v.x + v.y + v.z + v.w;
    }
    red[tid] = sum; __syncthreads();
    for (int s = 128; s > 0; s >>= 1) { if (tid < s) red[tid] += red[tid + s]; __syncthreads(); }
    const float invs = 1.f / red[0];
    for (int c = tid; c < n4; c += 256) {
        float4 v = x[c];
        v.x *= invs; v.y *= invs; v.z *= invs; v.w *= invs;
        x[c] = v;
    }
}

// ---------------- Launch ----------------
static inline float* sym(const void* s)
{
    void* p = nullptr;
    cudaGetSymbolAddress(&p, s);
    return (float*)p;
}

static inline int smem_bytes(int NT, bool transb) {
    int a = 128 * 36;
    int b = transb ? NT * 32 * 36 : 32 * (NT * 32 + 8);
    return 3 * (a + b) * 4;
}

extern "C" void kernel_launch(void* const* d_in, const int* in_sizes, int n_in,
                              void* d_out, int out_size)
{
    const float* hq    = (const float*)d_in[0];
    const float* hkv   = (const float*)d_in[1];
    const float* W_qa  = (const float*)d_in[2];
    const float* gqa   = (const float*)d_in[3];
    const float* W_qb  = (const float*)d_in[4];
    const float* W_kva = (const float*)d_in[5];
    const float* gkva  = (const float*)d_in[6];
    const float* W_kvb = (const float*)d_in[7];
    const float* W_o   = (const float*)d_in[8];
    const int*   qpos  = (const int*)d_in[9];
    const int*   kvpos = (const int*)d_in[10];
    float*       out   = (float*)d_out;

    float* qa     = sym(g_qa_buf);
    float* qfull  = sym(g_qfull);
    float* ckvraw = sym(g_ckvraw);
    float* Kc     = sym(g_Kc);
    float* Qc     = sym(g_Qc);
    float* logits = sym(g_logits);
    float* oc     = sym(g_oc);
    float* ao     = sym(g_ao);
    float* part   = sym(g_part);

    cudaFuncSetAttribute(mma_gemm<4, false, 1>, cudaFuncAttributeMaxDynamicSharedMemorySize, smem_bytes(4, false));
    cudaFuncSetAttribute(mma_gemm<3, false, 1>, cudaFuncAttributeMaxDynamicSharedMemorySize, smem_bytes(3, false));
    cudaFuncSetAttribute(mma_gemm<4, true,  1>, cudaFuncAttributeMaxDynamicSharedMemorySize, smem_bytes(4, true));
    cudaFuncSetAttribute(mma_gemm<8, true,  0>, cudaFuncAttributeMaxDynamicSharedMemorySize, smem_bytes(8, true));
    cudaFuncSetAttribute(mma_gemm<8, false, 0>, cudaFuncAttributeMaxDynamicSharedMemorySize, smem_bytes(8, false));

    // 1) qa = hq @ W_qa : (256,1536), K=5120  [NN bf16x3, split-K 8]
    mma_gemm<4, false, 1><<<dim3(RQ / 128, 2, 8), 256, smem_bytes(4, false)>>>(
        hq, W_qa, part, HID / 8, HID, RQ, RQ,
        (long)(HID / 8), (long)(HID / 8) * RQ, (long)QLEN * RQ);
    reduce_slices<<<(QLEN * RQ / 4 + 255) / 256, 256>>>((const float4*)part, (float4*)qa, QLEN * RQ / 4, 8);

    // 2) rmsnorm(qa)
    rmsnorm_rows<<<QLEN, 256>>>(qa, gqa, RQ);

    // 3) qfull = qa @ W_qb : (256,24576), K=1536  [NN bf16x3]
    mma_gemm<4, false, 1><<<dim3(QB_COLS / 128, 2, 1), 256, smem_bytes(4, false)>>>(
        qa, W_qb, qfull, RQ, RQ, QB_COLS, QB_COLS, 0, 0, 0);

    // 4) ckvraw = hkv @ W_kva : (4096,576), K=5120  [NN bf16x3, BN=96 -> grid 192]
    mma_gemm<3, false, 1><<<dim3(DQK / 96, SLEN / 128, 1), 256, smem_bytes(3, false)>>>(
        hkv, W_kva, ckvraw, HID, HID, DQK, DQK, 0, 0, 0);

    // 5) K_comb
    build_K<<<SLEN, 128>>>(ckvraw, gkva, kvpos, Kc);

    // 6) q_c[h] = q_nope[h] @ q_absorb[h] : batched (256,512), K=128  [NN bf16x3]
    mma_gemm<4, false, 1><<<dim3(RKV / 128, 2, NHEADS), 256, smem_bytes(4, false)>>>(
        qfull, W_kvb, Qc, DNOPE,
        QB_COLS, RKV, DQK,
        (long)(DNOPE + DROPE), (long)(DNOPE + DNOPE) * RKV, (long)QLEN * DQK);

    // 7) rope q_pe
    rope_Q<<<dim3(QLEN, NHEADS), 32>>>(qfull, qpos, Qc);

    // 8) logits[h] = Q_comb[h] @ K_comb^T : batched (256,4096), K=576  [NT tf32 single]
    mma_gemm<8, true, 0><<<dim3(SLEN / 256, 2, NHEADS), 256, smem_bytes(8, true)>>>(
        Qc, Kc, logits, DQK,
        DQK, DQK, SLEN,
        (long)QLEN * DQK, 0, (long)QLEN * SLEN);

    // 9) softmax
    softmax_rows<<<NHEADS * QLEN, 256>>>(logits, SLEN, 1.0f / sqrtf(192.0f));

    // 10) oc[h] = P[h] @ ckv : batched (256,512), K=4096  [NN tf32 single]
    mma_gemm<8, false, 0><<<dim3(RKV / 256, 2, NHEADS), 256, smem_bytes(8, false)>>>(
        logits, Kc, oc, SLEN,
        SLEN, DQK, RKV,
        (long)QLEN * SLEN, 0, (long)QLEN * RKV);

    // 11) ao[:, h*128:] = oc[h] @ out_absorb[h]^T : batched (256,128), K=512  [NT bf16x3]
    mma_gemm<4, true, 1><<<dim3(1, 2, NHEADS), 256, smem_bytes(4, true)>>>(
        oc, W_kvb + (long)DNOPE * RKV, ao, RKV,
        RKV, RKV, AO_COLS,
        (long)QLEN * RKV, (long)(DNOPE + DNOPE) * RKV, (long)DNOPE);

    // 12) out = ao @ W_o : (256,5120), K=16384  [NN bf16x3, split-K 4]
    mma_gemm<4, false, 1><<<dim3(HID / 128, 2, 4), 256, smem_bytes(4, false)>>>(
        ao, W_o, part, AO_COLS / 4, AO_COLS, HID, HID,
        (long)(AO_COLS / 4), (long)(AO_COLS / 4) * HID, (long)QLEN * HID);
    reduce_slices<<<(QLEN * HID / 4 + 255) / 256, 256>>>((const float4*)part, (float4*)out, QLEN * HID / 4, 4);
}

// round 6
// speedup vs baseline: 1.4892x; 1.0636x over previous
#include <cuda_runtime.h>
#include <math.h>
#include <stdint.h>

// ---------------- Problem constants ----------------
#define NHEADS   128
#define DNOPE    128
#define DROPE    64
#define DQK      576
#define RKV      512
#define RQ       1536
#define HID      5120
#define QLEN     256
#define SLEN     4096
#define QB_COLS  24576
#define AO_COLS  16384
#define EPSF     1e-6f

// ---------------- Scratch (device globals) ----------------
__device__ __align__(128) float g_qa_buf [QLEN * RQ];
__device__ __align__(128) float g_qfull  [QLEN * QB_COLS];
__device__ __align__(128) float g_ckvraw [SLEN * DQK];
__device__ __align__(128) float g_Kc     [SLEN * DQK];
__device__ __align__(128) float g_Qc     [(size_t)NHEADS * QLEN * DQK];
__device__ __align__(128) float g_logits [(size_t)NHEADS * QLEN * SLEN];   // 512 MB
__device__ __align__(128) float g_oc     [(size_t)NHEADS * QLEN * RKV];
__device__ __align__(128) float g_ao     [QLEN * AO_COLS];
__device__ __align__(128) float g_part   [8 * QLEN * HID];                  // split-K partials

// ---------------- helpers ----------------
__device__ __forceinline__ uint32_t smem_u32(const void* p) {
    uint32_t a;
    asm("{ .reg .u64 t; cvta.to.shared.u64 t, %1; cvt.u32.u64 %0, t; }" : "=r"(a) : "l"(p));
    return a;
}
__device__ __forceinline__ uint32_t f2tf(float x) {
    uint32_t r;
    asm("cvt.rna.tf32.f32 %0, %1;" : "=r"(r) : "f"(x));
    return r;
}
__device__ __forceinline__ uint32_t pack_bf16(float lo, float hi) {
    uint32_t r;
    asm("cvt.rn.bf16x2.f32 %0, %1, %2;" : "=r"(r) : "f"(hi), "f"(lo));
    return r;
}
__device__ __forceinline__ float bflo(uint32_t p) { return __uint_as_float(p << 16); }
__device__ __forceinline__ float bfhi(uint32_t p) { return __uint_as_float(p & 0xffff0000u); }

__device__ __forceinline__ void mma8(float* d, const uint32_t* a, uint32_t b0, uint32_t b1) {
    asm volatile(
        "mma.sync.aligned.m16n8k8.row.col.f32.tf32.tf32.f32 "
        "{%0,%1,%2,%3},{%4,%5,%6,%7},{%8,%9},{%0,%1,%2,%3};"
        : "+f"(d[0]), "+f"(d[1]), "+f"(d[2]), "+f"(d[3])
        : "r"(a[0]), "r"(a[1]), "r"(a[2]), "r"(a[3]), "r"(b0), "r"(b1));
}
__device__ __forceinline__ void mma16(float* d, const uint32_t* a, uint32_t b0, uint32_t b1) {
    asm volatile(
        "mma.sync.aligned.m16n8k16.row.col.f32.bf16.bf16.f32 "
        "{%0,%1,%2,%3},{%4,%5,%6,%7},{%8,%9},{%0,%1,%2,%3};"
        : "+f"(d[0]), "+f"(d[1]), "+f"(d[2]), "+f"(d[3])
        : "r"(a[0]), "r"(a[1]), "r"(a[2]), "r"(a[3]), "r"(b0), "r"(b1));
}
__device__ __forceinline__ void ldm_x4(uint32_t* r, uint32_t addr) {
    asm volatile("ldmatrix.sync.aligned.m8n8.x4.shared.b16 {%0,%1,%2,%3}, [%4];"
                 : "=r"(r[0]), "=r"(r[1]), "=r"(r[2]), "=r"(r[3]) : "r"(addr));
}

// ---------------- mma.sync GEMM (register-staged, pre-converted smem) ----------------
// TRANSB=1: C = A @ B^T, B:[N,K] K-major. TRANSB=0: C = A @ B, B:[K,N] N-major.
// A:[M,K]. BN = NT*32. K%32==0. 8 warps 2(m)x4(n), warp tile 64 x (NT*8).
// PREC=0: tf32 single (smem holds pre-rounded tf32).
// PREC=1: bf16 3-term split (smem holds pre-packed bf16x2 hi and lo arrays).
template<int NT, bool TRANSB, int PREC>
__global__ void __launch_bounds__(256, 2)
mma_gemm(const float* __restrict__ A, const float* __restrict__ B, float* __restrict__ C,
         int K, int lda, int ldb, int ldc, long sA, long sB, long sC)
{
    constexpr int BN   = NT * 32;
    constexpr int A_ST = (PREC == 0) ? 128 * 36 : 128 * 20 * 2;   // u32 per stage
    constexpr int B_ST = TRANSB ? ((PREC == 0) ? BN * 36 : BN * 20 * 2)
                                : ((PREC == 0) ? 32 * (BN + 8) : 16 * (BN + 8) * 2);
    constexpr int STG  = A_ST + B_ST;
    constexpr int BQ   = BN / 4;                                   // float4 groups per B row (NN)

    extern __shared__ uint32_t smu[];
    const uint32_t smem_base = smem_u32(smu);

    const int tid  = threadIdx.x;
    const int warp = tid >> 5;
    const int lane = tid & 31;
    const int wm = (warp >> 2) * 64;
    const int wn = (warp & 3) * (BN / 4);
    const int g  = lane >> 2;
    const int tq = lane & 3;

    const int bm = blockIdx.y * 128;
    const int bn = blockIdx.x * BN;
    A += (long)blockIdx.z * sA + (long)bm * lda;
    if (TRANSB) B += (long)blockIdx.z * sB + (long)bn * ldb;
    else        B += (long)blockIdx.z * sB + bn;
    C += (long)blockIdx.z * sC + (long)bm * ldc + bn;

    const int NC = K >> 5;

    float acc[4][NT][4];
#pragma unroll
    for (int i = 0; i < 4; i++)
#pragma unroll
        for (int j = 0; j < NT; j++)
#pragma unroll
            for (int l = 0; l < 4; l++) acc[i][j][l] = 0.f;

    float4 rA[4];
    float4 rB[4];

    // ---- global -> registers for chunk c ----
    auto ldg_chunk = [&](int c) {
        const float* ga = A + c * 32;
#pragma unroll
        for (int i = 0; i < 4; i++) {
            int idx = tid + i * 256;
            int r = idx >> 3, c4 = (idx & 7) << 2;
            rA[i] = *(const float4*)(ga + (long)r * lda + c4);
        }
        if (TRANSB) {
            const float* gb = B + c * 32;
#pragma unroll
            for (int i = 0; i < NT; i++) {
                int idx = tid + i * 256;
                int r = idx >> 3, c4 = (idx & 7) << 2;
                rB[i] = *(const float4*)(gb + (long)r * ldb + c4);
            }
        } else if (PREC == 0) {
            const float* gb = B + (long)(c * 32) * ldb;
#pragma unroll
            for (int i = 0; i < NT; i++) {
                int idx = tid + i * 256;
                int r = idx / BQ, c4 = (idx % BQ) << 2;
                rB[i] = *(const float4*)(gb + (long)r * ldb + c4);
            }
        } else {
            const float* gb = B + (long)(c * 32) * ldb;
#pragma unroll
            for (int i = 0; i < 2; i++) {
                int u = tid + i * 256;
                if (u < 16 * BQ) {
                    int kp = u / BQ, c4 = (u % BQ) << 2;
                    rB[2 * i]     = *(const float4*)(gb + (long)(2 * kp) * ldb + c4);
                    rB[2 * i + 1] = *(const float4*)(gb + (long)(2 * kp + 1) * ldb + c4);
                }
            }
        }
    };

    // ---- registers -> smem (convert/pack) ----
    auto sts_chunk = [&](int sbase) {
        uint32_t* sa = smu + sbase;
        uint32_t* sb = smu + sbase + A_ST;
        if (PREC == 0) {
#pragma unroll
            for (int i = 0; i < 4; i++) {
                int idx = tid + i * 256;
                int r = idx >> 3, c4 = (idx & 7) << 2;
                uint4 w = { f2tf(rA[i].x), f2tf(rA[i].y), f2tf(rA[i].z), f2tf(rA[i].w) };
                *(uint4*)&sa[r * 36 + c4] = w;
            }
            if (TRANSB) {
#pragma unroll
                for (int i = 0; i < NT; i++) {
                    int idx = tid + i * 256;
                    int r = idx >> 3, c4 = (idx & 7) << 2;
                    uint4 w = { f2tf(rB[i].x), f2tf(rB[i].y), f2tf(rB[i].z), f2tf(rB[i].w) };
                    *(uint4*)&sb[r * 36 + c4] = w;
                }
            } else {
#pragma unroll
                for (int i = 0; i < NT; i++) {
                    int idx = tid + i * 256;
                    int r = idx / BQ, c4 = (idx % BQ) << 2;
                    uint4 w = { f2tf(rB[i].x), f2tf(rB[i].y), f2tf(rB[i].z), f2tf(rB[i].w) };
                    *(uint4*)&sb[r * (BN + 8) + c4] = w;
                }
            }
        } else {
            // A: pack pairs along k -> hi array [128][20], lo array after it
#pragma unroll
            for (int i = 0; i < 4; i++) {
                int idx = tid + i * 256;
                int r = idx >> 3, cu = (idx & 7) << 1;       // u32 col (k/2)
                float4 v = rA[i];
                uint32_t h0 = pack_bf16(v.x, v.y), h1 = pack_bf16(v.z, v.w);
                uint32_t l0 = pack_bf16(v.x - bflo(h0), v.y - bfhi(h0));
                uint32_t l1 = pack_bf16(v.z - bflo(h1), v.w - bfhi(h1));
                *(uint2*)&sa[r * 20 + cu]            = make_uint2(h0, h1);
                *(uint2*)&sa[128 * 20 + r * 20 + cu] = make_uint2(l0, l1);
            }
            if (TRANSB) {
#pragma unroll
                for (int i = 0; i < NT; i++) {
                    int idx = tid + i * 256;
                    int r = idx >> 3, cu = (idx & 7) << 1;
                    float4 v = rB[i];
                    uint32_t h0 = pack_bf16(v.x, v.y), h1 = pack_bf16(v.z, v.w);
                    uint32_t l0 = pack_bf16(v.x - bflo(h0), v.y - bfhi(h0));
                    uint32_t l1 = pack_bf16(v.z - bflo(h1), v.w - bfhi(h1));
                    *(uint2*)&sb[r * 20 + cu]           = make_uint2(h0, h1);
                    *(uint2*)&sb[BN * 20 + r * 20 + cu] = make_uint2(l0, l1);
                }
            } else {
#pragma unroll
                for (int i = 0; i < 2; i++) {
                    int u = tid + i * 256;
                    if (u < 16 * BQ) {
                        int kp = u / BQ, c4 = (u % BQ) << 2;
                        float4 v0 = rB[2 * i], v1 = rB[2 * i + 1];
                        uint4 h = { pack_bf16(v0.x, v1.x), pack_bf16(v0.y, v1.y),
                                    pack_bf16(v0.z, v1.z), pack_bf16(v0.w, v1.w) };
                        uint4 l = { pack_bf16(v0.x - bflo(h.x), v1.x - bfhi(h.x)),
                                    pack_bf16(v0.y - bflo(h.y), v1.y - bfhi(h.y)),
                                    pack_bf16(v0.z - bflo(h.z), v1.z - bfhi(h.z)),
                                    pack_bf16(v0.w - bflo(h.w), v1.w - bfhi(h.w)) };
                        *(uint4*)&sb[kp * (BN + 8) + c4]                 = h;
                        *(uint4*)&sb[16 * (BN + 8) + kp * (BN + 8) + c4] = l;
                    }
                }
            }
        }
    };

    // ---- compute one k32 chunk from stage sbase ----
    auto compute = [&](int sbase) {
        const uint32_t aB = smem_base + (uint32_t)sbase * 4;
        const uint32_t bB = smem_base + (uint32_t)(sbase + A_ST) * 4;
        const int mat = lane >> 3;
        if (PREC == 0) {
#pragma unroll
            for (int kk = 0; kk < 4; kk++) {
                const int kcu = kk * 8;
                uint32_t af[4][4];
#pragma unroll
                for (int mt = 0; mt < 4; mt++) {
                    int row = wm + mt * 16 + ((mat & 1) << 3) + (lane & 7);
                    int col = kcu + ((mat >> 1) << 2);
                    ldm_x4(af[mt], aB + (uint32_t)(row * 36 + col) * 4);
                }
                if (TRANSB) {
#pragma unroll
                    for (int np = 0; np < NT / 2; np++) {
                        uint32_t bf[4];
                        int row = wn + (2 * np + (mat >> 1)) * 8 + (lane & 7);
                        int col = kcu + ((mat & 1) << 2);
                        ldm_x4(bf, bB + (uint32_t)(row * 36 + col) * 4);
#pragma unroll
                        for (int mt = 0; mt < 4; mt++) {
                            mma8(acc[mt][2 * np],     af[mt], bf[0], bf[1]);
                            mma8(acc[mt][2 * np + 1], af[mt], bf[2], bf[3]);
                        }
                    }
                } else {
                    const uint32_t* sb = smu + sbase + A_ST;
#pragma unroll
                    for (int nt = 0; nt < NT; nt++) {
                        int n0 = wn + nt * 8 + g;
                        uint32_t b0 = sb[(kcu + tq) * (BN + 8) + n0];
                        uint32_t b1 = sb[(kcu + tq + 4) * (BN + 8) + n0];
#pragma unroll
                        for (int mt = 0; mt < 4; mt++)
                            mma8(acc[mt][nt], af[mt], b0, b1);
                    }
                }
            }
        } else {
#pragma unroll
            for (int kk = 0; kk < 2; kk++) {
                const int kcu = kk * 8;
                uint32_t ah[4][4], al[4][4];
#pragma unroll
                for (int mt = 0; mt < 4; mt++) {
                    int row = wm + mt * 16 + ((mat & 1) << 3) + (lane & 7);
                    int col = kcu + ((mat >> 1) << 2);
                    ldm_x4(ah[mt], aB + (uint32_t)(row * 20 + col) * 4);
                    ldm_x4(al[mt], aB + (uint32_t)(128 * 20 + row * 20 + col) * 4);
                }
                if (TRANSB) {
#pragma unroll
                    for (int np = 0; np < NT / 2; np++) {
                        uint32_t bh[4], bl[4];
                        int row = wn + (2 * np + (mat >> 1)) * 8 + (lane & 7);
                        int col = kcu + ((mat & 1) << 2);
                        ldm_x4(bh, bB + (uint32_t)(row * 20 + col) * 4);
                        ldm_x4(bl, bB + (uint32_t)(BN * 20 + row * 20 + col) * 4);
#pragma unroll
                        for (int mt = 0; mt < 4; mt++) {
                            mma16(acc[mt][2 * np], ah[mt], bh[0], bh[1]);
                            mma16(acc[mt][2 * np], al[mt], bh[0], bh[1]);
                            mma16(acc[mt][2 * np], ah[mt], bl[0], bl[1]);
                            mma16(acc[mt][2 * np + 1], ah[mt], bh[2], bh[3]);
                            mma16(acc[mt][2 * np + 1], al[mt], bh[2], bh[3]);
                            mma16(acc[mt][2 * np + 1], ah[mt], bl[2], bl[3]);
                        }
                    }
                } else {
                    const uint32_t* sbh = smu + sbase + A_ST;
                    const uint32_t* sbl = sbh + 16 * (BN + 8);
#pragma unroll
                    for (int nt = 0; nt < NT; nt++) {
                        int n0 = wn + nt * 8 + g;
                        uint32_t b0h = sbh[(kcu + tq) * (BN + 8) + n0];
                        uint32_t b1h = sbh[(kcu + tq + 4) * (BN + 8) + n0];
                        uint32_t b0l = sbl[(kcu + tq) * (BN + 8) + n0];
                        uint32_t b1l = sbl[(kcu + tq + 4) * (BN + 8) + n0];
#pragma unroll
                        for (int mt = 0; mt < 4; mt++) {
                            mma16(acc[mt][nt], ah[mt], b0h, b1h);
                            mma16(acc[mt][nt], al[mt], b0h, b1h);
                            mma16(acc[mt][nt], ah[mt], b0l, b1l);
                        }
                    }
                }
            }
        }
    };

    // ---- pipeline ----
    ldg_chunk(0);
    sts_chunk(0);
    __syncthreads();
    for (int c = 0; c < NC; c++) {
        if (c + 1 < NC) ldg_chunk(c + 1);
        compute((c & 1) * STG);
        if (c + 1 < NC) {
            __syncthreads();
            sts_chunk(((c + 1) & 1) * STG);
            __syncthreads();
        }
    }

    // ---- epilogue ----
#pragma unroll
    for (int mt = 0; mt < 4; mt++) {
        const int r0 = wm + mt * 16 + g;
#pragma unroll
        for (int nt = 0; nt < NT; nt++) {
            const int c0 = wn + nt * 8 + tq * 2;
            *(float2*)&C[(long)r0 * ldc + c0]       = make_float2(acc[mt][nt][0], acc[mt][nt][1]);
            *(float2*)&C[(long)(r0 + 8) * ldc + c0] = make_float2(acc[mt][nt][2], acc[mt][nt][3]);
        }
    }
}

// ---------------- Split-K reduction ----------------
__global__ void reduce_slices(const float4* __restrict__ in, float4* __restrict__ out,
                              int n4, int S)
{
    int i = blockIdx.x * 256 + threadIdx.x;
    if (i >= n4) return;
    float4 a = in[i];
    for (int s = 1; s < S; s++) {
        float4 b = in[i + (long)s * n4];
        a.x += b.x; a.y += b.y; a.z += b.z; a.w += b.w;
    }
    out[i] = a;
}

// ---------------- RMSNorm (in place) ----------------
__global__ void rmsnorm_rows(float* __restrict__ X, const float* __restrict__ g, int cols)
{
    const long row = blockIdx.x;
    float* x = X + row * (long)cols;
    const int tid = threadIdx.x;
    const int n4 = cols >> 2;
    float ss = 0.f;
    for (int c = tid; c < n4; c += blockDim.x) {
        float4 v = ((const float4*)x)[c];
        ss += v.x * v.x + v.y * v.y + v.z * v.z + v.w * v.w;
    }
    __shared__ float red[256];
    red[tid] = ss; __syncthreads();
    for (int s = 128; s > 0; s >>= 1) { if (tid < s) red[tid] += red[tid + s]; __syncthreads(); }
    const float inv = rsqrtf(red[0] / (float)cols + EPSF);
    for (int c = tid; c < n4; c += blockDim.x) {
        float4 v = ((const float4*)x)[c];
        float4 w = ((const float4*)g)[c];
        v.x *= inv * w.x; v.y *= inv * w.y; v.z *= inv * w.z; v.w *= inv * w.w;
        ((float4*)x)[c] = v;
    }
}

// ---------------- Build K_comb ----------------
__global__ void build_K(const float* __restrict__ raw, const float* __restrict__ g,
                        const int* __restrict__ kvpos, float* __restrict__ Kc)
{
    const int s = blockIdx.x;
    const float* r = raw + (long)s * DQK;
    float* k = Kc + (long)s * DQK;
    const int tid = threadIdx.x;   // 128

    float ss = 0.f;
    for (int c = tid; c < RKV / 4; c += 128) {
        float4 v = ((const float4*)r)[c];
        ss += v.x * v.x + v.y * v.y + v.z * v.z + v.w * v.w;
    }
    __shared__ float red[128];
    red[tid] = ss; __syncthreads();
    for (int st = 64; st > 0; st >>= 1) { if (tid < st) red[tid] += red[tid + st]; __syncthreads(); }
    const float inv = rsqrtf(red[0] / (float)RKV + EPSF);
    for (int c = tid; c < RKV / 4; c += 128) {
        float4 v = ((const float4*)r)[c];
        float4 w = ((const float4*)g)[c];
        v.x *= inv * w.x; v.y *= inv * w.y; v.z *= inv * w.z; v.w *= inv * w.w;
        ((float4*)k)[c] = v;
    }

    if (tid < 32) {
        const int j = tid;
        const float x0 = r[RKV + 2 * j];
        const float x1 = r[RKV + 2 * j + 1];
        const float pos = (float)kvpos[s];
        const float invf = powf(10000.f, -(float)j / 32.f);
        float cs, sn; sincosf(pos * invf, &sn, &cs);
        k[RKV + j]      = x0 * cs - x1 * sn;
        k[RKV + 32 + j] = x0 * sn + x1 * cs;
    }
}

// ---------------- RoPE for q_pe ----------------
__global__ void rope_Q(const float* __restrict__ qfull, const int* __restrict__ qpos,
                       float* __restrict__ Qc)
{
    const int t = blockIdx.x;
    const int h = blockIdx.y;
    const int j = threadIdx.x;   // 32
    const float* src = qfull + (long)t * QB_COLS + h * (DNOPE + DROPE) + DNOPE;
    const float x0 = src[2 * j];
    const float x1 = src[2 * j + 1];
    const float pos = (float)qpos[t];
    const float invf = powf(10000.f, -(float)j / 32.f);
    float cs, sn; sincosf(pos * invf, &sn, &cs);
    float* dst = Qc + ((long)h * QLEN + t) * DQK + RKV;
    dst[j]      = x0 * cs - x1 * sn;
    dst[32 + j] = x0 * sn + x1 * cs;
}

// ---------------- Row softmax (float4) ----------------
__global__ void softmax_rows(float* __restrict__ X, int cols, float scale)
{
    const long row = blockIdx.x;
    float4* x = (float4*)(X + row * (long)cols);
    const int n4 = cols >> 2;
    const int tid = threadIdx.x;   // 256
    __shared__ float red[256];

    float m = -INFINITY;
    for (int c = tid; c < n4; c += 256) {
        float4 v = x[c];
        m = fmaxf(m, fmaxf(fmaxf(v.x, v.y), fmaxf(v.z, v.w)));
    }
    red[tid] = m; __syncthreads();
    for (int s = 128; s > 0; s >>= 1) { if (tid < s) red[tid] = fmaxf(red[tid], red[tid + s]); __syncthreads(); }
    m = red[0]; __syncthreads();

    float sum = 0.f;
    for (int c = tid; c < n4; c += 256) {
        float4 v = x[c];
        v.x = __expf((v.x - m) * scale);
        v.y = __expf((v.y - m) * scale);
        v.z = __expf((v.z - m) * scale);
        v.w = __expf((v.w - m) * scale);
        x[c] = v;
        sum += v.x + v.y + v.z + v.w;
    }
    red[tid] = sum; __syncthreads();
    for (int s = 128; s > 0; s >>= 1) { if (tid < s) red[tid] += red[tid + s]; __syncthreads(); }
    const float invs = 1.f / red[0];
    for (int c = tid; c < n4; c += 256) {
        float4 v = x[c];
        v.x *= invs; v.y *= invs; v.z *= invs; v.w *= invs;
        x[c] = v;
    }
}

// ---------------- Launch ----------------
static inline float* sym(const void* s)
{
    void* p = nullptr;
    cudaGetSymbolAddress(&p, s);
    return (float*)p;
}

static inline int smem_b(int NT, bool transb, int prec)
{
    int a = (prec == 0) ? 128 * 36 : 128 * 40;
    int b = transb ? ((prec == 0) ? NT * 32 * 36 : NT * 32 * 40)
                   : 32 * (NT * 32 + 8);    // NN: tf32 and bf16 coincide
    return 2 * (a + b) * 4;
}

extern "C" void kernel_launch(void* const* d_in, const int* in_sizes, int n_in,
                              void* d_out, int out_size)
{
    const float* hq    = (const float*)d_in[0];
    const float* hkv   = (const float*)d_in[1];
    const float* W_qa  = (const float*)d_in[2];
    const float* gqa   = (const float*)d_in[3];
    const float* W_qb  = (const float*)d_in[4];
    const float* W_kva = (const float*)d_in[5];
    const float* gkva  = (const float*)d_in[6];
    const float* W_kvb = (const float*)d_in[7];
    const float* W_o   = (const float*)d_in[8];
    const int*   qpos  = (const int*)d_in[9];
    const int*   kvpos = (const int*)d_in[10];
    float*       out   = (float*)d_out;

    float* qa     = sym(g_qa_buf);
    float* qfull  = sym(g_qfull);
    float* ckvraw = sym(g_ckvraw);
    float* Kc     = sym(g_Kc);
    float* Qc     = sym(g_Qc);
    float* logits = sym(g_logits);
    float* oc     = sym(g_oc);
    float* ao     = sym(g_ao);
    float* part   = sym(g_part);

    cudaFuncSetAttribute(mma_gemm<4, false, 1>, cudaFuncAttributeMaxDynamicSharedMemorySize, smem_b(4, false, 1));
    cudaFuncSetAttribute(mma_gemm<3, false, 1>, cudaFuncAttributeMaxDynamicSharedMemorySize, smem_b(3, false, 1));
    cudaFuncSetAttribute(mma_gemm<4, true,  1>, cudaFuncAttributeMaxDynamicSharedMemorySize, smem_b(4, true, 1));
    cudaFuncSetAttribute(mma_gemm<4, true,  0>, cudaFuncAttributeMaxDynamicSharedMemorySize, smem_b(4, true, 0));
    cudaFuncSetAttribute(mma_gemm<4, false, 0>, cudaFuncAttributeMaxDynamicSharedMemorySize, smem_b(4, false, 0));

    // 1) qa = hq @ W_qa : (256,1536), K=5120  [NN bf16x3, split-K 8]
    mma_gemm<4, false, 1><<<dim3(RQ / 128, 2, 8), 256, smem_b(4, false, 1)>>>(
        hq, W_qa, part, HID / 8, HID, RQ, RQ,
        (long)(HID / 8), (long)(HID / 8) * RQ, (long)QLEN * RQ);
    reduce_slices<<<(QLEN * RQ / 4 + 255) / 256, 256>>>((const float4*)part, (float4*)qa, QLEN * RQ / 4, 8);

    // 2) rmsnorm(qa)
    rmsnorm_rows<<<QLEN, 256>>>(qa, gqa, RQ);

    // 3) qfull = qa @ W_qb : (256,24576), K=1536  [NN bf16x3]
    mma_gemm<4, false, 1><<<dim3(QB_COLS / 128, 2, 1), 256, smem_b(4, false, 1)>>>(
        qa, W_qb, qfull, RQ, RQ, QB_COLS, QB_COLS, 0, 0, 0);

    // 4) ckvraw = hkv @ W_kva : (4096,576), K=5120  [NN bf16x3, BN=96]
    mma_gemm<3, false, 1><<<dim3(DQK / 96, SLEN / 128, 1), 256, smem_b(3, false, 1)>>>(
        hkv, W_kva, ckvraw, HID, HID, DQK, DQK, 0, 0, 0);

    // 5) K_comb
    build_K<<<SLEN, 128>>>(ckvraw, gkva, kvpos, Kc);

    // 6) q_c[h] = q_nope[h] @ q_absorb[h] : batched (256,512), K=128  [NN bf16x3]
    mma_gemm<4, false, 1><<<dim3(RKV / 128, 2, NHEADS), 256, smem_b(4, false, 1)>>>(
        qfull, W_kvb, Qc, DNOPE,
        QB_COLS, RKV, DQK,
        (long)(DNOPE + DROPE), (long)(DNOPE + DNOPE) * RKV, (long)QLEN * DQK);

    // 7) rope q_pe
    rope_Q<<<dim3(QLEN, NHEADS), 32>>>(qfull, qpos, Qc);

    // 8) logits[h] = Q_comb[h] @ K_comb^T : batched (256,4096), K=576  [NT tf32]
    mma_gemm<4, true, 0><<<dim3(SLEN / 128, 2, NHEADS), 256, smem_b(4, true, 0)>>>(
        Qc, Kc, logits, DQK,
        DQK, DQK, SLEN,
        (long)QLEN * DQK, 0, (long)QLEN * SLEN);

    // 9) softmax
    softmax_rows<<<NHEADS * QLEN, 256>>>(logits, SLEN, 1.0f / sqrtf(192.0f));

    // 10) oc[h] = P[h] @ ckv : batched (256,512), K=4096  [NN tf32; B=Kc cols 0..511]
    mma_gemm<4, false, 0><<<dim3(RKV / 128, 2, NHEADS), 256, smem_b(4, false, 0)>>>(
        logits, Kc, oc, SLEN,
        SLEN, DQK, RKV,
        (long)QLEN * SLEN, 0, (long)QLEN * RKV);

    // 11) ao[:, h*128:] = oc[h] @ out_absorb[h]^T : batched (256,128), K=512  [NT bf16x3]
    mma_gemm<4, true, 1><<<dim3(1, 2, NHEADS), 256, smem_b(4, true, 1)>>>(
        oc, W_kvb + (long)DNOPE * RKV, ao, RKV,
        RKV, RKV, AO_COLS,
        (long)QLEN * RKV, (long)(DNOPE + DNOPE) * RKV, (long)DNOPE);

    // 12) out = ao @ W_o : (256,5120), K=16384  [NN bf16x3, split-K 4]
    mma_gemm<4, false, 1><<<dim3(HID / 128, 2, 4), 256, smem_b(4, false, 1)>>>(
        ao, W_o, part, AO_COLS / 4, AO_COLS, HID, HID,
        (long)(AO_COLS / 4), (long)(AO_COLS / 4) * HID, (long)QLEN * HID);
    reduce_slices<<<(QLEN * HID / 4 + 255) / 256, 256>>>((const float4*)part, (float4*)out, QLEN * HID / 4, 4);
}

// round 7
// speedup vs baseline: 1.5146x; 1.0171x over previous
#include <cuda_runtime.h>
#include <math.h>
#include <stdint.h>

// ---------------- Problem constants ----------------
#define NHEADS   128
#define DNOPE    128
#define DROPE    64
#define DQK      576
#define RKV      512
#define RQ       1536
#define HID      5120
#define QLEN     256
#define SLEN     4096
#define QB_COLS  24576
#define AO_COLS  16384
#define EPSF     1e-6f

// ---------------- Scratch (device globals) ----------------
__device__ __align__(128) float g_qa_buf [QLEN * RQ];
__device__ __align__(128) float g_qfull  [QLEN * QB_COLS];
__device__ __align__(128) float g_ckvraw [SLEN * DQK];
__device__ __align__(128) float g_Kc     [SLEN * DQK];
__device__ __align__(128) float g_ckvT   [(size_t)RKV * SLEN];
__device__ __align__(128) float g_Qc     [(size_t)NHEADS * QLEN * DQK];
__device__ __align__(128) float g_logits [(size_t)NHEADS * QLEN * SLEN];   // 512 MB
__device__ __align__(128) float g_oc     [(size_t)NHEADS * QLEN * RKV];
__device__ __align__(128) float g_ao     [QLEN * AO_COLS];
__device__ __align__(128) float g_part   [8 * QLEN * HID];                  // split-K partials
__device__ __align__(128) float g_rowm   [NHEADS * QLEN];                   // max * scale
__device__ __align__(128) float g_rowis  [NHEADS * QLEN];                   // 1 / sum(exp)

// ---------------- helpers ----------------
__device__ __forceinline__ uint32_t smem_u32(const void* p) {
    uint32_t a;
    asm("{ .reg .u64 t; cvta.to.shared.u64 t, %1; cvt.u32.u64 %0, t; }" : "=r"(a) : "l"(p));
    return a;
}
__device__ __forceinline__ uint32_t f2tf(float x) {
    uint32_t r;
    asm("cvt.rna.tf32.f32 %0, %1;" : "=r"(r) : "f"(x));
    return r;
}
__device__ __forceinline__ uint32_t pack_bf16(float lo, float hi) {
    uint32_t r;
    asm("cvt.rn.bf16x2.f32 %0, %1, %2;" : "=r"(r) : "f"(hi), "f"(lo));
    return r;
}
__device__ __forceinline__ float bflo(uint32_t p) { return __uint_as_float(p << 16); }
__device__ __forceinline__ float bfhi(uint32_t p) { return __uint_as_float(p & 0xffff0000u); }

__device__ __forceinline__ void mma8(float* d, const uint32_t* a, uint32_t b0, uint32_t b1) {
    asm volatile(
        "mma.sync.aligned.m16n8k8.row.col.f32.tf32.tf32.f32 "
        "{%0,%1,%2,%3},{%4,%5,%6,%7},{%8,%9},{%0,%1,%2,%3};"
        : "+f"(d[0]), "+f"(d[1]), "+f"(d[2]), "+f"(d[3])
        : "r"(a[0]), "r"(a[1]), "r"(a[2]), "r"(a[3]), "r"(b0), "r"(b1));
}
__device__ __forceinline__ void mma16(float* d, const uint32_t* a, uint32_t b0, uint32_t b1) {
    asm volatile(
        "mma.sync.aligned.m16n8k16.row.col.f32.bf16.bf16.f32 "
        "{%0,%1,%2,%3},{%4,%5,%6,%7},{%8,%9},{%0,%1,%2,%3};"
        : "+f"(d[0]), "+f"(d[1]), "+f"(d[2]), "+f"(d[3])
        : "r"(a[0]), "r"(a[1]), "r"(a[2]), "r"(a[3]), "r"(b0), "r"(b1));
}
__device__ __forceinline__ void ldm_x4(uint32_t* r, uint32_t addr) {
    asm volatile("ldmatrix.sync.aligned.m8n8.x4.shared.b16 {%0,%1,%2,%3}, [%4];"
                 : "=r"(r[0]), "=r"(r[1]), "=r"(r[2]), "=r"(r[3]) : "r"(addr));
}

// ---------------- mma.sync GEMM (register-staged, pre-converted smem) ----------------
// TRANSB=1: C = A @ B^T, B:[N,K] K-major. TRANSB=0: C = A @ B, B:[K,N] N-major.
// A:[M,K]. BN = NT*32. K%32==0. 8 warps 2(m)x4(n), warp tile 64 x (NT*8).
// PREC=0: tf32 single. PREC=1: bf16 3-term hi/lo split.
// EXPA=1 (PREC=0 only): A elements transformed p=exp(x*scale - rsm[row])*rsis[row].
template<int NT, bool TRANSB, int PREC, int EXPA>
__global__ void __launch_bounds__(256, 2)
mma_gemm(const float* __restrict__ A, const float* __restrict__ B, float* __restrict__ C,
         int K, int lda, int ldb, int ldc, long sA, long sB, long sC,
         const float* __restrict__ rsm, const float* __restrict__ rsis, float escale)
{
    constexpr int BN   = NT * 32;
    constexpr int A_ST = (PREC == 0) ? 128 * 36 : 128 * 20 * 2;   // u32 per stage
    constexpr int B_ST = TRANSB ? ((PREC == 0) ? BN * 36 : BN * 20 * 2)
                                : ((PREC == 0) ? 32 * (BN + 8) : 16 * (BN + 8) * 2);
    constexpr int STG  = A_ST + B_ST;
    constexpr int BQ   = BN / 4;

    extern __shared__ uint32_t smu[];
    const uint32_t smem_base = smem_u32(smu);

    const int tid  = threadIdx.x;
    const int warp = tid >> 5;
    const int lane = tid & 31;
    const int wm = (warp >> 2) * 64;
    const int wn = (warp & 3) * (BN / 4);
    const int g  = lane >> 2;
    const int tq = lane & 3;

    const int bm = blockIdx.y * 128;
    const int bn = blockIdx.x * BN;
    A += (long)blockIdx.z * sA + (long)bm * lda;
    if (TRANSB) B += (long)blockIdx.z * sB + (long)bn * ldb;
    else        B += (long)blockIdx.z * sB + bn;
    C += (long)blockIdx.z * sC + (long)bm * ldc + bn;

    // per-thread A-row softmax stats (rows tid>>3 + 32*i)
    float e_m[4], e_is[4];
    if (EXPA) {
        const int rb = tid >> 3;
#pragma unroll
        for (int i = 0; i < 4; i++) {
            int r = blockIdx.z * QLEN + bm + rb + 32 * i;
            e_m[i]  = rsm[r];
            e_is[i] = rsis[r];
        }
    }

    const int NC = K >> 5;

    float acc[4][NT][4];
#pragma unroll
    for (int i = 0; i < 4; i++)
#pragma unroll
        for (int j = 0; j < NT; j++)
#pragma unroll
            for (int l = 0; l < 4; l++) acc[i][j][l] = 0.f;

    float4 rA[4];
    float4 rB[4];

    auto ldg_chunk = [&](int c) {
        const float* ga = A + c * 32;
#pragma unroll
        for (int i = 0; i < 4; i++) {
            int idx = tid + i * 256;
            int r = idx >> 3, c4 = (idx & 7) << 2;
            rA[i] = *(const float4*)(ga + (long)r * lda + c4);
        }
        if (TRANSB) {
            const float* gb = B + c * 32;
#pragma unroll
            for (int i = 0; i < NT; i++) {
                int idx = tid + i * 256;
                int r = idx >> 3, c4 = (idx & 7) << 2;
                rB[i] = *(const float4*)(gb + (long)r * ldb + c4);
            }
        } else if (PREC == 0) {
            const float* gb = B + (long)(c * 32) * ldb;
#pragma unroll
            for (int i = 0; i < NT; i++) {
                int idx = tid + i * 256;
                int r = idx / BQ, c4 = (idx % BQ) << 2;
                rB[i] = *(const float4*)(gb + (long)r * ldb + c4);
            }
        } else {
            const float* gb = B + (long)(c * 32) * ldb;
#pragma unroll
            for (int i = 0; i < 2; i++) {
                int u = tid + i * 256;
                if (u < 16 * BQ) {
                    int kp = u / BQ, c4 = (u % BQ) << 2;
                    rB[2 * i]     = *(const float4*)(gb + (long)(2 * kp) * ldb + c4);
                    rB[2 * i + 1] = *(const float4*)(gb + (long)(2 * kp + 1) * ldb + c4);
                }
            }
        }
    };

    auto sts_chunk = [&](int sbase) {
        uint32_t* sa = smu + sbase;
        uint32_t* sb = smu + sbase + A_ST;
        if (PREC == 0) {
#pragma unroll
            for (int i = 0; i < 4; i++) {
                int idx = tid + i * 256;
                int r = idx >> 3, c4 = (idx & 7) << 2;
                float4 v = rA[i];
                if (EXPA) {
                    v.x = __expf(fmaf(v.x, escale, -e_m[i])) * e_is[i];
                    v.y = __expf(fmaf(v.y, escale, -e_m[i])) * e_is[i];
                    v.z = __expf(fmaf(v.z, escale, -e_m[i])) * e_is[i];
                    v.w = __expf(fmaf(v.w, escale, -e_m[i])) * e_is[i];
                }
                uint4 w = { f2tf(v.x), f2tf(v.y), f2tf(v.z), f2tf(v.w) };
                *(uint4*)&sa[r * 36 + c4] = w;
            }
            if (TRANSB) {
#pragma unroll
                for (int i = 0; i < NT; i++) {
                    int idx = tid + i * 256;
                    int r = idx >> 3, c4 = (idx & 7) << 2;
                    uint4 w = { f2tf(rB[i].x), f2tf(rB[i].y), f2tf(rB[i].z), f2tf(rB[i].w) };
                    *(uint4*)&sb[r * 36 + c4] = w;
                }
            } else {
#pragma unroll
                for (int i = 0; i < NT; i++) {
                    int idx = tid + i * 256;
                    int r = idx / BQ, c4 = (idx % BQ) << 2;
                    uint4 w = { f2tf(rB[i].x), f2tf(rB[i].y), f2tf(rB[i].z), f2tf(rB[i].w) };
                    *(uint4*)&sb[r * (BN + 8) + c4] = w;
                }
            }
        } else {
#pragma unroll
            for (int i = 0; i < 4; i++) {
                int idx = tid + i * 256;
                int r = idx >> 3, cu = (idx & 7) << 1;
                float4 v = rA[i];
                uint32_t h0 = pack_bf16(v.x, v.y), h1 = pack_bf16(v.z, v.w);
                uint32_t l0 = pack_bf16(v.x - bflo(h0), v.y - bfhi(h0));
                uint32_t l1 = pack_bf16(v.z - bflo(h1), v.w - bfhi(h1));
                *(uint2*)&sa[r * 20 + cu]            = make_uint2(h0, h1);
                *(uint2*)&sa[128 * 20 + r * 20 + cu] = make_uint2(l0, l1);
            }
            if (TRANSB) {
#pragma unroll
                for (int i = 0; i < NT; i++) {
                    int idx = tid + i * 256;
                    int r = idx >> 3, cu = (idx & 7) << 1;
                    float4 v = rB[i];
                    uint32_t h0 = pack_bf16(v.x, v.y), h1 = pack_bf16(v.z, v.w);
                    uint32_t l0 = pack_bf16(v.x - bflo(h0), v.y - bfhi(h0));
                    uint32_t l1 = pack_bf16(v.z - bflo(h1), v.w - bfhi(h1));
                    *(uint2*)&sb[r * 20 + cu]           = make_uint2(h0, h1);
                    *(uint2*)&sb[BN * 20 + r * 20 + cu] = make_uint2(l0, l1);
                }
            } else {
#pragma unroll
                for (int i = 0; i < 2; i++) {
                    int u = tid + i * 256;
                    if (u < 16 * BQ) {
                        int kp = u / BQ, c4 = (u % BQ) << 2;
                        float4 v0 = rB[2 * i], v1 = rB[2 * i + 1];
                        uint4 h = { pack_bf16(v0.x, v1.x), pack_bf16(v0.y, v1.y),
                                    pack_bf16(v0.z, v1.z), pack_bf16(v0.w, v1.w) };
                        uint4 l = { pack_bf16(v0.x - bflo(h.x), v1.x - bfhi(h.x)),
                                    pack_bf16(v0.y - bflo(h.y), v1.y - bfhi(h.y)),
                                    pack_bf16(v0.z - bflo(h.z), v1.z - bfhi(h.z)),
                                    pack_bf16(v0.w - bflo(h.w), v1.w - bfhi(h.w)) };
                        *(uint4*)&sb[kp * (BN + 8) + c4]                 = h;
                        *(uint4*)&sb[16 * (BN + 8) + kp * (BN + 8) + c4] = l;
                    }
                }
            }
        }
    };

    auto compute = [&](int sbase) {
        const uint32_t aB = smem_base + (uint32_t)sbase * 4;
        const uint32_t bB = smem_base + (uint32_t)(sbase + A_ST) * 4;
        const int mat = lane >> 3;
        if (PREC == 0) {
#pragma unroll
            for (int kk = 0; kk < 4; kk++) {
                const int kcu = kk * 8;
                uint32_t af[4][4];
#pragma unroll
                for (int mt = 0; mt < 4; mt++) {
                    int row = wm + mt * 16 + ((mat & 1) << 3) + (lane & 7);
                    int col = kcu + ((mat >> 1) << 2);
                    ldm_x4(af[mt], aB + (uint32_t)(row * 36 + col) * 4);
                }
                if (TRANSB) {
#pragma unroll
                    for (int np = 0; np < NT / 2; np++) {
                        uint32_t bf[4];
                        int row = wn + (2 * np + (mat >> 1)) * 8 + (lane & 7);
                        int col = kcu + ((mat & 1) << 2);
                        ldm_x4(bf, bB + (uint32_t)(row * 36 + col) * 4);
#pragma unroll
                        for (int mt = 0; mt < 4; mt++) {
                            mma8(acc[mt][2 * np],     af[mt], bf[0], bf[1]);
                            mma8(acc[mt][2 * np + 1], af[mt], bf[2], bf[3]);
                        }
                    }
                } else {
                    const uint32_t* sb = smu + sbase + A_ST;
#pragma unroll
                    for (int nt = 0; nt < NT; nt++) {
                        int n0 = wn + nt * 8 + g;
                        uint32_t b0 = sb[(kcu + tq) * (BN + 8) + n0];
                        uint32_t b1 = sb[(kcu + tq + 4) * (BN + 8) + n0];
#pragma unroll
                        for (int mt = 0; mt < 4; mt++)
                            mma8(acc[mt][nt], af[mt], b0, b1);
                    }
                }
            }
        } else {
#pragma unroll
            for (int kk = 0; kk < 2; kk++) {
                const int kcu = kk * 8;
                uint32_t ah[4][4], al[4][4];
#pragma unroll
                for (int mt = 0; mt < 4; mt++) {
                    int row = wm + mt * 16 + ((mat & 1) << 3) + (lane & 7);
                    int col = kcu + ((mat >> 1) << 2);
                    ldm_x4(ah[mt], aB + (uint32_t)(row * 20 + col) * 4);
                    ldm_x4(al[mt], aB + (uint32_t)(128 * 20 + row * 20 + col) * 4);
                }
                if (TRANSB) {
#pragma unroll
                    for (int np = 0; np < NT / 2; np++) {
                        uint32_t bh[4], bl[4];
                        int row = wn + (2 * np + (mat >> 1)) * 8 + (lane & 7);
                        int col = kcu + ((mat & 1) << 2);
                        ldm_x4(bh, bB + (uint32_t)(row * 20 + col) * 4);
                        ldm_x4(bl, bB + (uint32_t)(BN * 20 + row * 20 + col) * 4);
#pragma unroll
                        for (int mt = 0; mt < 4; mt++) {
                            mma16(acc[mt][2 * np], ah[mt], bh[0], bh[1]);
                            mma16(acc[mt][2 * np], al[mt], bh[0], bh[1]);
                            mma16(acc[mt][2 * np], ah[mt], bl[0], bl[1]);
                            mma16(acc[mt][2 * np + 1], ah[mt], bh[2], bh[3]);
                            mma16(acc[mt][2 * np + 1], al[mt], bh[2], bh[3]);
                            mma16(acc[mt][2 * np + 1], ah[mt], bl[2], bl[3]);
                        }
                    }
                } else {
                    const uint32_t* sbh = smu + sbase + A_ST;
                    const uint32_t* sbl = sbh + 16 * (BN + 8);
#pragma unroll
                    for (int nt = 0; nt < NT; nt++) {
                        int n0 = wn + nt * 8 + g;
                        uint32_t b0h = sbh[(kcu + tq) * (BN + 8) + n0];
                        uint32_t b1h = sbh[(kcu + tq + 4) * (BN + 8) + n0];
                        uint32_t b0l = sbl[(kcu + tq) * (BN + 8) + n0];
                        uint32_t b1l = sbl[(kcu + tq + 4) * (BN + 8) + n0];
#pragma unroll
                        for (int mt = 0; mt < 4; mt++) {
                            mma16(acc[mt][nt], ah[mt], b0h, b1h);
                            mma16(acc[mt][nt], al[mt], b0h, b1h);
                            mma16(acc[mt][nt], ah[mt], b0l, b1l);
                        }
                    }
                }
            }
        }
    };

    // ---- pipeline (single barrier per chunk) ----
    ldg_chunk(0);
    sts_chunk(0);
    __syncthreads();
    for (int c = 0; c < NC; c++) {
        if (c + 1 < NC) ldg_chunk(c + 1);
        compute((c & 1) * STG);
        if (c + 1 < NC) {
            sts_chunk(((c + 1) & 1) * STG);
            __syncthreads();
        }
    }

    // ---- epilogue ----
#pragma unroll
    for (int mt = 0; mt < 4; mt++) {
        const int r0 = wm + mt * 16 + g;
#pragma unroll
        for (int nt = 0; nt < NT; nt++) {
            const int c0 = wn + nt * 8 + tq * 2;
            *(float2*)&C[(long)r0 * ldc + c0]       = make_float2(acc[mt][nt][0], acc[mt][nt][1]);
            *(float2*)&C[(long)(r0 + 8) * ldc + c0] = make_float2(acc[mt][nt][2], acc[mt][nt][3]);
        }
    }
}

// ---------------- Row stats: m*scale and 1/sum(exp((x-m)*scale)) ----------------
__global__ void rowstat(const float* __restrict__ X, float* __restrict__ rm,
                        float* __restrict__ ris, int cols, float scale)
{
    const long row = blockIdx.x;
    const float4* x = (const float4*)(X + row * (long)cols);
    const int n4 = cols >> 2;
    const int tid = threadIdx.x;   // 256
    __shared__ float red[256];

    float m = -INFINITY;
    for (int c = tid; c < n4; c += 256) {
        float4 v = x[c];
        m = fmaxf(m, fmaxf(fmaxf(v.x, v.y), fmaxf(v.z, v.w)));
    }
    red[tid] = m; __syncthreads();
    for (int s = 128; s > 0; s >>= 1) { if (tid < s) red[tid] = fmaxf(red[tid], red[tid + s]); __syncthreads(); }
    m = red[0]; __syncthreads();
    const float msc = m * scale;

    float sum = 0.f;
    for (int c = tid; c < n4; c += 256) {
        float4 v = x[c];
        sum += __expf(fmaf(v.x, scale, -msc));
        sum += __expf(fmaf(v.y, scale, -msc));
        sum += __expf(fmaf(v.z, scale, -msc));
        sum += __expf(fmaf(v.w, scale, -msc));
    }
    red[tid] = sum; __syncthreads();
    for (int s = 128; s > 0; s >>= 1) { if (tid < s) red[tid] += red[tid + s]; __syncthreads(); }
    if (tid == 0) { rm[row] = msc; ris[row] = 1.f / red[0]; }
}

// ---------------- Transpose: out[c][r] = in[r*ldin + c] ----------------
__global__ void transpose_k(const float* __restrict__ in, float* __restrict__ out,
                            int R, int ldin)
{
    __shared__ float t[32][33];
    const int c0 = blockIdx.x * 32, r0 = blockIdx.y * 32;
    const int x = threadIdx.x, y0 = threadIdx.y;
    #pragma unroll
    for (int i = y0; i < 32; i += 8) t[i][x] = in[(long)(r0 + i) * ldin + c0 + x];
    __syncthreads();
    #pragma unroll
    for (int i = y0; i < 32; i += 8) out[(long)(c0 + i) * R + r0 + x] = t[x][i];
}

// ---------------- Split-K reduction ----------------
__global__ void reduce_slices(const float4* __restrict__ in, float4* __restrict__ out,
                              int n4, int S)
{
    int i = blockIdx.x * 256 + threadIdx.x;
    if (i >= n4) return;
    float4 a = in[i];
    for (int s = 1; s < S; s++) {
        float4 b = in[i + (long)s * n4];
        a.x += b.x; a.y += b.y; a.z += b.z; a.w += b.w;
    }
    out[i] = a;
}

// ---------------- RMSNorm (in place) ----------------
__global__ void rmsnorm_rows(float* __restrict__ X, const float* __restrict__ g, int cols)
{
    const long row = blockIdx.x;
    float* x = X + row * (long)cols;
    const int tid = threadIdx.x;
    const int n4 = cols >> 2;
    float ss = 0.f;
    for (int c = tid; c < n4; c += blockDim.x) {
        float4 v = ((const float4*)x)[c];
        ss += v.x * v.x + v.y * v.y + v.z * v.z + v.w * v.w;
    }
    __shared__ float red[256];
    red[tid] = ss; __syncthreads();
    for (int s = 128; s > 0; s >>= 1) { if (tid < s) red[tid] += red[tid + s]; __syncthreads(); }
    const float inv = rsqrtf(red[0] / (float)cols + EPSF);
    for (int c = tid; c < n4; c += blockDim.x) {
        float4 v = ((const float4*)x)[c];
        float4 w = ((const float4*)g)[c];
        v.x *= inv * w.x; v.y *= inv * w.y; v.z *= inv * w.z; v.w *= inv * w.w;
        ((float4*)x)[c] = v;
    }
}

// ---------------- Build K_comb ----------------
__global__ void build_K(const float* __restrict__ raw, const float* __restrict__ g,
                        const int* __restrict__ kvpos, float* __restrict__ Kc)
{
    const int s = blockIdx.x;
    const float* r = raw + (long)s * DQK;
    float* k = Kc + (long)s * DQK;
    const int tid = threadIdx.x;   // 128

    float ss = 0.f;
    for (int c = tid; c < RKV / 4; c += 128) {
        float4 v = ((const float4*)r)[c];
        ss += v.x * v.x + v.y * v.y + v.z * v.z + v.w * v.w;
    }
    __shared__ float red[128];
    red[tid] = ss; __syncthreads();
    for (int st = 64; st > 0; st >>= 1) { if (tid < st) red[tid] += red[tid + st]; __syncthreads(); }
    const float inv = rsqrtf(red[0] / (float)RKV + EPSF);
    for (int c = tid; c < RKV / 4; c += 128) {
        float4 v = ((const float4*)r)[c];
        float4 w = ((const float4*)g)[c];
        v.x *= inv * w.x; v.y *= inv * w.y; v.z *= inv * w.z; v.w *= inv * w.w;
        ((float4*)k)[c] = v;
    }

    if (tid < 32) {
        const int j = tid;
        const float x0 = r[RKV + 2 * j];
        const float x1 = r[RKV + 2 * j + 1];
        const float pos = (float)kvpos[s];
        const float invf = powf(10000.f, -(float)j / 32.f);
        float cs, sn; sincosf(pos * invf, &sn, &cs);
        k[RKV + j]      = x0 * cs - x1 * sn;
        k[RKV + 32 + j] = x0 * sn + x1 * cs;
    }
}

// ---------------- RoPE for q_pe ----------------
__global__ void rope_Q(const float* __restrict__ qfull, const int* __restrict__ qpos,
                       float* __restrict__ Qc)
{
    const int t = blockIdx.x;
    const int h = blockIdx.y;
    const int j = threadIdx.x;   // 32
    const float* src = qfull + (long)t * QB_COLS + h * (DNOPE + DROPE) + DNOPE;
    const float x0 = src[2 * j];
    const float x1 = src[2 * j + 1];
    const float pos = (float)qpos[t];
    const float invf = powf(10000.f, -(float)j / 32.f);
    float cs, sn; sincosf(pos * invf, &sn, &cs);
    float* dst = Qc + ((long)h * QLEN + t) * DQK + RKV;
    dst[j]      = x0 * cs - x1 * sn;
    dst[32 + j] = x0 * sn + x1 * cs;
}

// ---------------- Launch ----------------
static inline float* sym(const void* s)
{
    void* p = nullptr;
    cudaGetSymbolAddress(&p, s);
    return (float*)p;
}

static inline int smem_b(int NT, bool transb, int prec)
{
    int a = (prec == 0) ? 128 * 36 : 128 * 40;
    int b = transb ? ((prec == 0) ? NT * 32 * 36 : NT * 32 * 40)
                   : 32 * (NT * 32 + 8);
    return 2 * (a + b) * 4;
}

extern "C" void kernel_launch(void* const* d_in, const int* in_sizes, int n_in,
                              void* d_out, int out_size)
{
    const float* hq    = (const float*)d_in[0];
    const float* hkv   = (const float*)d_in[1];
    const float* W_qa  = (const float*)d_in[2];
    const float* gqa   = (const float*)d_in[3];
    const float* W_qb  = (const float*)d_in[4];
    const float* W_kva = (const float*)d_in[5];
    const float* gkva  = (const float*)d_in[6];
    const float* W_kvb = (const float*)d_in[7];
    const float* W_o   = (const float*)d_in[8];
    const int*   qpos  = (const int*)d_in[9];
    const int*   kvpos = (const int*)d_in[10];
    float*       out   = (float*)d_out;

    float* qa     = sym(g_qa_buf);
    float* qfull  = sym(g_qfull);
    float* ckvraw = sym(g_ckvraw);
    float* Kc     = sym(g_Kc);
    float* ckvT   = sym(g_ckvT);
    float* Qc     = sym(g_Qc);
    float* logits = sym(g_logits);
    float* oc     = sym(g_oc);
    float* ao     = sym(g_ao);
    float* part   = sym(g_part);
    float* rowm   = sym(g_rowm);
    float* rowis  = sym(g_rowis);

    const float scale = 1.0f / sqrtf(192.0f);

    cudaFuncSetAttribute(mma_gemm<4, false, 1, 0>, cudaFuncAttributeMaxDynamicSharedMemorySize, smem_b(4, false, 1));
    cudaFuncSetAttribute(mma_gemm<3, false, 1, 0>, cudaFuncAttributeMaxDynamicSharedMemorySize, smem_b(3, false, 1));
    cudaFuncSetAttribute(mma_gemm<4, true,  1, 0>, cudaFuncAttributeMaxDynamicSharedMemorySize, smem_b(4, true, 1));
    cudaFuncSetAttribute(mma_gemm<4, true,  0, 0>, cudaFuncAttributeMaxDynamicSharedMemorySize, smem_b(4, true, 0));
    cudaFuncSetAttribute(mma_gemm<4, true,  0, 1>, cudaFuncAttributeMaxDynamicSharedMemorySize, smem_b(4, true, 0));

    // 1) qa = hq @ W_qa : (256,1536), K=5120  [NN bf16x3, split-K 8]
    mma_gemm<4, false, 1, 0><<<dim3(RQ / 128, 2, 8), 256, smem_b(4, false, 1)>>>(
        hq, W_qa, part, HID / 8, HID, RQ, RQ,
        (long)(HID / 8), (long)(HID / 8) * RQ, (long)QLEN * RQ, nullptr, nullptr, 0.f);
    reduce_slices<<<(QLEN * RQ / 4 + 255) / 256, 256>>>((const float4*)part, (float4*)qa, QLEN * RQ / 4, 8);

    // 2) rmsnorm(qa)
    rmsnorm_rows<<<QLEN, 256>>>(qa, gqa, RQ);

    // 3) qfull = qa @ W_qb : (256,24576), K=1536  [NN bf16x3]
    mma_gemm<4, false, 1, 0><<<dim3(QB_COLS / 128, 2, 1), 256, smem_b(4, false, 1)>>>(
        qa, W_qb, qfull, RQ, RQ, QB_COLS, QB_COLS, 0, 0, 0, nullptr, nullptr, 0.f);

    // 4) ckvraw = hkv @ W_kva : (4096,576), K=5120  [NN bf16x3, BN=96]
    mma_gemm<3, false, 1, 0><<<dim3(DQK / 96, SLEN / 128, 1), 256, smem_b(3, false, 1)>>>(
        hkv, W_kva, ckvraw, HID, HID, DQK, DQK, 0, 0, 0, nullptr, nullptr, 0.f);

    // 5) K_comb; ckvT = Kc[:, :512]^T
    build_K<<<SLEN, 128>>>(ckvraw, gkva, kvpos, Kc);
    transpose_k<<<dim3(RKV / 32, SLEN / 32), dim3(32, 8)>>>(Kc, ckvT, SLEN, DQK);

    // 6) q_c[h] = q_nope[h] @ q_absorb[h] : batched (256,512), K=128  [NN bf16x3]
    mma_gemm<4, false, 1, 0><<<dim3(RKV / 128, 2, NHEADS), 256, smem_b(4, false, 1)>>>(
        qfull, W_kvb, Qc, DNOPE,
        QB_COLS, RKV, DQK,
        (long)(DNOPE + DROPE), (long)(DNOPE + DNOPE) * RKV, (long)QLEN * DQK, nullptr, nullptr, 0.f);

    // 7) rope q_pe
    rope_Q<<<dim3(QLEN, NHEADS), 32>>>(qfull, qpos, Qc);

    // 8) logits[h] = Q_comb[h] @ K_comb^T : batched (256,4096), K=576  [NT tf32]
    mma_gemm<4, true, 0, 0><<<dim3(SLEN / 128, 2, NHEADS), 256, smem_b(4, true, 0)>>>(
        Qc, Kc, logits, DQK,
        DQK, DQK, SLEN,
        (long)QLEN * DQK, 0, (long)QLEN * SLEN, nullptr, nullptr, 0.f);

    // 9) row stats (replaces softmax)
    rowstat<<<NHEADS * QLEN, 256>>>(logits, rowm, rowis, SLEN, scale);

    // 10) oc[h] = softmax(logits[h]) @ ckv : batched (256,512), K=4096  [NT tf32 + EXPA]
    mma_gemm<4, true, 0, 1><<<dim3(RKV / 128, 2, NHEADS), 256, smem_b(4, true, 0)>>>(
        logits, ckvT, oc, SLEN,
        SLEN, SLEN, RKV,
        (long)QLEN * SLEN, 0, (long)QLEN * RKV, rowm, rowis, scale);

    // 11) ao[:, h*128:] = oc[h] @ out_absorb[h]^T : batched (256,128), K=512  [NT bf16x3]
    mma_gemm<4, true, 1, 0><<<dim3(1, 2, NHEADS), 256, smem_b(4, true, 1)>>>(
        oc, W_kvb + (long)DNOPE * RKV, ao, RKV,
        RKV, RKV, AO_COLS,
        (long)QLEN * RKV, (long)(DNOPE + DNOPE) * RKV, (long)DNOPE, nullptr, nullptr, 0.f);

    // 12) out = ao @ W_o : (256,5120), K=16384  [NN bf16x3, split-K 4]
    mma_gemm<4, false, 1, 0><<<dim3(HID / 128, 2, 4), 256, smem_b(4, false, 1)>>>(
        ao, W_o, part, AO_COLS / 4, AO_COLS, HID, HID,
        (long)(AO_COLS / 4), (long)(AO_COLS / 4) * HID, (long)QLEN * HID, nullptr, nullptr, 0.f);
    reduce_slices<<<(QLEN * HID / 4 + 255) / 256, 256>>>((const float4*)part, (float4*)out, QLEN * HID / 4, 4);
}

// round 8
// speedup vs baseline: 1.6310x; 1.0768x over previous
#include <cuda_runtime.h>
#include <math.h>
#include <stdint.h>

// ---------------- Problem constants ----------------
#define NHEADS   128
#define DNOPE    128
#define DROPE    64
#define DQK      576
#define RKV      512
#define RQ       1536
#define HID      5120
#define QLEN     256
#define SLEN     4096
#define QB_COLS  24576
#define AO_COLS  16384
#define EPSF     1e-6f
#define NTILES_S (SLEN / 128)    // 32

// ---------------- Scratch (device globals) ----------------
__device__ __align__(128) float g_qa_buf [QLEN * RQ];
__device__ __align__(128) float g_qfull  [QLEN * QB_COLS];
__device__ __align__(128) float g_ckvraw [SLEN * DQK];
__device__ __align__(128) float g_Kc     [SLEN * DQK];
__device__ __align__(128) float g_ckvT   [(size_t)RKV * SLEN];
__device__ __align__(128) float g_Qc     [(size_t)NHEADS * QLEN * DQK];
__device__ __align__(128) float g_logits [(size_t)NHEADS * QLEN * SLEN];   // 512 MB
__device__ __align__(128) float g_oc     [(size_t)NHEADS * QLEN * RKV];
__device__ __align__(128) float g_ao     [QLEN * AO_COLS];
__device__ __align__(128) float g_part   [8 * QLEN * HID];                  // split-K partials
__device__ __align__(128) float g_rowm   [NHEADS * QLEN];                   // max * scale
__device__ __align__(128) float g_rowis  [NHEADS * QLEN];                   // 1 / sum(exp)
__device__ __align__(128) float g_tmax   [(size_t)NHEADS * QLEN * NTILES_S];
__device__ __align__(128) float g_tsum   [(size_t)NHEADS * QLEN * NTILES_S];

// ---------------- helpers ----------------
__device__ __forceinline__ uint32_t smem_u32(const void* p) {
    uint32_t a;
    asm("{ .reg .u64 t; cvta.to.shared.u64 t, %1; cvt.u32.u64 %0, t; }" : "=r"(a) : "l"(p));
    return a;
}
__device__ __forceinline__ uint32_t f2tf(float x) {
    uint32_t r;
    asm("cvt.rna.tf32.f32 %0, %1;" : "=r"(r) : "f"(x));
    return r;
}
__device__ __forceinline__ uint32_t pack_bf16(float lo, float hi) {
    uint32_t r;
    asm("cvt.rn.bf16x2.f32 %0, %1, %2;" : "=r"(r) : "f"(hi), "f"(lo));
    return r;
}
__device__ __forceinline__ float bflo(uint32_t p) { return __uint_as_float(p << 16); }
__device__ __forceinline__ float bfhi(uint32_t p) { return __uint_as_float(p & 0xffff0000u); }

__device__ __forceinline__ void mma8(float* d, const uint32_t* a, uint32_t b0, uint32_t b1) {
    asm volatile(
        "mma.sync.aligned.m16n8k8.row.col.f32.tf32.tf32.f32 "
        "{%0,%1,%2,%3},{%4,%5,%6,%7},{%8,%9},{%0,%1,%2,%3};"
        : "+f"(d[0]), "+f"(d[1]), "+f"(d[2]), "+f"(d[3])
        : "r"(a[0]), "r"(a[1]), "r"(a[2]), "r"(a[3]), "r"(b0), "r"(b1));
}
__device__ __forceinline__ void mma16(float* d, const uint32_t* a, uint32_t b0, uint32_t b1) {
    asm volatile(
        "mma.sync.aligned.m16n8k16.row.col.f32.bf16.bf16.f32 "
        "{%0,%1,%2,%3},{%4,%5,%6,%7},{%8,%9},{%0,%1,%2,%3};"
        : "+f"(d[0]), "+f"(d[1]), "+f"(d[2]), "+f"(d[3])
        : "r"(a[0]), "r"(a[1]), "r"(a[2]), "r"(a[3]), "r"(b0), "r"(b1));
}
__device__ __forceinline__ void ldm_x4(uint32_t* r, uint32_t addr) {
    asm volatile("ldmatrix.sync.aligned.m8n8.x4.shared.b16 {%0,%1,%2,%3}, [%4];"
                 : "=r"(r[0]), "=r"(r[1]), "=r"(r[2]), "=r"(r[3]) : "r"(addr));
}

// ---------------- mma.sync GEMM (register-staged, pre-converted smem) ----------------
// TRANSB=1: C = A @ B^T, B:[N,K] K-major. TRANSB=0: C = A @ B, B:[K,N] N-major.
// A:[M,K]. BN = NT*32. K%32==0. 8 warps 2(m)x4(n), warp tile 64 x (NT*8).
// PREC=0: tf32 single. PREC=1: bf16 3-term hi/lo split.
// EXPA=1 (PREC=0): A transformed p=exp(x*escale - rsm[row])*rsis[row] at staging.
// STATS=1: epilogue also emits per-tile row max (scaled) and sum-exp into gtmax/gtsum.
template<int NT, bool TRANSB, int PREC, int EXPA, int STATS>
__global__ void __launch_bounds__(256, 2)
mma_gemm(const float* __restrict__ A, const float* __restrict__ B, float* __restrict__ C,
         int K, int lda, int ldb, int ldc, long sA, long sB, long sC,
         const float* __restrict__ rsm, const float* __restrict__ rsis, float escale,
         float* __restrict__ gtmax, float* __restrict__ gtsum)
{
    constexpr int BN   = NT * 32;
    constexpr int A_ST = (PREC == 0) ? 128 * 36 : 128 * 20 * 2;   // u32 per stage
    constexpr int B_ST = TRANSB ? ((PREC == 0) ? BN * 36 : BN * 20 * 2)
                                : ((PREC == 0) ? 32 * (BN + 8) : 16 * (BN + 8) * 2);
    constexpr int STG  = A_ST + B_ST;
    constexpr int BQ   = BN / 4;

    extern __shared__ uint32_t smu[];
    const uint32_t smem_base = smem_u32(smu);

    const int tid  = threadIdx.x;
    const int warp = tid >> 5;
    const int lane = tid & 31;
    const int wm = (warp >> 2) * 64;
    const int wn = (warp & 3) * (BN / 4);
    const int g  = lane >> 2;
    const int tq = lane & 3;

    const int bm = blockIdx.y * 128;
    const int bn = blockIdx.x * BN;
    A += (long)blockIdx.z * sA + (long)bm * lda;
    if (TRANSB) B += (long)blockIdx.z * sB + (long)bn * ldb;
    else        B += (long)blockIdx.z * sB + bn;
    C += (long)blockIdx.z * sC + (long)bm * ldc + bn;

    float e_m[4], e_is[4];
    if (EXPA) {
        const int rb = tid >> 3;
#pragma unroll
        for (int i = 0; i < 4; i++) {
            int r = blockIdx.z * QLEN + bm + rb + 32 * i;
            e_m[i]  = rsm[r];
            e_is[i] = rsis[r];
        }
    }

    const int NC = K >> 5;

    float acc[4][NT][4];
#pragma unroll
    for (int i = 0; i < 4; i++)
#pragma unroll
        for (int j = 0; j < NT; j++)
#pragma unroll
            for (int l = 0; l < 4; l++) acc[i][j][l] = 0.f;

    float4 rA[4];
    float4 rB[4];

    auto ldg_chunk = [&](int c) {
        const float* ga = A + c * 32;
#pragma unroll
        for (int i = 0; i < 4; i++) {
            int idx = tid + i * 256;
            int r = idx >> 3, c4 = (idx & 7) << 2;
            rA[i] = *(const float4*)(ga + (long)r * lda + c4);
        }
        if (TRANSB) {
            const float* gb = B + c * 32;
#pragma unroll
            for (int i = 0; i < NT; i++) {
                int idx = tid + i * 256;
                int r = idx >> 3, c4 = (idx & 7) << 2;
                rB[i] = *(const float4*)(gb + (long)r * ldb + c4);
            }
        } else if (PREC == 0) {
            const float* gb = B + (long)(c * 32) * ldb;
#pragma unroll
            for (int i = 0; i < NT; i++) {
                int idx = tid + i * 256;
                int r = idx / BQ, c4 = (idx % BQ) << 2;
                rB[i] = *(const float4*)(gb + (long)r * ldb + c4);
            }
        } else {
            const float* gb = B + (long)(c * 32) * ldb;
#pragma unroll
            for (int i = 0; i < 2; i++) {
                int u = tid + i * 256;
                if (u < 16 * BQ) {
                    int kp = u / BQ, c4 = (u % BQ) << 2;
                    rB[2 * i]     = *(const float4*)(gb + (long)(2 * kp) * ldb + c4);
                    rB[2 * i + 1] = *(const float4*)(gb + (long)(2 * kp + 1) * ldb + c4);
                }
            }
        }
    };

    auto sts_chunk = [&](int sbase) {
        uint32_t* sa = smu + sbase;
        uint32_t* sb = smu + sbase + A_ST;
        if (PREC == 0) {
#pragma unroll
            for (int i = 0; i < 4; i++) {
                int idx = tid + i * 256;
                int r = idx >> 3, c4 = (idx & 7) << 2;
                float4 v = rA[i];
                if (EXPA) {
                    v.x = __expf(fmaf(v.x, escale, -e_m[i])) * e_is[i];
                    v.y = __expf(fmaf(v.y, escale, -e_m[i])) * e_is[i];
                    v.z = __expf(fmaf(v.z, escale, -e_m[i])) * e_is[i];
                    v.w = __expf(fmaf(v.w, escale, -e_m[i])) * e_is[i];
                }
                uint4 w = { f2tf(v.x), f2tf(v.y), f2tf(v.z), f2tf(v.w) };
                *(uint4*)&sa[r * 36 + c4] = w;
            }
            if (TRANSB) {
#pragma unroll
                for (int i = 0; i < NT; i++) {
                    int idx = tid + i * 256;
                    int r = idx >> 3, c4 = (idx & 7) << 2;
                    uint4 w = { f2tf(rB[i].x), f2tf(rB[i].y), f2tf(rB[i].z), f2tf(rB[i].w) };
                    *(uint4*)&sb[r * 36 + c4] = w;
                }
            } else {
#pragma unroll
                for (int i = 0; i < NT; i++) {
                    int idx = tid + i * 256;
                    int r = idx / BQ, c4 = (idx % BQ) << 2;
                    uint4 w = { f2tf(rB[i].x), f2tf(rB[i].y), f2tf(rB[i].z), f2tf(rB[i].w) };
                    *(uint4*)&sb[r * (BN + 8) + c4] = w;
                }
            }
        } else {
#pragma unroll
            for (int i = 0; i < 4; i++) {
                int idx = tid + i * 256;
                int r = idx >> 3, cu = (idx & 7) << 1;
                float4 v = rA[i];
                uint32_t h0 = pack_bf16(v.x, v.y), h1 = pack_bf16(v.z, v.w);
                uint32_t l0 = pack_bf16(v.x - bflo(h0), v.y - bfhi(h0));
                uint32_t l1 = pack_bf16(v.z - bflo(h1), v.w - bfhi(h1));
                *(uint2*)&sa[r * 20 + cu]            = make_uint2(h0, h1);
                *(uint2*)&sa[128 * 20 + r * 20 + cu] = make_uint2(l0, l1);
            }
            if (TRANSB) {
#pragma unroll
                for (int i = 0; i < NT; i++) {
                    int idx = tid + i * 256;
                    int r = idx >> 3, cu = (idx & 7) << 1;
                    float4 v = rB[i];
                    uint32_t h0 = pack_bf16(v.x, v.y), h1 = pack_bf16(v.z, v.w);
                    uint32_t l0 = pack_bf16(v.x - bflo(h0), v.y - bfhi(h0));
                    uint32_t l1 = pack_bf16(v.z - bflo(h1), v.w - bfhi(h1));
                    *(uint2*)&sb[r * 20 + cu]           = make_uint2(h0, h1);
                    *(uint2*)&sb[BN * 20 + r * 20 + cu] = make_uint2(l0, l1);
                }
            } else {
#pragma unroll
                for (int i = 0; i < 2; i++) {
                    int u = tid + i * 256;
                    if (u < 16 * BQ) {
                        int kp = u / BQ, c4 = (u % BQ) << 2;
                        float4 v0 = rB[2 * i], v1 = rB[2 * i + 1];
                        uint4 h = { pack_bf16(v0.x, v1.x), pack_bf16(v0.y, v1.y),
                                    pack_bf16(v0.z, v1.z), pack_bf16(v0.w, v1.w) };
                        uint4 l = { pack_bf16(v0.x - bflo(h.x), v1.x - bfhi(h.x)),
                                    pack_bf16(v0.y - bflo(h.y), v1.y - bfhi(h.y)),
                                    pack_bf16(v0.z - bflo(h.z), v1.z - bfhi(h.z)),
                                    pack_bf16(v0.w - bflo(h.w), v1.w - bfhi(h.w)) };
                        *(uint4*)&sb[kp * (BN + 8) + c4]                 = h;
                        *(uint4*)&sb[16 * (BN + 8) + kp * (BN + 8) + c4] = l;
                    }
                }
            }
        }
    };

    auto compute = [&](int sbase) {
        const uint32_t aB = smem_base + (uint32_t)sbase * 4;
        const uint32_t bB = smem_base + (uint32_t)(sbase + A_ST) * 4;
        const int mat = lane >> 3;
        if (PREC == 0) {
#pragma unroll
            for (int kk = 0; kk < 4; kk++) {
                const int kcu = kk * 8;
                uint32_t af[4][4];
#pragma unroll
                for (int mt = 0; mt < 4; mt++) {
                    int row = wm + mt * 16 + ((mat & 1) << 3) + (lane & 7);
                    int col = kcu + ((mat >> 1) << 2);
                    ldm_x4(af[mt], aB + (uint32_t)(row * 36 + col) * 4);
                }
                if (TRANSB) {
#pragma unroll
                    for (int np = 0; np < NT / 2; np++) {
                        uint32_t bf[4];
                        int row = wn + (2 * np + (mat >> 1)) * 8 + (lane & 7);
                        int col = kcu + ((mat & 1) << 2);
                        ldm_x4(bf, bB + (uint32_t)(row * 36 + col) * 4);
#pragma unroll
                        for (int mt = 0; mt < 4; mt++) {
                            mma8(acc[mt][2 * np],     af[mt], bf[0], bf[1]);
                            mma8(acc[mt][2 * np + 1], af[mt], bf[2], bf[3]);
                        }
                    }
                } else {
                    const uint32_t* sb = smu + sbase + A_ST;
#pragma unroll
                    for (int nt = 0; nt < NT; nt++) {
                        int n0 = wn + nt * 8 + g;
                        uint32_t b0 = sb[(kcu + tq) * (BN + 8) + n0];
                        uint32_t b1 = sb[(kcu + tq + 4) * (BN + 8) + n0];
#pragma unroll
                        for (int mt = 0; mt < 4; mt++)
                            mma8(acc[mt][nt], af[mt], b0, b1);
                    }
                }
            }
        } else {
#pragma unroll
            for (int kk = 0; kk < 2; kk++) {
                const int kcu = kk * 8;
                uint32_t ah[4][4], al[4][4];
#pragma unroll
                for (int mt = 0; mt < 4; mt++) {
                    int row = wm + mt * 16 + ((mat & 1) << 3) + (lane & 7);
                    int col = kcu + ((mat >> 1) << 2);
                    ldm_x4(ah[mt], aB + (uint32_t)(row * 20 + col) * 4);
                    ldm_x4(al[mt], aB + (uint32_t)(128 * 20 + row * 20 + col) * 4);
                }
                if (TRANSB) {
#pragma unroll
                    for (int np = 0; np < NT / 2; np++) {
                        uint32_t bh[4], bl[4];
                        int row = wn + (2 * np + (mat >> 1)) * 8 + (lane & 7);
                        int col = kcu + ((mat & 1) << 2);
                        ldm_x4(bh, bB + (uint32_t)(row * 20 + col) * 4);
                        ldm_x4(bl, bB + (uint32_t)(BN * 20 + row * 20 + col) * 4);
#pragma unroll
                        for (int mt = 0; mt < 4; mt++) {
                            mma16(acc[mt][2 * np], ah[mt], bh[0], bh[1]);
                            mma16(acc[mt][2 * np], al[mt], bh[0], bh[1]);
                            mma16(acc[mt][2 * np], ah[mt], bl[0], bl[1]);
                            mma16(acc[mt][2 * np + 1], ah[mt], bh[2], bh[3]);
                            mma16(acc[mt][2 * np + 1], al[mt], bh[2], bh[3]);
                            mma16(acc[mt][2 * np + 1], ah[mt], bl[2], bl[3]);
                        }
                    }
                } else {
                    const uint32_t* sbh = smu + sbase + A_ST;
                    const uint32_t* sbl = sbh + 16 * (BN + 8);
#pragma unroll
                    for (int nt = 0; nt < NT; nt++) {
                        int n0 = wn + nt * 8 + g;
                        uint32_t b0h = sbh[(kcu + tq) * (BN + 8) + n0];
                        uint32_t b1h = sbh[(kcu + tq + 4) * (BN + 8) + n0];
                        uint32_t b0l = sbl[(kcu + tq) * (BN + 8) + n0];
                        uint32_t b1l = sbl[(kcu + tq + 4) * (BN + 8) + n0];
#pragma unroll
                        for (int mt = 0; mt < 4; mt++) {
                            mma16(acc[mt][nt], ah[mt], b0h, b1h);
                            mma16(acc[mt][nt], al[mt], b0h, b1h);
                            mma16(acc[mt][nt], ah[mt], b0l, b1l);
                        }
                    }
                }
            }
        }
    };

    // ---- pipeline (single barrier per chunk) ----
    ldg_chunk(0);
    sts_chunk(0);
    __syncthreads();
    for (int c = 0; c < NC; c++) {
        if (c + 1 < NC) ldg_chunk(c + 1);
        compute((c & 1) * STG);
        if (c + 1 < NC) {
            sts_chunk(((c + 1) & 1) * STG);
            __syncthreads();
        }
    }

    // ---- epilogue: store C ----
#pragma unroll
    for (int mt = 0; mt < 4; mt++) {
        const int r0 = wm + mt * 16 + g;
#pragma unroll
        for (int nt = 0; nt < NT; nt++) {
            const int c0 = wn + nt * 8 + tq * 2;
            *(float2*)&C[(long)r0 * ldc + c0]       = make_float2(acc[mt][nt][0], acc[mt][nt][1]);
            *(float2*)&C[(long)(r0 + 8) * ldc + c0] = make_float2(acc[mt][nt][2], acc[mt][nt][3]);
        }
    }

    // ---- epilogue: fused per-tile softmax stats ----
    if (STATS) {
        float* st_max = (float*)(smu + 2 * STG);
        float* st_sum = st_max + 512;
        const int nw = warp & 3;
        __syncthreads();
#pragma unroll
        for (int mt = 0; mt < 4; mt++) {
#pragma unroll
            for (int h = 0; h < 2; h++) {
                float mx = -INFINITY;
#pragma unroll
                for (int nt = 0; nt < NT; nt++) {
                    mx = fmaxf(mx, acc[mt][nt][2 * h]);
                    mx = fmaxf(mx, acc[mt][nt][2 * h + 1]);
                }
                mx = fmaxf(mx, __shfl_xor_sync(0xffffffffu, mx, 1));
                mx = fmaxf(mx, __shfl_xor_sync(0xffffffffu, mx, 2));
                if (tq == 0) st_max[(wm + mt * 16 + h * 8 + g) * 4 + nw] = mx * escale;
            }
        }
        __syncthreads();
#pragma unroll
        for (int mt = 0; mt < 4; mt++) {
#pragma unroll
            for (int h = 0; h < 2; h++) {
                const int row = wm + mt * 16 + h * 8 + g;
                float rm = fmaxf(fmaxf(st_max[row * 4 + 0], st_max[row * 4 + 1]),
                                 fmaxf(st_max[row * 4 + 2], st_max[row * 4 + 3]));
                float s = 0.f;
#pragma unroll
                for (int nt = 0; nt < NT; nt++) {
                    s += __expf(fmaf(acc[mt][nt][2 * h],     escale, -rm));
                    s += __expf(fmaf(acc[mt][nt][2 * h + 1], escale, -rm));
                }
                s += __shfl_xor_sync(0xffffffffu, s, 1);
                s += __shfl_xor_sync(0xffffffffu, s, 2);
                if (tq == 0) st_sum[row * 4 + nw] = s;
            }
        }
        __syncthreads();
        if (tid < 128) {
            float m = fmaxf(fmaxf(st_max[tid * 4 + 0], st_max[tid * 4 + 1]),
                            fmaxf(st_max[tid * 4 + 2], st_max[tid * 4 + 3]));
            float s = st_sum[tid * 4 + 0] + st_sum[tid * 4 + 1]
                    + st_sum[tid * 4 + 2] + st_sum[tid * 4 + 3];
            long grow = (long)blockIdx.z * QLEN + bm + tid;
            gtmax[grow * NTILES_S + blockIdx.x] = m;
            gtsum[grow * NTILES_S + blockIdx.x] = s;
        }
    }
}

// ---------------- Combine tile stats: rowm = max, rowis = 1/sum ----------------
__global__ void combine_stats(const float* __restrict__ tmax, const float* __restrict__ tsum,
                              float* __restrict__ rm, float* __restrict__ ris)
{
    const int row = blockIdx.x * 8 + threadIdx.y;
    const int t = threadIdx.x;   // 32 = NTILES_S
    float mv = tmax[(long)row * NTILES_S + t];
    float m = mv;
#pragma unroll
    for (int o = 16; o > 0; o >>= 1) m = fmaxf(m, __shfl_xor_sync(0xffffffffu, m, o));
    float s = tsum[(long)row * NTILES_S + t] * __expf(mv - m);
#pragma unroll
    for (int o = 16; o > 0; o >>= 1) s += __shfl_xor_sync(0xffffffffu, s, o);
    if (t == 0) { rm[row] = m; ris[row] = 1.f / s; }
}

// ---------------- Transpose: out[c][r] = in[r*ldin + c] ----------------
__global__ void transpose_k(const float* __restrict__ in, float* __restrict__ out,
                            int R, int ldin)
{
    __shared__ float t[32][33];
    const int c0 = blockIdx.x * 32, r0 = blockIdx.y * 32;
    const int x = threadIdx.x, y0 = threadIdx.y;
    #pragma unroll
    for (int i = y0; i < 32; i += 8) t[i][x] = in[(long)(r0 + i) * ldin + c0 + x];
    __syncthreads();
    #pragma unroll
    for (int i = y0; i < 32; i += 8) out[(long)(c0 + i) * R + r0 + x] = t[x][i];
}

// ---------------- Split-K reduction ----------------
__global__ void reduce_slices(const float4* __restrict__ in, float4* __restrict__ out,
                              int n4, int S)
{
    int i = blockIdx.x * 256 + threadIdx.x;
    if (i >= n4) return;
    float4 a = in[i];
    for (int s = 1; s < S; s++) {
        float4 b = in[i + (long)s * n4];
        a.x += b.x; a.y += b.y; a.z += b.z; a.w += b.w;
    }
    out[i] = a;
}

// ---------------- RMSNorm (in place) ----------------
__global__ void rmsnorm_rows(float* __restrict__ X, const float* __restrict__ g, int cols)
{
    const long row = blockIdx.x;
    float* x = X + row * (long)cols;
    const int tid = threadIdx.x;
    const int n4 = cols >> 2;
    float ss = 0.f;
    for (int c = tid; c < n4; c += blockDim.x) {
        float4 v = ((const float4*)x)[c];
        ss += v.x * v.x + v.y * v.y + v.z * v.z + v.w * v.w;
    }
    __shared__ float red[256];
    red[tid] = ss; __syncthreads();
    for (int s = 128; s > 0; s >>= 1) { if (tid < s) red[tid] += red[tid + s]; __syncthreads(); }
    const float inv = rsqrtf(red[0] / (float)cols + EPSF);
    for (int c = tid; c < n4; c += blockDim.x) {
        float4 v = ((const float4*)x)[c];
        float4 w = ((const float4*)g)[c];
        v.x *= inv * w.x; v.y *= inv * w.y; v.z *= inv * w.z; v.w *= inv * w.w;
        ((float4*)x)[c] = v;
    }
}

// ---------------- Build K_comb ----------------
__global__ void build_K(const float* __restrict__ raw, const float* __restrict__ g,
                        const int* __restrict__ kvpos, float* __restrict__ Kc)
{
    const int s = blockIdx.x;
    const float* r = raw + (long)s * DQK;
    float* k = Kc + (long)s * DQK;
    const int tid = threadIdx.x;   // 128

    float ss = 0.f;
    for (int c = tid; c < RKV / 4; c += 128) {
        float4 v = ((const float4*)r)[c];
        ss += v.x * v.x + v.y * v.y + v.z * v.z + v.w * v.w;
    }
    __shared__ float red[128];
    red[tid] = ss; __syncthreads();
    for (int st = 64; st > 0; st >>= 1) { if (tid < st) red[tid] += red[tid + st]; __syncthreads(); }
    const float inv = rsqrtf(red[0] / (float)RKV + EPSF);
    for (int c = tid; c < RKV / 4; c += 128) {
        float4 v = ((const float4*)r)[c];
        float4 w = ((const float4*)g)[c];
        v.x *= inv * w.x; v.y *= inv * w.y; v.z *= inv * w.z; v.w *= inv * w.w;
        ((float4*)k)[c] = v;
    }

    if (tid < 32) {
        const int j = tid;
        const float x0 = r[RKV + 2 * j];
        const float x1 = r[RKV + 2 * j + 1];
        const float pos = (float)kvpos[s];
        const float invf = powf(10000.f, -(float)j / 32.f);
        float cs, sn; sincosf(pos * invf, &sn, &cs);
        k[RKV + j]      = x0 * cs - x1 * sn;
        k[RKV + 32 + j] = x0 * sn + x1 * cs;
    }
}

// ---------------- RoPE for q_pe ----------------
__global__ void rope_Q(const float* __restrict__ qfull, const int* __restrict__ qpos,
                       float* __restrict__ Qc)
{
    const int t = blockIdx.x;
    const int h = blockIdx.y;
    const int j = threadIdx.x;   // 32
    const float* src = qfull + (long)t * QB_COLS + h * (DNOPE + DROPE) + DNOPE;
    const float x0 = src[2 * j];
    const float x1 = src[2 * j + 1];
    const float pos = (float)qpos[t];
    const float invf = powf(10000.f, -(float)j / 32.f);
    float cs, sn; sincosf(pos * invf, &sn, &cs);
    float* dst = Qc + ((long)h * QLEN + t) * DQK + RKV;
    dst[j]      = x0 * cs - x1 * sn;
    dst[32 + j] = x0 * sn + x1 * cs;
}

// ---------------- Launch ----------------
static inline float* sym(const void* s)
{
    void* p = nullptr;
    cudaGetSymbolAddress(&p, s);
    return (float*)p;
}

static inline int smem_b(int NT, bool transb, int prec, int stats = 0)
{
    int a = (prec == 0) ? 128 * 36 : 128 * 40;
    int b = transb ? ((prec == 0) ? NT * 32 * 36 : NT * 32 * 40)
                   : 32 * (NT * 32 + 8);
    return 2 * (a + b) * 4 + (stats ? 4096 : 0);
}

extern "C" void kernel_launch(void* const* d_in, const int* in_sizes, int n_in,
                              void* d_out, int out_size)
{
    const float* hq    = (const float*)d_in[0];
    const float* hkv   = (const float*)d_in[1];
    const float* W_qa  = (const float*)d_in[2];
    const float* gqa   = (const float*)d_in[3];
    const float* W_qb  = (const float*)d_in[4];
    const float* W_kva = (const float*)d_in[5];
    const float* gkva  = (const float*)d_in[6];
    const float* W_kvb = (const float*)d_in[7];
    const float* W_o   = (const float*)d_in[8];
    const int*   qpos  = (const int*)d_in[9];
    const int*   kvpos = (const int*)d_in[10];
    float*       out   = (float*)d_out;

    float* qa     = sym(g_qa_buf);
    float* qfull  = sym(g_qfull);
    float* ckvraw = sym(g_ckvraw);
    float* Kc     = sym(g_Kc);
    float* ckvT   = sym(g_ckvT);
    float* Qc     = sym(g_Qc);
    float* logits = sym(g_logits);
    float* oc     = sym(g_oc);
    float* ao     = sym(g_ao);
    float* part   = sym(g_part);
    float* rowm   = sym(g_rowm);
    float* rowis  = sym(g_rowis);
    float* tmax   = sym(g_tmax);
    float* tsum   = sym(g_tsum);

    const float scale = 1.0f / sqrtf(192.0f);

    // one-time resources (work per call is identical; resources only)
    static cudaStream_t s2 = nullptr;
    static cudaEvent_t evF = nullptr, evKV = nullptr;
    if (!s2) {
        cudaStreamCreateWithFlags(&s2, cudaStreamNonBlocking);
        cudaEventCreateWithFlags(&evF,  cudaEventDisableTiming);
        cudaEventCreateWithFlags(&evKV, cudaEventDisableTiming);
        cudaFuncSetAttribute(mma_gemm<4, false, 1, 0, 0>, cudaFuncAttributeMaxDynamicSharedMemorySize, smem_b(4, false, 1));
        cudaFuncSetAttribute(mma_gemm<3, false, 1, 0, 0>, cudaFuncAttributeMaxDynamicSharedMemorySize, smem_b(3, false, 1));
        cudaFuncSetAttribute(mma_gemm<4, true,  1, 0, 0>, cudaFuncAttributeMaxDynamicSharedMemorySize, smem_b(4, true, 1));
        cudaFuncSetAttribute(mma_gemm<4, true,  0, 0, 1>, cudaFuncAttributeMaxDynamicSharedMemorySize, smem_b(4, true, 0, 1));
        cudaFuncSetAttribute(mma_gemm<4, true,  0, 1, 0>, cudaFuncAttributeMaxDynamicSharedMemorySize, smem_b(4, true, 0));
    }

    // ---- fork: KV path on s2 ----
    cudaEventRecord(evF, 0);
    cudaStreamWaitEvent(s2, evF, 0);

    // 4) ckvraw = hkv @ W_kva : (4096,576), K=5120  [NN bf16x3, BN=96]  (s2)
    mma_gemm<3, false, 1, 0, 0><<<dim3(DQK / 96, SLEN / 128, 1), 256, smem_b(3, false, 1), s2>>>(
        hkv, W_kva, ckvraw, HID, HID, DQK, DQK, 0, 0, 0, nullptr, nullptr, 0.f, nullptr, nullptr);
    // 5) K_comb; ckvT = Kc[:, :512]^T  (s2)
    build_K<<<SLEN, 128, 0, s2>>>(ckvraw, gkva, kvpos, Kc);
    transpose_k<<<dim3(RKV / 32, SLEN / 32), dim3(32, 8), 0, s2>>>(Kc, ckvT, SLEN, DQK);
    cudaEventRecord(evKV, s2);

    // ---- Q path on default stream ----
    // 1) qa = hq @ W_qa : (256,1536), K=5120  [NN bf16x3, split-K 8]
    mma_gemm<4, false, 1, 0, 0><<<dim3(RQ / 128, 2, 8), 256, smem_b(4, false, 1)>>>(
        hq, W_qa, part, HID / 8, HID, RQ, RQ,
        (long)(HID / 8), (long)(HID / 8) * RQ, (long)QLEN * RQ, nullptr, nullptr, 0.f, nullptr, nullptr);
    reduce_slices<<<(QLEN * RQ / 4 + 255) / 256, 256>>>((const float4*)part, (float4*)qa, QLEN * RQ / 4, 8);

    // 2) rmsnorm(qa)
    rmsnorm_rows<<<QLEN, 256>>>(qa, gqa, RQ);

    // 3) qfull = qa @ W_qb : (256,24576), K=1536  [NN bf16x3]
    mma_gemm<4, false, 1, 0, 0><<<dim3(QB_COLS / 128, 2, 1), 256, smem_b(4, false, 1)>>>(
        qa, W_qb, qfull, RQ, RQ, QB_COLS, QB_COLS, 0, 0, 0, nullptr, nullptr, 0.f, nullptr, nullptr);

    // 6) q_c[h] = q_nope[h] @ q_absorb[h] : batched (256,512), K=128  [NN bf16x3]
    mma_gemm<4, false, 1, 0, 0><<<dim3(RKV / 128, 2, NHEADS), 256, smem_b(4, false, 1)>>>(
        qfull, W_kvb, Qc, DNOPE,
        QB_COLS, RKV, DQK,
        (long)(DNOPE + DROPE), (long)(DNOPE + DNOPE) * RKV, (long)QLEN * DQK, nullptr, nullptr, 0.f, nullptr, nullptr);

    // 7) rope q_pe
    rope_Q<<<dim3(QLEN, NHEADS), 32>>>(qfull, qpos, Qc);

    // ---- join ----
    cudaStreamWaitEvent(0, evKV, 0);

    // 8) logits[h] = Q_comb[h] @ K_comb^T : batched (256,4096), K=576  [NT tf32 + fused stats]
    mma_gemm<4, true, 0, 0, 1><<<dim3(SLEN / 128, 2, NHEADS), 256, smem_b(4, true, 0, 1)>>>(
        Qc, Kc, logits, DQK,
        DQK, DQK, SLEN,
        (long)QLEN * DQK, 0, (long)QLEN * SLEN, nullptr, nullptr, scale, tmax, tsum);

    // 9) combine tile stats -> rowm, rowis
    combine_stats<<<NHEADS * QLEN / 8, dim3(32, 8)>>>(tmax, tsum, rowm, rowis);

    // 10) oc[h] = softmax(logits[h]) @ ckv : batched (256,512), K=4096  [NT tf32 + EXPA]
    mma_gemm<4, true, 0, 1, 0><<<dim3(RKV / 128, 2, NHEADS), 256, smem_b(4, true, 0)>>>(
        logits, ckvT, oc, SLEN,
        SLEN, SLEN, RKV,
        (long)QLEN * SLEN, 0, (long)QLEN * RKV, rowm, rowis, scale, nullptr, nullptr);

    // 11) ao[:, h*128:] = oc[h] @ out_absorb[h]^T : batched (256,128), K=512  [NT bf16x3]
    mma_gemm<4, true, 1, 0, 0><<<dim3(1, 2, NHEADS), 256, smem_b(4, true, 1)>>>(
        oc, W_kvb + (long)DNOPE * RKV, ao, RKV,
        RKV, RKV, AO_COLS,
        (long)QLEN * RKV, (long)(DNOPE + DNOPE) * RKV, (long)DNOPE, nullptr, nullptr, 0.f, nullptr, nullptr);

    // 12) out = ao @ W_o : (256,5120), K=16384  [NN bf16x3, split-K 4]
    mma_gemm<4, false, 1, 0, 0><<<dim3(HID / 128, 2, 4), 256, smem_b(4, false, 1)>>>(
        ao, W_o, part, AO_COLS / 4, AO_COLS, HID, HID,
        (long)(AO_COLS / 4), (long)(AO_COLS / 4) * HID, (long)QLEN * HID, nullptr, nullptr, 0.f, nullptr, nullptr);
    reduce_slices<<<(QLEN * HID / 4 + 255) / 256, 256>>>((const float4*)part, (float4*)out, QLEN * HID / 4, 4);
}

// round 9
// speedup vs baseline: 1.7674x; 1.0837x over previous
#include <cuda_runtime.h>
#include <cuda_fp16.h>
#include <math.h>
#include <stdint.h>

// ---------------- Problem constants ----------------
#define NHEADS   128
#define DNOPE    128
#define DROPE    64
#define DQK      576
#define RKV      512
#define RQ       1536
#define HID      5120
#define QLEN     256
#define SLEN     4096
#define QB_COLS  24576
#define AO_COLS  16384
#define EPSF     1e-6f
#define NTILES_S (SLEN / 128)    // 32

// ---------------- Scratch (device globals) ----------------
__device__ __align__(128) float  g_qa_buf [QLEN * RQ];
__device__ __align__(128) float  g_qfull  [QLEN * QB_COLS];
__device__ __align__(128) float  g_ckvraw [SLEN * DQK];
__device__ __align__(128) float  g_Kc     [SLEN * DQK];
__device__ __align__(128) __half g_ckvTh  [(size_t)RKV * SLEN];
__device__ __align__(128) float  g_Qc     [(size_t)NHEADS * QLEN * DQK];
__device__ __align__(128) __half g_P      [(size_t)NHEADS * QLEN * SLEN];  // 256 MB
__device__ __align__(128) float  g_oc     [(size_t)NHEADS * QLEN * RKV];
__device__ __align__(128) float  g_ao     [QLEN * AO_COLS];
__device__ __align__(128) float  g_part   [8 * QLEN * HID];
__device__ __align__(128) float  g_rowm   [NHEADS * QLEN];
__device__ __align__(128) float  g_rowis  [NHEADS * QLEN];
__device__ __align__(128) float  g_tmax   [(size_t)NHEADS * QLEN * NTILES_S];
__device__ __align__(128) float  g_tsum   [(size_t)NHEADS * QLEN * NTILES_S];

// ---------------- helpers ----------------
__device__ __forceinline__ uint32_t smem_u32(const void* p) {
    uint32_t a;
    asm("{ .reg .u64 t; cvta.to.shared.u64 t, %1; cvt.u32.u64 %0, t; }" : "=r"(a) : "l"(p));
    return a;
}
__device__ __forceinline__ uint32_t f2tf(float x) {
    uint32_t r;
    asm("cvt.rna.tf32.f32 %0, %1;" : "=r"(r) : "f"(x));
    return r;
}
__device__ __forceinline__ uint32_t pack_bf16(float lo, float hi) {
    uint32_t r;
    asm("cvt.rn.bf16x2.f32 %0, %1, %2;" : "=r"(r) : "f"(hi), "f"(lo));
    return r;
}
__device__ __forceinline__ float bflo(uint32_t p) { return __uint_as_float(p << 16); }
__device__ __forceinline__ float bfhi(uint32_t p) { return __uint_as_float(p & 0xffff0000u); }

__device__ __forceinline__ void mma8(float* d, const uint32_t* a, uint32_t b0, uint32_t b1) {
    asm volatile(
        "mma.sync.aligned.m16n8k8.row.col.f32.tf32.tf32.f32 "
        "{%0,%1,%2,%3},{%4,%5,%6,%7},{%8,%9},{%0,%1,%2,%3};"
        : "+f"(d[0]), "+f"(d[1]), "+f"(d[2]), "+f"(d[3])
        : "r"(a[0]), "r"(a[1]), "r"(a[2]), "r"(a[3]), "r"(b0), "r"(b1));
}
__device__ __forceinline__ void mma16b(float* d, const uint32_t* a, uint32_t b0, uint32_t b1) {
    asm volatile(
        "mma.sync.aligned.m16n8k16.row.col.f32.bf16.bf16.f32 "
        "{%0,%1,%2,%3},{%4,%5,%6,%7},{%8,%9},{%0,%1,%2,%3};"
        : "+f"(d[0]), "+f"(d[1]), "+f"(d[2]), "+f"(d[3])
        : "r"(a[0]), "r"(a[1]), "r"(a[2]), "r"(a[3]), "r"(b0), "r"(b1));
}
__device__ __forceinline__ void mma16h(float* d, const uint32_t* a, uint32_t b0, uint32_t b1) {
    asm volatile(
        "mma.sync.aligned.m16n8k16.row.col.f32.f16.f16.f32 "
        "{%0,%1,%2,%3},{%4,%5,%6,%7},{%8,%9},{%0,%1,%2,%3};"
        : "+f"(d[0]), "+f"(d[1]), "+f"(d[2]), "+f"(d[3])
        : "r"(a[0]), "r"(a[1]), "r"(a[2]), "r"(a[3]), "r"(b0), "r"(b1));
}
__device__ __forceinline__ void ldm_x4(uint32_t* r, uint32_t addr) {
    asm volatile("ldmatrix.sync.aligned.m8n8.x4.shared.b16 {%0,%1,%2,%3}, [%4];"
                 : "=r"(r[0]), "=r"(r[1]), "=r"(r[2]), "=r"(r[3]) : "r"(addr));
}

// ---------------- generic mma.sync GEMM ----------------
// TRANSB=1: C = A @ B^T, B:[N,K] K-major. TRANSB=0: C = A @ B, B:[K,N] N-major.
// PREC=0: tf32 single. PREC=1: bf16 3-term hi/lo split.
// STATS=1: instead of f32 C, write P=exp(x*escale - tilemax) as fp16 to Ph and
//          per-tile row max / sum-exp into gtmax/gtsum.
template<int NT, bool TRANSB, int PREC, int STATS>
__global__ void __launch_bounds__(256, 2)
mma_gemm(const float* __restrict__ A, const float* __restrict__ B, float* __restrict__ C,
         int K, int lda, int ldb, int ldc, long sA, long sB, long sC,
         float escale, __half* __restrict__ Ph,
         float* __restrict__ gtmax, float* __restrict__ gtsum)
{
    constexpr int BN   = NT * 32;
    constexpr int A_ST = (PREC == 0) ? 128 * 36 : 128 * 20 * 2;
    constexpr int B_ST = TRANSB ? ((PREC == 0) ? BN * 36 : BN * 20 * 2)
                                : ((PREC == 0) ? 32 * (BN + 8) : 16 * (BN + 8) * 2);
    constexpr int STG  = A_ST + B_ST;
    constexpr int BQ   = BN / 4;

    extern __shared__ uint32_t smu[];
    const uint32_t smem_base = smem_u32(smu);

    const int tid  = threadIdx.x;
    const int warp = tid >> 5;
    const int lane = tid & 31;
    const int wm = (warp >> 2) * 64;
    const int wn = (warp & 3) * (BN / 4);
    const int g  = lane >> 2;
    const int tq = lane & 3;

    const int bm = blockIdx.y * 128;
    const int bn = blockIdx.x * BN;
    A += (long)blockIdx.z * sA + (long)bm * lda;
    if (TRANSB) B += (long)blockIdx.z * sB + (long)bn * ldb;
    else        B += (long)blockIdx.z * sB + bn;
    if (!STATS) C  += (long)blockIdx.z * sC + (long)bm * ldc + bn;
    else        Ph += (long)blockIdx.z * sC + (long)bm * ldc + bn;

    const int NC = K >> 5;

    float acc[4][NT][4];
#pragma unroll
    for (int i = 0; i < 4; i++)
#pragma unroll
        for (int j = 0; j < NT; j++)
#pragma unroll
            for (int l = 0; l < 4; l++) acc[i][j][l] = 0.f;

    float4 rA[4];
    float4 rB[4];

    auto ldg_chunk = [&](int c) {
        const float* ga = A + c * 32;
#pragma unroll
        for (int i = 0; i < 4; i++) {
            int idx = tid + i * 256;
            int r = idx >> 3, c4 = (idx & 7) << 2;
            rA[i] = *(const float4*)(ga + (long)r * lda + c4);
        }
        if (TRANSB) {
            const float* gb = B + c * 32;
#pragma unroll
            for (int i = 0; i < NT; i++) {
                int idx = tid + i * 256;
                int r = idx >> 3, c4 = (idx & 7) << 2;
                rB[i] = *(const float4*)(gb + (long)r * ldb + c4);
            }
        } else if (PREC == 0) {
            const float* gb = B + (long)(c * 32) * ldb;
#pragma unroll
            for (int i = 0; i < NT; i++) {
                int idx = tid + i * 256;
                int r = idx / BQ, c4 = (idx % BQ) << 2;
                rB[i] = *(const float4*)(gb + (long)r * ldb + c4);
            }
        } else {
            const float* gb = B + (long)(c * 32) * ldb;
#pragma unroll
            for (int i = 0; i < 2; i++) {
                int u = tid + i * 256;
                if (u < 16 * BQ) {
                    int kp = u / BQ, c4 = (u % BQ) << 2;
                    rB[2 * i]     = *(const float4*)(gb + (long)(2 * kp) * ldb + c4);
                    rB[2 * i + 1] = *(const float4*)(gb + (long)(2 * kp + 1) * ldb + c4);
                }
            }
        }
    };

    auto sts_chunk = [&](int sbase) {
        uint32_t* sa = smu + sbase;
        uint32_t* sb = smu + sbase + A_ST;
        if (PREC == 0) {
#pragma unroll
            for (int i = 0; i < 4; i++) {
                int idx = tid + i * 256;
                int r = idx >> 3, c4 = (idx & 7) << 2;
                float4 v = rA[i];
                uint4 w = { f2tf(v.x), f2tf(v.y), f2tf(v.z), f2tf(v.w) };
                *(uint4*)&sa[r * 36 + c4] = w;
            }
            if (TRANSB) {
#pragma unroll
                for (int i = 0; i < NT; i++) {
                    int idx = tid + i * 256;
                    int r = idx >> 3, c4 = (idx & 7) << 2;
                    uint4 w = { f2tf(rB[i].x), f2tf(rB[i].y), f2tf(rB[i].z), f2tf(rB[i].w) };
                    *(uint4*)&sb[r * 36 + c4] = w;
                }
            } else {
#pragma unroll
                for (int i = 0; i < NT; i++) {
                    int idx = tid + i * 256;
                    int r = idx / BQ, c4 = (idx % BQ) << 2;
                    uint4 w = { f2tf(rB[i].x), f2tf(rB[i].y), f2tf(rB[i].z), f2tf(rB[i].w) };
                    *(uint4*)&sb[r * (BN + 8) + c4] = w;
                }
            }
        } else {
#pragma unroll
            for (int i = 0; i < 4; i++) {
                int idx = tid + i * 256;
                int r = idx >> 3, cu = (idx & 7) << 1;
                float4 v = rA[i];
                uint32_t h0 = pack_bf16(v.x, v.y), h1 = pack_bf16(v.z, v.w);
                uint32_t l0 = pack_bf16(v.x - bflo(h0), v.y - bfhi(h0));
                uint32_t l1 = pack_bf16(v.z - bflo(h1), v.w - bfhi(h1));
                *(uint2*)&sa[r * 20 + cu]            = make_uint2(h0, h1);
                *(uint2*)&sa[128 * 20 + r * 20 + cu] = make_uint2(l0, l1);
            }
            if (TRANSB) {
#pragma unroll
                for (int i = 0; i < NT; i++) {
                    int idx = tid + i * 256;
                    int r = idx >> 3, cu = (idx & 7) << 1;
                    float4 v = rB[i];
                    uint32_t h0 = pack_bf16(v.x, v.y), h1 = pack_bf16(v.z, v.w);
                    uint32_t l0 = pack_bf16(v.x - bflo(h0), v.y - bfhi(h0));
                    uint32_t l1 = pack_bf16(v.z - bflo(h1), v.w - bfhi(h1));
                    *(uint2*)&sb[r * 20 + cu]           = make_uint2(h0, h1);
                    *(uint2*)&sb[BN * 20 + r * 20 + cu] = make_uint2(l0, l1);
                }
            } else {
#pragma unroll
                for (int i = 0; i < 2; i++) {
                    int u = tid + i * 256;
                    if (u < 16 * BQ) {
                        int kp = u / BQ, c4 = (u % BQ) << 2;
                        float4 v0 = rB[2 * i], v1 = rB[2 * i + 1];
                        uint4 h = { pack_bf16(v0.x, v1.x), pack_bf16(v0.y, v1.y),
                                    pack_bf16(v0.z, v1.z), pack_bf16(v0.w, v1.w) };
                        uint4 l = { pack_bf16(v0.x - bflo(h.x), v1.x - bfhi(h.x)),
                                    pack_bf16(v0.y - bflo(h.y), v1.y - bfhi(h.y)),
                                    pack_bf16(v0.z - bflo(h.z), v1.z - bfhi(h.z)),
                                    pack_bf16(v0.w - bflo(h.w), v1.w - bfhi(h.w)) };
                        *(uint4*)&sb[kp * (BN + 8) + c4]                 = h;
                        *(uint4*)&sb[16 * (BN + 8) + kp * (BN + 8) + c4] = l;
                    }
                }
            }
        }
    };

    auto compute = [&](int sbase) {
        const uint32_t aB = smem_base + (uint32_t)sbase * 4;
        const uint32_t bB = smem_base + (uint32_t)(sbase + A_ST) * 4;
        const int mat = lane >> 3;
        if (PREC == 0) {
#pragma unroll
            for (int kk = 0; kk < 4; kk++) {
                const int kcu = kk * 8;
                uint32_t af[4][4];
#pragma unroll
                for (int mt = 0; mt < 4; mt++) {
                    int row = wm + mt * 16 + ((mat & 1) << 3) + (lane & 7);
                    int col = kcu + ((mat >> 1) << 2);
                    ldm_x4(af[mt], aB + (uint32_t)(row * 36 + col) * 4);
                }
                if (TRANSB) {
#pragma unroll
                    for (int np = 0; np < NT / 2; np++) {
                        uint32_t bf[4];
                        int row = wn + (2 * np + (mat >> 1)) * 8 + (lane & 7);
                        int col = kcu + ((mat & 1) << 2);
                        ldm_x4(bf, bB + (uint32_t)(row * 36 + col) * 4);
#pragma unroll
                        for (int mt = 0; mt < 4; mt++) {
                            mma8(acc[mt][2 * np],     af[mt], bf[0], bf[1]);
                            mma8(acc[mt][2 * np + 1], af[mt], bf[2], bf[3]);
                        }
                    }
                } else {
                    const uint32_t* sb = smu + sbase + A_ST;
#pragma unroll
                    for (int nt = 0; nt < NT; nt++) {
                        int n0 = wn + nt * 8 + g;
                        uint32_t b0 = sb[(kcu + tq) * (BN + 8) + n0];
                        uint32_t b1 = sb[(kcu + tq + 4) * (BN + 8) + n0];
#pragma unroll
                        for (int mt = 0; mt < 4; mt++)
                            mma8(acc[mt][nt], af[mt], b0, b1);
                    }
                }
            }
        } else {
#pragma unroll
            for (int kk = 0; kk < 2; kk++) {
                const int kcu = kk * 8;
                uint32_t ah[4][4], al[4][4];
#pragma unroll
                for (int mt = 0; mt < 4; mt++) {
                    int row = wm + mt * 16 + ((mat & 1) << 3) + (lane & 7);
                    int col = kcu + ((mat >> 1) << 2);
                    ldm_x4(ah[mt], aB + (uint32_t)(row * 20 + col) * 4);
                    ldm_x4(al[mt], aB + (uint32_t)(128 * 20 + row * 20 + col) * 4);
                }
                if (TRANSB) {
#pragma unroll
                    for (int np = 0; np < NT / 2; np++) {
                        uint32_t bh[4], bl[4];
                        int row = wn + (2 * np + (mat >> 1)) * 8 + (lane & 7);
                        int col = kcu + ((mat & 1) << 2);
                        ldm_x4(bh, bB + (uint32_t)(row * 20 + col) * 4);
                        ldm_x4(bl, bB + (uint32_t)(BN * 20 + row * 20 + col) * 4);
#pragma unroll
                        for (int mt = 0; mt < 4; mt++) {
                            mma16b(acc[mt][2 * np], ah[mt], bh[0], bh[1]);
                            mma16b(acc[mt][2 * np], al[mt], bh[0], bh[1]);
                            mma16b(acc[mt][2 * np], ah[mt], bl[0], bl[1]);
                            mma16b(acc[mt][2 * np + 1], ah[mt], bh[2], bh[3]);
                            mma16b(acc[mt][2 * np + 1], al[mt], bh[2], bh[3]);
                            mma16b(acc[mt][2 * np + 1], ah[mt], bl[2], bl[3]);
                        }
                    }
                } else {
                    const uint32_t* sbh = smu + sbase + A_ST;
                    const uint32_t* sbl = sbh + 16 * (BN + 8);
#pragma unroll
                    for (int nt = 0; nt < NT; nt++) {
                        int n0 = wn + nt * 8 + g;
                        uint32_t b0h = sbh[(kcu + tq) * (BN + 8) + n0];
                        uint32_t b1h = sbh[(kcu + tq + 4) * (BN + 8) + n0];
                        uint32_t b0l = sbl[(kcu + tq) * (BN + 8) + n0];
                        uint32_t b1l = sbl[(kcu + tq + 4) * (BN + 8) + n0];
#pragma unroll
                        for (int mt = 0; mt < 4; mt++) {
                            mma16b(acc[mt][nt], ah[mt], b0h, b1h);
                            mma16b(acc[mt][nt], al[mt], b0h, b1h);
                            mma16b(acc[mt][nt], ah[mt], b0l, b1l);
                        }
                    }
                }
            }
        }
    };

    // ---- pipeline ----
    ldg_chunk(0);
    sts_chunk(0);
    __syncthreads();
    for (int c = 0; c < NC; c++) {
        if (c + 1 < NC) ldg_chunk(c + 1);
        compute((c & 1) * STG);
        if (c + 1 < NC) {
            sts_chunk(((c + 1) & 1) * STG);
            __syncthreads();
        }
    }

    if (!STATS) {
#pragma unroll
        for (int mt = 0; mt < 4; mt++) {
            const int r0 = wm + mt * 16 + g;
#pragma unroll
            for (int nt = 0; nt < NT; nt++) {
                const int c0 = wn + nt * 8 + tq * 2;
                *(float2*)&C[(long)r0 * ldc + c0]       = make_float2(acc[mt][nt][0], acc[mt][nt][1]);
                *(float2*)&C[(long)(r0 + 8) * ldc + c0] = make_float2(acc[mt][nt][2], acc[mt][nt][3]);
            }
        }
    } else {
        // fused: per-tile row max, P=exp fp16 store, per-tile sum
        float* st_max = (float*)(smu + 2 * STG);
        float* st_sum = st_max + 512;
        const int nw = warp & 3;
        __syncthreads();
#pragma unroll
        for (int mt = 0; mt < 4; mt++) {
#pragma unroll
            for (int h = 0; h < 2; h++) {
                float mx = -INFINITY;
#pragma unroll
                for (int nt = 0; nt < NT; nt++) {
                    mx = fmaxf(mx, acc[mt][nt][2 * h]);
                    mx = fmaxf(mx, acc[mt][nt][2 * h + 1]);
                }
                mx = fmaxf(mx, __shfl_xor_sync(0xffffffffu, mx, 1));
                mx = fmaxf(mx, __shfl_xor_sync(0xffffffffu, mx, 2));
                if (tq == 0) st_max[(wm + mt * 16 + h * 8 + g) * 4 + nw] = mx * escale;
            }
        }
        __syncthreads();
#pragma unroll
        for (int mt = 0; mt < 4; mt++) {
#pragma unroll
            for (int h = 0; h < 2; h++) {
                const int row = wm + mt * 16 + h * 8 + g;
                float rm = fmaxf(fmaxf(st_max[row * 4 + 0], st_max[row * 4 + 1]),
                                 fmaxf(st_max[row * 4 + 2], st_max[row * 4 + 3]));
                float s = 0.f;
#pragma unroll
                for (int nt = 0; nt < NT; nt++) {
                    float p0 = __expf(fmaf(acc[mt][nt][2 * h],     escale, -rm));
                    float p1 = __expf(fmaf(acc[mt][nt][2 * h + 1], escale, -rm));
                    s += p0 + p1;
                    *(__half2*)&Ph[(long)row * ldc + wn + nt * 8 + tq * 2] =
                        __floats2half2_rn(p0, p1);
                }
                s += __shfl_xor_sync(0xffffffffu, s, 1);
                s += __shfl_xor_sync(0xffffffffu, s, 2);
                if (tq == 0) st_sum[row * 4 + nw] = s;
            }
        }
        __syncthreads();
        if (tid < 128) {
            float m = fmaxf(fmaxf(st_max[tid * 4 + 0], st_max[tid * 4 + 1]),
                            fmaxf(st_max[tid * 4 + 2], st_max[tid * 4 + 3]));
            float s = st_sum[tid * 4 + 0] + st_sum[tid * 4 + 1]
                    + st_sum[tid * 4 + 2] + st_sum[tid * 4 + 3];
            long grow = (long)blockIdx.z * QLEN + bm + tid;
            gtmax[grow * NTILES_S + blockIdx.x] = m;
            gtsum[grow * NTILES_S + blockIdx.x] = s;
        }
    }
}

// ---------------- fp16 PV GEMM: oc[h] = softmax(P)[h] @ ckv ----------------
// A: P fp16 [head][256][4096]; rescale exp(tmax - m)*invsum folded at staging.
// B: ckvT fp16 [512][4096] (K-major). C: oc f32 [head][256][512].
__global__ void __launch_bounds__(256, 2)
pv_gemm(const __half* __restrict__ A, const __half* __restrict__ B, float* __restrict__ C,
        const float* __restrict__ tmax, const float* __restrict__ rowm,
        const float* __restrict__ rowis)
{
    constexpr int A_ST = 128 * 20;   // u32 per stage
    constexpr int B_ST = 128 * 20;
    constexpr int STG  = A_ST + B_ST;

    extern __shared__ uint32_t smu[];
    const uint32_t smem_base = smem_u32(smu);

    const int tid  = threadIdx.x;
    const int warp = tid >> 5;
    const int lane = tid & 31;
    const int wm = (warp >> 2) * 64;
    const int wn = (warp & 3) * 32;
    const int g  = lane >> 2;
    const int tq = lane & 3;
    const int mat = lane >> 3;

    const int bm = blockIdx.y * 128;
    const int bn = blockIdx.x * 128;
    const int z  = blockIdx.z;
    A += (long)z * QLEN * SLEN + (long)bm * SLEN;
    B += (long)bn * SLEN;
    C += (long)z * QLEN * RKV + (long)bm * RKV + bn;

    // staging assignment: each thread owns one A row and one B row
    const int ar  = tid >> 1;
    const int ahc = (tid & 1) * 16;        // half offset within 32-half chunk
    const long grow = (long)z * QLEN + bm + ar;
    const float m_r  = rowm[grow];
    const float is_r = rowis[grow];
    const float* tmax_r = tmax + grow * NTILES_S;

    float acc[4][4][4];
#pragma unroll
    for (int i = 0; i < 4; i++)
#pragma unroll
        for (int j = 0; j < 4; j++)
#pragma unroll
            for (int l = 0; l < 4; l++) acc[i][j][l] = 0.f;

    uint4 ra0, ra1, rb0, rb1;

    auto ldg_chunk = [&](int c) {
        const __half* ga = A + (long)ar * SLEN + c * 32 + ahc;
        ra0 = *(const uint4*)(ga);
        ra1 = *(const uint4*)(ga + 8);
        const __half* gb = B + (long)ar * SLEN + c * 32 + ahc;
        rb0 = *(const uint4*)(gb);
        rb1 = *(const uint4*)(gb + 8);
    };

    auto sts_chunk = [&](int c, int sbase) {
        const float f = __expf(tmax_r[c >> 2] - m_r) * is_r;
        uint32_t* sa = smu + sbase;
        uint32_t* sb = smu + sbase + A_ST;
        const int cu = ahc >> 1;   // u32 col
        uint32_t aw[8] = { ra0.x, ra0.y, ra0.z, ra0.w, ra1.x, ra1.y, ra1.z, ra1.w };
#pragma unroll
        for (int i = 0; i < 8; i++) {
            float2 v = __half22float2(*(__half2*)&aw[i]);
            v.x *= f; v.y *= f;
            __half2 h = __floats2half2_rn(v.x, v.y);
            aw[i] = *(uint32_t*)&h;
        }
        *(uint4*)&sa[ar * 20 + cu]     = make_uint4(aw[0], aw[1], aw[2], aw[3]);
        *(uint4*)&sa[ar * 20 + cu + 4] = make_uint4(aw[4], aw[5], aw[6], aw[7]);
        *(uint4*)&sb[ar * 20 + cu]     = rb0;
        *(uint4*)&sb[ar * 20 + cu + 4] = rb1;
    };

    auto compute = [&](int sbase) {
        const uint32_t aB = smem_base + (uint32_t)sbase * 4;
        const uint32_t bB = smem_base + (uint32_t)(sbase + A_ST) * 4;
#pragma unroll
        for (int kk = 0; kk < 2; kk++) {
            const int kcu = kk * 8;
            uint32_t af[4][4];
#pragma unroll
            for (int mt = 0; mt < 4; mt++) {
                int row = wm + mt * 16 + ((mat & 1) << 3) + (lane & 7);
                int col = kcu + ((mat >> 1) << 2);
                ldm_x4(af[mt], aB + (uint32_t)(row * 20 + col) * 4);
            }
#pragma unroll
            for (int np = 0; np < 2; np++) {
                uint32_t bf[4];
                int row = wn + (2 * np + (mat >> 1)) * 8 + (lane & 7);
                int col = kcu + ((mat & 1) << 2);
                ldm_x4(bf, bB + (uint32_t)(row * 20 + col) * 4);
#pragma unroll
                for (int mt = 0; mt < 4; mt++) {
                    mma16h(acc[mt][2 * np],     af[mt], bf[0], bf[1]);
                    mma16h(acc[mt][2 * np + 1], af[mt], bf[2], bf[3]);
                }
            }
        }
    };

    ldg_chunk(0);
    sts_chunk(0, 0);
    __syncthreads();
    const int NC = SLEN / 32;
    for (int c = 0; c < NC; c++) {
        if (c + 1 < NC) ldg_chunk(c + 1);
        compute((c & 1) * STG);
        if (c + 1 < NC) {
            sts_chunk(c + 1, ((c + 1) & 1) * STG);
            __syncthreads();
        }
    }

#pragma unroll
    for (int mt = 0; mt < 4; mt++) {
        const int r0 = wm + mt * 16 + g;
#pragma unroll
        for (int nt = 0; nt < 4; nt++) {
            const int c0 = wn + nt * 8 + tq * 2;
            *(float2*)&C[(long)r0 * RKV + c0]       = make_float2(acc[mt][nt][0], acc[mt][nt][1]);
            *(float2*)&C[(long)(r0 + 8) * RKV + c0] = make_float2(acc[mt][nt][2], acc[mt][nt][3]);
        }
    }
}

// ---------------- Combine tile stats ----------------
__global__ void combine_stats(const float* __restrict__ tmax, const float* __restrict__ tsum,
                              float* __restrict__ rm, float* __restrict__ ris)
{
    const int row = blockIdx.x * 8 + threadIdx.y;
    const int t = threadIdx.x;
    float mv = tmax[(long)row * NTILES_S + t];
    float m = mv;
#pragma unroll
    for (int o = 16; o > 0; o >>= 1) m = fmaxf(m, __shfl_xor_sync(0xffffffffu, m, o));
    float s = tsum[(long)row * NTILES_S + t] * __expf(mv - m);
#pragma unroll
    for (int o = 16; o > 0; o >>= 1) s += __shfl_xor_sync(0xffffffffu, s, o);
    if (t == 0) { rm[row] = m; ris[row] = 1.f / s; }
}

// ---------------- Transpose to half: out[c][r] = (half)in[r*ldin + c] ----------------
__global__ void transpose_kh(const float* __restrict__ in, __half* __restrict__ out,
                             int R, int ldin)
{
    __shared__ float t[32][33];
    const int c0 = blockIdx.x * 32, r0 = blockIdx.y * 32;
    const int x = threadIdx.x, y0 = threadIdx.y;
    #pragma unroll
    for (int i = y0; i < 32; i += 8) t[i][x] = in[(long)(r0 + i) * ldin + c0 + x];
    __syncthreads();
    #pragma unroll
    for (int i = y0; i < 32; i += 8) out[(long)(c0 + i) * R + r0 + x] = __float2half_rn(t[x][i]);
}

// ---------------- Split-K reduction ----------------
__global__ void reduce_slices(const float4* __restrict__ in, float4* __restrict__ out,
                              int n4, int S)
{
    int i = blockIdx.x * 256 + threadIdx.x;
    if (i >= n4) return;
    float4 a = in[i];
    for (int s = 1; s < S; s++) {
        float4 b = in[i + (long)s * n4];
        a.x += b.x; a.y += b.y; a.z += b.z; a.w += b.w;
    }
    out[i] = a;
}

// ---------------- RMSNorm (in place) ----------------
__global__ void rmsnorm_rows(float* __restrict__ X, const float* __restrict__ g, int cols)
{
    const long row = blockIdx.x;
    float* x = X + row * (long)cols;
    const int tid = threadIdx.x;
    const int n4 = cols >> 2;
    float ss = 0.f;
    for (int c = tid; c < n4; c += blockDim.x) {
        float4 v = ((const float4*)x)[c];
        ss += v.x * v.x + v.y * v.y + v.z * v.z + v.w * v.w;
    }
    __shared__ float red[256];
    red[tid] = ss; __syncthreads();
    for (int s = 128; s > 0; s >>= 1) { if (tid < s) red[tid] += red[tid + s]; __syncthreads(); }
    const float inv = rsqrtf(red[0] / (float)cols + EPSF);
    for (int c = tid; c < n4; c += blockDim.x) {
        float4 v = ((const float4*)x)[c];
        float4 w = ((const float4*)g)[c];
        v.x *= inv * w.x; v.y *= inv * w.y; v.z *= inv * w.z; v.w *= inv * w.w;
        ((float4*)x)[c] = v;
    }
}

// ---------------- Build K_comb ----------------
__global__ void build_K(const float* __restrict__ raw, const float* __restrict__ g,
                        const int* __restrict__ kvpos, float* __restrict__ Kc)
{
    const int s = blockIdx.x;
    const float* r = raw + (long)s * DQK;
    float* k = Kc + (long)s * DQK;
    const int tid = threadIdx.x;

    float ss = 0.f;
    for (int c = tid; c < RKV / 4; c += 128) {
        float4 v = ((const float4*)r)[c];
        ss += v.x * v.x + v.y * v.y + v.z * v.z + v.w * v.w;
    }
    __shared__ float red[128];
    red[tid] = ss; __syncthreads();
    for (int st = 64; st > 0; st >>= 1) { if (tid < st) red[tid] += red[tid + st]; __syncthreads(); }
    const float inv = rsqrtf(red[0] / (float)RKV + EPSF);
    for (int c = tid; c < RKV / 4; c += 128) {
        float4 v = ((const float4*)r)[c];
        float4 w = ((const float4*)g)[c];
        v.x *= inv * w.x; v.y *= inv * w.y; v.z *= inv * w.z; v.w *= inv * w.w;
        ((float4*)k)[c] = v;
    }

    if (tid < 32) {
        const int j = tid;
        const float x0 = r[RKV + 2 * j];
        const float x1 = r[RKV + 2 * j + 1];
        const float pos = (float)kvpos[s];
        const float invf = powf(10000.f, -(float)j / 32.f);
        float cs, sn; sincosf(pos * invf, &sn, &cs);
        k[RKV + j]      = x0 * cs - x1 * sn;
        k[RKV + 32 + j] = x0 * sn + x1 * cs;
    }
}

// ---------------- RoPE for q_pe ----------------
__global__ void rope_Q(const float* __restrict__ qfull, const int* __restrict__ qpos,
                       float* __restrict__ Qc)
{
    const int t = blockIdx.x;
    const int h = blockIdx.y;
    const int j = threadIdx.x;
    const float* src = qfull + (long)t * QB_COLS + h * (DNOPE + DROPE) + DNOPE;
    const float x0 = src[2 * j];
    const float x1 = src[2 * j + 1];
    const float pos = (float)qpos[t];
    const float invf = powf(10000.f, -(float)j / 32.f);
    float cs, sn; sincosf(pos * invf, &sn, &cs);
    float* dst = Qc + ((long)h * QLEN + t) * DQK + RKV;
    dst[j]      = x0 * cs - x1 * sn;
    dst[32 + j] = x0 * sn + x1 * cs;
}

// ---------------- Launch ----------------
static inline void* symv(const void* s)
{
    void* p = nullptr;
    cudaGetSymbolAddress(&p, s);
    return p;
}

static inline int smem_b(int NT, bool transb, int prec, int stats = 0)
{
    int a = (prec == 0) ? 128 * 36 : 128 * 40;
    int b = transb ? ((prec == 0) ? NT * 32 * 36 : NT * 32 * 40)
                   : 32 * (NT * 32 + 8);
    return 2 * (a + b) * 4 + (stats ? 4096 : 0);
}

extern "C" void kernel_launch(void* const* d_in, const int* in_sizes, int n_in,
                              void* d_out, int out_size)
{
    const float* hq    = (const float*)d_in[0];
    const float* hkv   = (const float*)d_in[1];
    const float* W_qa  = (const float*)d_in[2];
    const float* gqa   = (const float*)d_in[3];
    const float* W_qb  = (const float*)d_in[4];
    const float* W_kva = (const float*)d_in[5];
    const float* gkva  = (const float*)d_in[6];
    const float* W_kvb = (const float*)d_in[7];
    const float* W_o   = (const float*)d_in[8];
    const int*   qpos  = (const int*)d_in[9];
    const int*   kvpos = (const int*)d_in[10];
    float*       out   = (float*)d_out;

    float*  qa     = (float*) symv(g_qa_buf);
    float*  qfull  = (float*) symv(g_qfull);
    float*  ckvraw = (float*) symv(g_ckvraw);
    float*  Kc     = (float*) symv(g_Kc);
    __half* ckvTh  = (__half*)symv(g_ckvTh);
    float*  Qc     = (float*) symv(g_Qc);
    __half* P      = (__half*)symv(g_P);
    float*  oc     = (float*) symv(g_oc);
    float*  ao     = (float*) symv(g_ao);
    float*  part   = (float*) symv(g_part);
    float*  rowm   = (float*) symv(g_rowm);
    float*  rowis  = (float*) symv(g_rowis);
    float*  tmax   = (float*) symv(g_tmax);
    float*  tsum   = (float*) symv(g_tsum);

    const float scale = 1.0f / sqrtf(192.0f);

    static cudaStream_t s2 = nullptr;
    static cudaEvent_t evF = nullptr, evKV = nullptr;
    if (!s2) {
        cudaStreamCreateWithFlags(&s2, cudaStreamNonBlocking);
        cudaEventCreateWithFlags(&evF,  cudaEventDisableTiming);
        cudaEventCreateWithFlags(&evKV, cudaEventDisableTiming);
        cudaFuncSetAttribute(mma_gemm<4, false, 1, 0>, cudaFuncAttributeMaxDynamicSharedMemorySize, smem_b(4, false, 1));
        cudaFuncSetAttribute(mma_gemm<3, false, 1, 0>, cudaFuncAttributeMaxDynamicSharedMemorySize, smem_b(3, false, 1));
        cudaFuncSetAttribute(mma_gemm<4, true,  1, 0>, cudaFuncAttributeMaxDynamicSharedMemorySize, smem_b(4, true, 1));
        cudaFuncSetAttribute(mma_gemm<4, true,  0, 1>, cudaFuncAttributeMaxDynamicSharedMemorySize, smem_b(4, true, 0, 1));
        cudaFuncSetAttribute(pv_gemm, cudaFuncAttributeMaxDynamicSharedMemorySize, 2 * (128 * 20 + 128 * 20) * 4);
    }

    // ---- fork: KV path on s2 ----
    cudaEventRecord(evF, 0);
    cudaStreamWaitEvent(s2, evF, 0);

    // 4) ckvraw = hkv @ W_kva : (4096,576), K=5120  [NN bf16x3, BN=96]  (s2)
    mma_gemm<3, false, 1, 0><<<dim3(DQK / 96, SLEN / 128, 1), 256, smem_b(3, false, 1), s2>>>(
        hkv, W_kva, ckvraw, HID, HID, DQK, DQK, 0, 0, 0, 0.f, nullptr, nullptr, nullptr);
    // 5) K_comb; ckvTh = (half)Kc[:, :512]^T  (s2)
    build_K<<<SLEN, 128, 0, s2>>>(ckvraw, gkva, kvpos, Kc);
    transpose_kh<<<dim3(RKV / 32, SLEN / 32), dim3(32, 8), 0, s2>>>(Kc, ckvTh, SLEN, DQK);
    cudaEventRecord(evKV, s2);

    // ---- Q path on default stream ----
    // 1) qa = hq @ W_qa : split-K 8
    mma_gemm<4, false, 1, 0><<<dim3(RQ / 128, 2, 8), 256, smem_b(4, false, 1)>>>(
        hq, W_qa, part, HID / 8, HID, RQ, RQ,
        (long)(HID / 8), (long)(HID / 8) * RQ, (long)QLEN * RQ, 0.f, nullptr, nullptr, nullptr);
    reduce_slices<<<(QLEN * RQ / 4 + 255) / 256, 256>>>((const float4*)part, (float4*)qa, QLEN * RQ / 4, 8);

    // 2) rmsnorm(qa)
    rmsnorm_rows<<<QLEN, 256>>>(qa, gqa, RQ);

    // 3) qfull = qa @ W_qb
    mma_gemm<4, false, 1, 0><<<dim3(QB_COLS / 128, 2, 1), 256, smem_b(4, false, 1)>>>(
        qa, W_qb, qfull, RQ, RQ, QB_COLS, QB_COLS, 0, 0, 0, 0.f, nullptr, nullptr, nullptr);

    // 6) q_c[h] = q_nope[h] @ q_absorb[h]
    mma_gemm<4, false, 1, 0><<<dim3(RKV / 128, 2, NHEADS), 256, smem_b(4, false, 1)>>>(
        qfull, W_kvb, Qc, DNOPE,
        QB_COLS, RKV, DQK,
        (long)(DNOPE + DROPE), (long)(DNOPE + DNOPE) * RKV, (long)QLEN * DQK, 0.f, nullptr, nullptr, nullptr);

    // 7) rope q_pe
    rope_Q<<<dim3(QLEN, NHEADS), 32>>>(qfull, qpos, Qc);

    // ---- join ----
    cudaStreamWaitEvent(0, evKV, 0);

    // 8) P[h] = exp(Q@K^T*scale - tilemax) fp16 + tile stats  [NT tf32, STATS]
    mma_gemm<4, true, 0, 1><<<dim3(SLEN / 128, 2, NHEADS), 256, smem_b(4, true, 0, 1)>>>(
        Qc, Kc, nullptr, DQK,
        DQK, DQK, SLEN,
        (long)QLEN * DQK, 0, (long)QLEN * SLEN, scale, P, tmax, tsum);

    // 9) combine tile stats
    combine_stats<<<NHEADS * QLEN / 8, dim3(32, 8)>>>(tmax, tsum, rowm, rowis);

    // 10) oc[h] = softmax @ ckv  [fp16 PV]
    pv_gemm<<<dim3(RKV / 128, 2, NHEADS), 256, 2 * (128 * 20 + 128 * 20) * 4>>>(
        P, ckvTh, oc, tmax, rowm, rowis);

    // 11) ao[:, h*128:] = oc[h] @ out_absorb[h]^T  [NT bf16x3]
    mma_gemm<4, true, 1, 0><<<dim3(1, 2, NHEADS), 256, smem_b(4, true, 1)>>>(
        oc, W_kvb + (long)DNOPE * RKV, ao, RKV,
        RKV, RKV, AO_COLS,
        (long)QLEN * RKV, (long)(DNOPE + DNOPE) * RKV, (long)DNOPE, 0.f, nullptr, nullptr, nullptr);

    // 12) out = ao @ W_o : split-K 4
    mma_gemm<4, false, 1, 0><<<dim3(HID / 128, 2, 4), 256, smem_b(4, false, 1)>>>(
        ao, W_o, part, AO_COLS / 4, AO_COLS, HID, HID,
        (long)(AO_COLS / 4), (long)(AO_COLS / 4) * HID, (long)QLEN * HID, 0.f, nullptr, nullptr, nullptr);
    reduce_slices<<<(QLEN * HID / 4 + 255) / 256, 256>>>((const float4*)part, (float4*)out, QLEN * HID / 4, 4);
}

// round 10
// speedup vs baseline: 1.9474x; 1.1019x over previous
#include <cuda_runtime.h>
#include <cuda_fp16.h>
#include <math.h>
#include <stdint.h>

// ---------------- Problem constants ----------------
#define NHEADS   128
#define DNOPE    128
#define DROPE    64
#define DQK      576
#define RKV      512
#define RQ       1536
#define HID      5120
#define QLEN     256
#define SLEN     4096
#define QB_COLS  24576
#define AO_COLS  16384
#define EPSF     1e-6f
#define NTILES_S (SLEN / 128)    // 32

// ---------------- Scratch (device globals) ----------------
__device__ __align__(128) float  g_qa_buf [QLEN * RQ];
__device__ __align__(128) float  g_qfull  [QLEN * QB_COLS];
__device__ __align__(128) float  g_ckvraw [SLEN * DQK];
__device__ __align__(128) __half g_Kch    [SLEN * DQK];
__device__ __align__(128) __half g_ckvTh  [(size_t)RKV * SLEN];
__device__ __align__(128) __half g_Qch    [(size_t)NHEADS * QLEN * DQK];
__device__ __align__(128) __half g_P      [(size_t)NHEADS * QLEN * SLEN];  // 256 MB
__device__ __align__(128) float  g_oc     [(size_t)NHEADS * QLEN * RKV];
__device__ __align__(128) float  g_ao     [QLEN * AO_COLS];
__device__ __align__(128) float  g_part   [8 * QLEN * HID];
__device__ __align__(128) float  g_rowm   [NHEADS * QLEN];
__device__ __align__(128) float  g_rowis  [NHEADS * QLEN];
__device__ __align__(128) float  g_tmax   [(size_t)NHEADS * QLEN * NTILES_S];
__device__ __align__(128) float  g_tsum   [(size_t)NHEADS * QLEN * NTILES_S];

// ---------------- helpers ----------------
__device__ __forceinline__ uint32_t smem_u32(const void* p) {
    uint32_t a;
    asm("{ .reg .u64 t; cvta.to.shared.u64 t, %1; cvt.u32.u64 %0, t; }" : "=r"(a) : "l"(p));
    return a;
}
__device__ __forceinline__ uint32_t f2tf(float x) {
    uint32_t r;
    asm("cvt.rna.tf32.f32 %0, %1;" : "=r"(r) : "f"(x));
    return r;
}
__device__ __forceinline__ uint32_t pack_bf16(float lo, float hi) {
    uint32_t r;
    asm("cvt.rn.bf16x2.f32 %0, %1, %2;" : "=r"(r) : "f"(hi), "f"(lo));
    return r;
}
__device__ __forceinline__ float bflo(uint32_t p) { return __uint_as_float(p << 16); }
__device__ __forceinline__ float bfhi(uint32_t p) { return __uint_as_float(p & 0xffff0000u); }

__device__ __forceinline__ void mma8(float* d, const uint32_t* a, uint32_t b0, uint32_t b1) {
    asm volatile(
        "mma.sync.aligned.m16n8k8.row.col.f32.tf32.tf32.f32 "
        "{%0,%1,%2,%3},{%4,%5,%6,%7},{%8,%9},{%0,%1,%2,%3};"
        : "+f"(d[0]), "+f"(d[1]), "+f"(d[2]), "+f"(d[3])
        : "r"(a[0]), "r"(a[1]), "r"(a[2]), "r"(a[3]), "r"(b0), "r"(b1));
}
__device__ __forceinline__ void mma16b(float* d, const uint32_t* a, uint32_t b0, uint32_t b1) {
    asm volatile(
        "mma.sync.aligned.m16n8k16.row.col.f32.bf16.bf16.f32 "
        "{%0,%1,%2,%3},{%4,%5,%6,%7},{%8,%9},{%0,%1,%2,%3};"
        : "+f"(d[0]), "+f"(d[1]), "+f"(d[2]), "+f"(d[3])
        : "r"(a[0]), "r"(a[1]), "r"(a[2]), "r"(a[3]), "r"(b0), "r"(b1));
}
__device__ __forceinline__ void mma16h(float* d, const uint32_t* a, uint32_t b0, uint32_t b1) {
    asm volatile(
        "mma.sync.aligned.m16n8k16.row.col.f32.f16.f16.f32 "
        "{%0,%1,%2,%3},{%4,%5,%6,%7},{%8,%9},{%0,%1,%2,%3};"
        : "+f"(d[0]), "+f"(d[1]), "+f"(d[2]), "+f"(d[3])
        : "r"(a[0]), "r"(a[1]), "r"(a[2]), "r"(a[3]), "r"(b0), "r"(b1));
}
__device__ __forceinline__ void ldm_x4(uint32_t* r, uint32_t addr) {
    asm volatile("ldmatrix.sync.aligned.m8n8.x4.shared.b16 {%0,%1,%2,%3}, [%4];"
                 : "=r"(r[0]), "=r"(r[1]), "=r"(r[2]), "=r"(r[3]) : "r"(addr));
}

// ---------------- generic mma.sync GEMM ----------------
// TRANSB=1: C = A @ B^T, B:[N,K] K-major. TRANSB=0: C = A @ B, B:[K,N] N-major.
// PREC=0: tf32 single. PREC=1: bf16 3-term hi/lo split.
// HOUT=1: C is __half* (ldc/sC in half elements).
template<int NT, bool TRANSB, int PREC, int HOUT>
__global__ void __launch_bounds__(256, 2)
mma_gemm(const float* __restrict__ A, const float* __restrict__ B, float* __restrict__ C,
         int K, int lda, int ldb, int ldc, long sA, long sB, long sC)
{
    constexpr int BN   = NT * 32;
    constexpr int A_ST = (PREC == 0) ? 128 * 36 : 128 * 20 * 2;
    constexpr int B_ST = TRANSB ? ((PREC == 0) ? BN * 36 : BN * 20 * 2)
                                : ((PREC == 0) ? 32 * (BN + 8) : 16 * (BN + 8) * 2);
    constexpr int STG  = A_ST + B_ST;
    constexpr int BQ   = BN / 4;

    extern __shared__ uint32_t smu[];
    const uint32_t smem_base = smem_u32(smu);

    const int tid  = threadIdx.x;
    const int warp = tid >> 5;
    const int lane = tid & 31;
    const int wm = (warp >> 2) * 64;
    const int wn = (warp & 3) * (BN / 4);
    const int g  = lane >> 2;
    const int tq = lane & 3;

    const int bm = blockIdx.y * 128;
    const int bn = blockIdx.x * BN;
    A += (long)blockIdx.z * sA + (long)bm * lda;
    if (TRANSB) B += (long)blockIdx.z * sB + (long)bn * ldb;
    else        B += (long)blockIdx.z * sB + bn;
    const long coff = (long)blockIdx.z * sC + (long)bm * ldc + bn;

    const int NC = K >> 5;

    float acc[4][NT][4];
#pragma unroll
    for (int i = 0; i < 4; i++)
#pragma unroll
        for (int j = 0; j < NT; j++)
#pragma unroll
            for (int l = 0; l < 4; l++) acc[i][j][l] = 0.f;

    float4 rA[4];
    float4 rB[4];

    auto ldg_chunk = [&](int c) {
        const float* ga = A + c * 32;
#pragma unroll
        for (int i = 0; i < 4; i++) {
            int idx = tid + i * 256;
            int r = idx >> 3, c4 = (idx & 7) << 2;
            rA[i] = *(const float4*)(ga + (long)r * lda + c4);
        }
        if (TRANSB) {
            const float* gb = B + c * 32;
#pragma unroll
            for (int i = 0; i < NT; i++) {
                int idx = tid + i * 256;
                int r = idx >> 3, c4 = (idx & 7) << 2;
                rB[i] = *(const float4*)(gb + (long)r * ldb + c4);
            }
        } else if (PREC == 0) {
            const float* gb = B + (long)(c * 32) * ldb;
#pragma unroll
            for (int i = 0; i < NT; i++) {
                int idx = tid + i * 256;
                int r = idx / BQ, c4 = (idx % BQ) << 2;
                rB[i] = *(const float4*)(gb + (long)r * ldb + c4);
            }
        } else {
            const float* gb = B + (long)(c * 32) * ldb;
#pragma unroll
            for (int i = 0; i < 2; i++) {
                int u = tid + i * 256;
                if (u < 16 * BQ) {
                    int kp = u / BQ, c4 = (u % BQ) << 2;
                    rB[2 * i]     = *(const float4*)(gb + (long)(2 * kp) * ldb + c4);
                    rB[2 * i + 1] = *(const float4*)(gb + (long)(2 * kp + 1) * ldb + c4);
                }
            }
        }
    };

    auto sts_chunk = [&](int sbase) {
        uint32_t* sa = smu + sbase;
        uint32_t* sb = smu + sbase + A_ST;
        if (PREC == 0) {
#pragma unroll
            for (int i = 0; i < 4; i++) {
                int idx = tid + i * 256;
                int r = idx >> 3, c4 = (idx & 7) << 2;
                float4 v = rA[i];
                uint4 w = { f2tf(v.x), f2tf(v.y), f2tf(v.z), f2tf(v.w) };
                *(uint4*)&sa[r * 36 + c4] = w;
            }
            if (TRANSB) {
#pragma unroll
                for (int i = 0; i < NT; i++) {
                    int idx = tid + i * 256;
                    int r = idx >> 3, c4 = (idx & 7) << 2;
                    uint4 w = { f2tf(rB[i].x), f2tf(rB[i].y), f2tf(rB[i].z), f2tf(rB[i].w) };
                    *(uint4*)&sb[r * 36 + c4] = w;
                }
            } else {
#pragma unroll
                for (int i = 0; i < NT; i++) {
                    int idx = tid + i * 256;
                    int r = idx / BQ, c4 = (idx % BQ) << 2;
                    uint4 w = { f2tf(rB[i].x), f2tf(rB[i].y), f2tf(rB[i].z), f2tf(rB[i].w) };
                    *(uint4*)&sb[r * (BN + 8) + c4] = w;
                }
            }
        } else {
#pragma unroll
            for (int i = 0; i < 4; i++) {
                int idx = tid + i * 256;
                int r = idx >> 3, cu = (idx & 7) << 1;
                float4 v = rA[i];
                uint32_t h0 = pack_bf16(v.x, v.y), h1 = pack_bf16(v.z, v.w);
                uint32_t l0 = pack_bf16(v.x - bflo(h0), v.y - bfhi(h0));
                uint32_t l1 = pack_bf16(v.z - bflo(h1), v.w - bfhi(h1));
                *(uint2*)&sa[r * 20 + cu]            = make_uint2(h0, h1);
                *(uint2*)&sa[128 * 20 + r * 20 + cu] = make_uint2(l0, l1);
            }
            if (TRANSB) {
#pragma unroll
                for (int i = 0; i < NT; i++) {
                    int idx = tid + i * 256;
                    int r = idx >> 3, cu = (idx & 7) << 1;
                    float4 v = rB[i];
                    uint32_t h0 = pack_bf16(v.x, v.y), h1 = pack_bf16(v.z, v.w);
                    uint32_t l0 = pack_bf16(v.x - bflo(h0), v.y - bfhi(h0));
                    uint32_t l1 = pack_bf16(v.z - bflo(h1), v.w - bfhi(h1));
                    *(uint2*)&sb[r * 20 + cu]           = make_uint2(h0, h1);
                    *(uint2*)&sb[BN * 20 + r * 20 + cu] = make_uint2(l0, l1);
                }
            } else {
#pragma unroll
                for (int i = 0; i < 2; i++) {
                    int u = tid + i * 256;
                    if (u < 16 * BQ) {
                        int kp = u / BQ, c4 = (u % BQ) << 2;
                        float4 v0 = rB[2 * i], v1 = rB[2 * i + 1];
                        uint4 h = { pack_bf16(v0.x, v1.x), pack_bf16(v0.y, v1.y),
                                    pack_bf16(v0.z, v1.z), pack_bf16(v0.w, v1.w) };
                        uint4 l = { pack_bf16(v0.x - bflo(h.x), v1.x - bfhi(h.x)),
                                    pack_bf16(v0.y - bflo(h.y), v1.y - bfhi(h.y)),
                                    pack_bf16(v0.z - bflo(h.z), v1.z - bfhi(h.z)),
                                    pack_bf16(v0.w - bflo(h.w), v1.w - bfhi(h.w)) };
                        *(uint4*)&sb[kp * (BN + 8) + c4]                 = h;
                        *(uint4*)&sb[16 * (BN + 8) + kp * (BN + 8) + c4] = l;
                    }
                }
            }
        }
    };

    auto compute = [&](int sbase) {
        const uint32_t aB = smem_base + (uint32_t)sbase * 4;
        const uint32_t bB = smem_base + (uint32_t)(sbase + A_ST) * 4;
        const int mat = lane >> 3;
        if (PREC == 0) {
#pragma unroll
            for (int kk = 0; kk < 4; kk++) {
                const int kcu = kk * 8;
                uint32_t af[4][4];
#pragma unroll
                for (int mt = 0; mt < 4; mt++) {
                    int row = wm + mt * 16 + ((mat & 1) << 3) + (lane & 7);
                    int col = kcu + ((mat >> 1) << 2);
                    ldm_x4(af[mt], aB + (uint32_t)(row * 36 + col) * 4);
                }
                if (TRANSB) {
#pragma unroll
                    for (int np = 0; np < NT / 2; np++) {
                        uint32_t bf[4];
                        int row = wn + (2 * np + (mat >> 1)) * 8 + (lane & 7);
                        int col = kcu + ((mat & 1) << 2);
                        ldm_x4(bf, bB + (uint32_t)(row * 36 + col) * 4);
#pragma unroll
                        for (int mt = 0; mt < 4; mt++) {
                            mma8(acc[mt][2 * np],     af[mt], bf[0], bf[1]);
                            mma8(acc[mt][2 * np + 1], af[mt], bf[2], bf[3]);
                        }
                    }
                } else {
                    const uint32_t* sb = smu + sbase + A_ST;
#pragma unroll
                    for (int nt = 0; nt < NT; nt++) {
                        int n0 = wn + nt * 8 + g;
                        uint32_t b0 = sb[(kcu + tq) * (BN + 8) + n0];
                        uint32_t b1 = sb[(kcu + tq + 4) * (BN + 8) + n0];
#pragma unroll
                        for (int mt = 0; mt < 4; mt++)
                            mma8(acc[mt][nt], af[mt], b0, b1);
                    }
                }
            }
        } else {
#pragma unroll
            for (int kk = 0; kk < 2; kk++) {
                const int kcu = kk * 8;
                uint32_t ah[4][4], al[4][4];
#pragma unroll
                for (int mt = 0; mt < 4; mt++) {
                    int row = wm + mt * 16 + ((mat & 1) << 3) + (lane & 7);
                    int col = kcu + ((mat >> 1) << 2);
                    ldm_x4(ah[mt], aB + (uint32_t)(row * 20 + col) * 4);
                    ldm_x4(al[mt], aB + (uint32_t)(128 * 20 + row * 20 + col) * 4);
                }
                if (TRANSB) {
#pragma unroll
                    for (int np = 0; np < NT / 2; np++) {
                        uint32_t bh[4], bl[4];
                        int row = wn + (2 * np + (mat >> 1)) * 8 + (lane & 7);
                        int col = kcu + ((mat & 1) << 2);
                        ldm_x4(bh, bB + (uint32_t)(row * 20 + col) * 4);
                        ldm_x4(bl, bB + (uint32_t)(BN * 20 + row * 20 + col) * 4);
#pragma unroll
                        for (int mt = 0; mt < 4; mt++) {
                            mma16b(acc[mt][2 * np], ah[mt], bh[0], bh[1]);
                            mma16b(acc[mt][2 * np], al[mt], bh[0], bh[1]);
                            mma16b(acc[mt][2 * np], ah[mt], bl[0], bl[1]);
                            mma16b(acc[mt][2 * np + 1], ah[mt], bh[2], bh[3]);
                            mma16b(acc[mt][2 * np + 1], al[mt], bh[2], bh[3]);
                            mma16b(acc[mt][2 * np + 1], ah[mt], bl[2], bl[3]);
                        }
                    }
                } else {
                    const uint32_t* sbh = smu + sbase + A_ST;
                    const uint32_t* sbl = sbh + 16 * (BN + 8);
#pragma unroll
                    for (int nt = 0; nt < NT; nt++) {
                        int n0 = wn + nt * 8 + g;
                        uint32_t b0h = sbh[(kcu + tq) * (BN + 8) + n0];
                        uint32_t b1h = sbh[(kcu + tq + 4) * (BN + 8) + n0];
                        uint32_t b0l = sbl[(kcu + tq) * (BN + 8) + n0];
                        uint32_t b1l = sbl[(kcu + tq + 4) * (BN + 8) + n0];
#pragma unroll
                        for (int mt = 0; mt < 4; mt++) {
                            mma16b(acc[mt][nt], ah[mt], b0h, b1h);
                            mma16b(acc[mt][nt], al[mt], b0h, b1h);
                            mma16b(acc[mt][nt], ah[mt], b0l, b1l);
                        }
                    }
                }
            }
        }
    };

    // ---- pipeline ----
    ldg_chunk(0);
    sts_chunk(0);
    __syncthreads();
    for (int c = 0; c < NC; c++) {
        if (c + 1 < NC) ldg_chunk(c + 1);
        compute((c & 1) * STG);
        if (c + 1 < NC) {
            sts_chunk(((c + 1) & 1) * STG);
            __syncthreads();
        }
    }

    if (!HOUT) {
        float* Cf = C + coff;
#pragma unroll
        for (int mt = 0; mt < 4; mt++) {
            const int r0 = wm + mt * 16 + g;
#pragma unroll
            for (int nt = 0; nt < NT; nt++) {
                const int c0 = wn + nt * 8 + tq * 2;
                *(float2*)&Cf[(long)r0 * ldc + c0]       = make_float2(acc[mt][nt][0], acc[mt][nt][1]);
                *(float2*)&Cf[(long)(r0 + 8) * ldc + c0] = make_float2(acc[mt][nt][2], acc[mt][nt][3]);
            }
        }
    } else {
        __half* Ch = ((__half*)C) + coff;
#pragma unroll
        for (int mt = 0; mt < 4; mt++) {
            const int r0 = wm + mt * 16 + g;
#pragma unroll
            for (int nt = 0; nt < NT; nt++) {
                const int c0 = wn + nt * 8 + tq * 2;
                *(__half2*)&Ch[(long)r0 * ldc + c0]       = __floats2half2_rn(acc[mt][nt][0], acc[mt][nt][1]);
                *(__half2*)&Ch[(long)(r0 + 8) * ldc + c0] = __floats2half2_rn(acc[mt][nt][2], acc[mt][nt][3]);
            }
        }
    }
}

// ---------------- fp16 QK^T GEMM with fused exp + tile stats ----------------
// A: Qch [head][256][576] fp16, B: Kch [4096][576] fp16 (both K-major).
// Writes P = exp(x*escale - tilemax) fp16 [head][256][4096] + tmax/tsum.
__global__ void __launch_bounds__(256, 2)
qk_gemm(const __half* __restrict__ A, const __half* __restrict__ B, __half* __restrict__ Ph,
        float escale, float* __restrict__ gtmax, float* __restrict__ gtsum)
{
    constexpr int A_ST = 128 * 20;
    constexpr int B_ST = 128 * 20;
    constexpr int STG  = A_ST + B_ST;

    extern __shared__ uint32_t smu[];
    const uint32_t smem_base = smem_u32(smu);

    const int tid  = threadIdx.x;
    const int warp = tid >> 5;
    const int lane = tid & 31;
    const int wm = (warp >> 2) * 64;
    const int wn = (warp & 3) * 32;
    const int g  = lane >> 2;
    const int tq = lane & 3;
    const int mat = lane >> 3;

    const int bm = blockIdx.y * 128;
    const int bn = blockIdx.x * 128;
    const int z  = blockIdx.z;
    A  += (long)z * QLEN * DQK + (long)bm * DQK;
    B  += (long)bn * DQK;
    Ph += (long)z * QLEN * SLEN + (long)bm * SLEN + bn;

    const int ar  = tid >> 1;
    const int ahc = (tid & 1) * 16;

    float acc[4][4][4];
#pragma unroll
    for (int i = 0; i < 4; i++)
#pragma unroll
        for (int j = 0; j < 4; j++)
#pragma unroll
            for (int l = 0; l < 4; l++) acc[i][j][l] = 0.f;

    uint4 ra0, ra1, rb0, rb1;

    auto ldg_chunk = [&](int c) {
        const __half* ga = A + (long)ar * DQK + c * 32 + ahc;
        ra0 = *(const uint4*)(ga);
        ra1 = *(const uint4*)(ga + 8);
        const __half* gb = B + (long)ar * DQK + c * 32 + ahc;
        rb0 = *(const uint4*)(gb);
        rb1 = *(const uint4*)(gb + 8);
    };

    auto sts_chunk = [&](int sbase) {
        uint32_t* sa = smu + sbase;
        uint32_t* sb = smu + sbase + A_ST;
        const int cu = ahc >> 1;
        *(uint4*)&sa[ar * 20 + cu]     = ra0;
        *(uint4*)&sa[ar * 20 + cu + 4] = ra1;
        *(uint4*)&sb[ar * 20 + cu]     = rb0;
        *(uint4*)&sb[ar * 20 + cu + 4] = rb1;
    };

    auto compute = [&](int sbase) {
        const uint32_t aB = smem_base + (uint32_t)sbase * 4;
        const uint32_t bB = smem_base + (uint32_t)(sbase + A_ST) * 4;
#pragma unroll
        for (int kk = 0; kk < 2; kk++) {
            const int kcu = kk * 8;
            uint32_t af[4][4];
#pragma unroll
            for (int mt = 0; mt < 4; mt++) {
                int row = wm + mt * 16 + ((mat & 1) << 3) + (lane & 7);
                int col = kcu + ((mat >> 1) << 2);
                ldm_x4(af[mt], aB + (uint32_t)(row * 20 + col) * 4);
            }
#pragma unroll
            for (int np = 0; np < 2; np++) {
                uint32_t bf[4];
                int row = wn + (2 * np + (mat >> 1)) * 8 + (lane & 7);
                int col = kcu + ((mat & 1) << 2);
                ldm_x4(bf, bB + (uint32_t)(row * 20 + col) * 4);
#pragma unroll
                for (int mt = 0; mt < 4; mt++) {
                    mma16h(acc[mt][2 * np],     af[mt], bf[0], bf[1]);
                    mma16h(acc[mt][2 * np + 1], af[mt], bf[2], bf[3]);
                }
            }
        }
    };

    ldg_chunk(0);
    sts_chunk(0);
    __syncthreads();
    const int NC = DQK / 32;   // 18
    for (int c = 0; c < NC; c++) {
        if (c + 1 < NC) ldg_chunk(c + 1);
        compute((c & 1) * STG);
        if (c + 1 < NC) {
            sts_chunk(((c + 1) & 1) * STG);
            __syncthreads();
        }
    }

    // fused: per-tile row max, P=exp fp16 store, per-tile sum
    float* st_max = (float*)(smu + 2 * STG);
    float* st_sum = st_max + 512;
    const int nw = warp & 3;
    __syncthreads();
#pragma unroll
    for (int mt = 0; mt < 4; mt++) {
#pragma unroll
        for (int h = 0; h < 2; h++) {
            float mx = -INFINITY;
#pragma unroll
            for (int nt = 0; nt < 4; nt++) {
                mx = fmaxf(mx, acc[mt][nt][2 * h]);
                mx = fmaxf(mx, acc[mt][nt][2 * h + 1]);
            }
            mx = fmaxf(mx, __shfl_xor_sync(0xffffffffu, mx, 1));
            mx = fmaxf(mx, __shfl_xor_sync(0xffffffffu, mx, 2));
            if (tq == 0) st_max[(wm + mt * 16 + h * 8 + g) * 4 + nw] = mx * escale;
        }
    }
    __syncthreads();
#pragma unroll
    for (int mt = 0; mt < 4; mt++) {
#pragma unroll
        for (int h = 0; h < 2; h++) {
            const int row = wm + mt * 16 + h * 8 + g;
            float rm = fmaxf(fmaxf(st_max[row * 4 + 0], st_max[row * 4 + 1]),
                             fmaxf(st_max[row * 4 + 2], st_max[row * 4 + 3]));
            float s = 0.f;
#pragma unroll
            for (int nt = 0; nt < 4; nt++) {
                float p0 = __expf(fmaf(acc[mt][nt][2 * h],     escale, -rm));
                float p1 = __expf(fmaf(acc[mt][nt][2 * h + 1], escale, -rm));
                s += p0 + p1;
                *(__half2*)&Ph[(long)row * SLEN + wn + nt * 8 + tq * 2] =
                    __floats2half2_rn(p0, p1);
            }
            s += __shfl_xor_sync(0xffffffffu, s, 1);
            s += __shfl_xor_sync(0xffffffffu, s, 2);
            if (tq == 0) st_sum[row * 4 + nw] = s;
        }
    }
    __syncthreads();
    if (tid < 128) {
        float m = fmaxf(fmaxf(st_max[tid * 4 + 0], st_max[tid * 4 + 1]),
                        fmaxf(st_max[tid * 4 + 2], st_max[tid * 4 + 3]));
        float s = st_sum[tid * 4 + 0] + st_sum[tid * 4 + 1]
                + st_sum[tid * 4 + 2] + st_sum[tid * 4 + 3];
        long grow = (long)z * QLEN + bm + tid;
        gtmax[grow * NTILES_S + blockIdx.x] = m;
        gtsum[grow * NTILES_S + blockIdx.x] = s;
    }
}

// ---------------- fp16 PV GEMM: oc[h] = softmax(P)[h] @ ckv ----------------
__global__ void __launch_bounds__(256, 2)
pv_gemm(const __half* __restrict__ A, const __half* __restrict__ B, float* __restrict__ C,
        const float* __restrict__ tmax, const float* __restrict__ rowm,
        const float* __restrict__ rowis)
{
    constexpr int A_ST = 128 * 20;
    constexpr int B_ST = 128 * 20;
    constexpr int STG  = A_ST + B_ST;

    extern __shared__ uint32_t smu[];
    const uint32_t smem_base = smem_u32(smu);

    const int tid  = threadIdx.x;
    const int warp = tid >> 5;
    const int lane = tid & 31;
    const int wm = (warp >> 2) * 64;
    const int wn = (warp & 3) * 32;
    const int g  = lane >> 2;
    const int tq = lane & 3;
    const int mat = lane >> 3;

    const int bm = blockIdx.y * 128;
    const int bn = blockIdx.x * 128;
    const int z  = blockIdx.z;
    A += (long)z * QLEN * SLEN + (long)bm * SLEN;
    B += (long)bn * SLEN;
    C += (long)z * QLEN * RKV + (long)bm * RKV + bn;

    const int ar  = tid >> 1;
    const int ahc = (tid & 1) * 16;
    const long grow = (long)z * QLEN + bm + ar;
    const float m_r  = rowm[grow];
    const float is_r = rowis[grow];
    const float* tmax_r = tmax + grow * NTILES_S;

    float acc[4][4][4];
#pragma unroll
    for (int i = 0; i < 4; i++)
#pragma unroll
        for (int j = 0; j < 4; j++)
#pragma unroll
            for (int l = 0; l < 4; l++) acc[i][j][l] = 0.f;

    uint4 ra0, ra1, rb0, rb1;

    auto ldg_chunk = [&](int c) {
        const __half* ga = A + (long)ar * SLEN + c * 32 + ahc;
        ra0 = *(const uint4*)(ga);
        ra1 = *(const uint4*)(ga + 8);
        const __half* gb = B + (long)ar * SLEN + c * 32 + ahc;
        rb0 = *(const uint4*)(gb);
        rb1 = *(const uint4*)(gb + 8);
    };

    auto sts_chunk = [&](int c, int sbase) {
        const float f = __expf(tmax_r[c >> 2] - m_r) * is_r;
        uint32_t* sa = smu + sbase;
        uint32_t* sb = smu + sbase + A_ST;
        const int cu = ahc >> 1;
        uint32_t aw[8] = { ra0.x, ra0.y, ra0.z, ra0.w, ra1.x, ra1.y, ra1.z, ra1.w };
#pragma unroll
        for (int i = 0; i < 8; i++) {
            float2 v = __half22float2(*(__half2*)&aw[i]);
            v.x *= f; v.y *= f;
            __half2 h = __floats2half2_rn(v.x, v.y);
            aw[i] = *(uint32_t*)&h;
        }
        *(uint4*)&sa[ar * 20 + cu]     = make_uint4(aw[0], aw[1], aw[2], aw[3]);
        *(uint4*)&sa[ar * 20 + cu + 4] = make_uint4(aw[4], aw[5], aw[6], aw[7]);
        *(uint4*)&sb[ar * 20 + cu]     = rb0;
        *(uint4*)&sb[ar * 20 + cu + 4] = rb1;
    };

    auto compute = [&](int sbase) {
        const uint32_t aB = smem_base + (uint32_t)sbase * 4;
        const uint32_t bB = smem_base + (uint32_t)(sbase + A_ST) * 4;
#pragma unroll
        for (int kk = 0; kk < 2; kk++) {
            const int kcu = kk * 8;
            uint32_t af[4][4];
#pragma unroll
            for (int mt = 0; mt < 4; mt++) {
                int row = wm + mt * 16 + ((mat & 1) << 3) + (lane & 7);
                int col = kcu + ((mat >> 1) << 2);
                ldm_x4(af[mt], aB + (uint32_t)(row * 20 + col) * 4);
            }
#pragma unroll
            for (int np = 0; np < 2; np++) {
                uint32_t bf[4];
                int row = wn + (2 * np + (mat >> 1)) * 8 + (lane & 7);
                int col = kcu + ((mat & 1) << 2);
                ldm_x4(bf, bB + (uint32_t)(row * 20 + col) * 4);
#pragma unroll
                for (int mt = 0; mt < 4; mt++) {
                    mma16h(acc[mt][2 * np],     af[mt], bf[0], bf[1]);
                    mma16h(acc[mt][2 * np + 1], af[mt], bf[2], bf[3]);
                }
            }
        }
    };

    ldg_chunk(0);
    sts_chunk(0, 0);
    __syncthreads();
    const int NC = SLEN / 32;
    for (int c = 0; c < NC; c++) {
        if (c + 1 < NC) ldg_chunk(c + 1);
        compute((c & 1) * STG);
        if (c + 1 < NC) {
            sts_chunk(c + 1, ((c + 1) & 1) * STG);
            __syncthreads();
        }
    }

#pragma unroll
    for (int mt = 0; mt < 4; mt++) {
        const int r0 = wm + mt * 16 + g;
#pragma unroll
        for (int nt = 0; nt < 4; nt++) {
            const int c0 = wn + nt * 8 + tq * 2;
            *(float2*)&C[(long)r0 * RKV + c0]       = make_float2(acc[mt][nt][0], acc[mt][nt][1]);
            *(float2*)&C[(long)(r0 + 8) * RKV + c0] = make_float2(acc[mt][nt][2], acc[mt][nt][3]);
        }
    }
}

// ---------------- Combine tile stats ----------------
__global__ void combine_stats(const float* __restrict__ tmax, const float* __restrict__ tsum,
                              float* __restrict__ rm, float* __restrict__ ris)
{
    const int row = blockIdx.x * 8 + threadIdx.y;
    const int t = threadIdx.x;
    float mv = tmax[(long)row * NTILES_S + t];
    float m = mv;
#pragma unroll
    for (int o = 16; o > 0; o >>= 1) m = fmaxf(m, __shfl_xor_sync(0xffffffffu, m, o));
    float s = tsum[(long)row * NTILES_S + t] * __expf(mv - m);
#pragma unroll
    for (int o = 16; o > 0; o >>= 1) s += __shfl_xor_sync(0xffffffffu, s, o);
    if (t == 0) { rm[row] = m; ris[row] = 1.f / s; }
}

// ---------------- Transpose half->half: out[c][r] = in[r*ldin + c] ----------------
__global__ void transpose_hh(const __half* __restrict__ in, __half* __restrict__ out,
                             int R, int ldin)
{
    __shared__ __half t[32][40];
    const int c0 = blockIdx.x * 32, r0 = blockIdx.y * 32;
    const int x = threadIdx.x, y0 = threadIdx.y;
    #pragma unroll
    for (int i = y0; i < 32; i += 8) t[i][x] = in[(long)(r0 + i) * ldin + c0 + x];
    __syncthreads();
    #pragma unroll
    for (int i = y0; i < 32; i += 8) out[(long)(c0 + i) * R + r0 + x] = t[x][i];
}

// ---------------- Split-K reduction ----------------
__global__ void reduce_slices(const float4* __restrict__ in, float4* __restrict__ out,
                              int n4, int S)
{
    int i = blockIdx.x * 256 + threadIdx.x;
    if (i >= n4) return;
    float4 a = in[i];
    for (int s = 1; s < S; s++) {
        float4 b = in[i + (long)s * n4];
        a.x += b.x; a.y += b.y; a.z += b.z; a.w += b.w;
    }
    out[i] = a;
}

// ---------------- RMSNorm (in place) ----------------
__global__ void rmsnorm_rows(float* __restrict__ X, const float* __restrict__ g, int cols)
{
    const long row = blockIdx.x;
    float* x = X + row * (long)cols;
    const int tid = threadIdx.x;
    const int n4 = cols >> 2;
    float ss = 0.f;
    for (int c = tid; c < n4; c += blockDim.x) {
        float4 v = ((const float4*)x)[c];
        ss += v.x * v.x + v.y * v.y + v.z * v.z + v.w * v.w;
    }
    __shared__ float red[256];
    red[tid] = ss; __syncthreads();
    for (int s = 128; s > 0; s >>= 1) { if (tid < s) red[tid] += red[tid + s]; __syncthreads(); }
    const float inv = rsqrtf(red[0] / (float)cols + EPSF);
    for (int c = tid; c < n4; c += blockDim.x) {
        float4 v = ((const float4*)x)[c];
        float4 w = ((const float4*)g)[c];
        v.x *= inv * w.x; v.y *= inv * w.y; v.z *= inv * w.z; v.w *= inv * w.w;
        ((float4*)x)[c] = v;
    }
}

// ---------------- Build K_comb -> fp16 ----------------
__global__ void build_K(const float* __restrict__ raw, const float* __restrict__ g,
                        const int* __restrict__ kvpos, __half* __restrict__ Kh)
{
    const int s = blockIdx.x;
    const float* r = raw + (long)s * DQK;
    __half* k = Kh + (long)s * DQK;
    const int tid = threadIdx.x;

    float ss = 0.f;
    for (int c = tid; c < RKV / 4; c += 128) {
        float4 v = ((const float4*)r)[c];
        ss += v.x * v.x + v.y * v.y + v.z * v.z + v.w * v.w;
    }
    __shared__ float red[128];
    red[tid] = ss; __syncthreads();
    for (int st = 64; st > 0; st >>= 1) { if (tid < st) red[tid] += red[tid + st]; __syncthreads(); }
    const float inv = rsqrtf(red[0] / (float)RKV + EPSF);
    for (int c = tid; c < RKV / 4; c += 128) {
        float4 v = ((const float4*)r)[c];
        float4 w = ((const float4*)g)[c];
        __half2 h0 = __floats2half2_rn(v.x * inv * w.x, v.y * inv * w.y);
        __half2 h1 = __floats2half2_rn(v.z * inv * w.z, v.w * inv * w.w);
        *(__half2*)&k[c * 4]     = h0;
        *(__half2*)&k[c * 4 + 2] = h1;
    }

    if (tid < 32) {
        const int j = tid;
        const float x0 = r[RKV + 2 * j];
        const float x1 = r[RKV + 2 * j + 1];
        const float pos = (float)kvpos[s];
        const float invf = powf(10000.f, -(float)j / 32.f);
        float cs, sn; sincosf(pos * invf, &sn, &cs);
        k[RKV + j]      = __float2half_rn(x0 * cs - x1 * sn);
        k[RKV + 32 + j] = __float2half_rn(x0 * sn + x1 * cs);
    }
}

// ---------------- RoPE for q_pe -> fp16 ----------------
__global__ void rope_Q(const float* __restrict__ qfull, const int* __restrict__ qpos,
                       __half* __restrict__ Qh)
{
    const int t = blockIdx.x;
    const int h = blockIdx.y;
    const int j = threadIdx.x;
    const float* src = qfull + (long)t * QB_COLS + h * (DNOPE + DROPE) + DNOPE;
    const float x0 = src[2 * j];
    const float x1 = src[2 * j + 1];
    const float pos = (float)qpos[t];
    const float invf = powf(10000.f, -(float)j / 32.f);
    float cs, sn; sincosf(pos * invf, &sn, &cs);
    __half* dst = Qh + ((long)h * QLEN + t) * DQK + RKV;
    dst[j]      = __float2half_rn(x0 * cs - x1 * sn);
    dst[32 + j] = __float2half_rn(x0 * sn + x1 * cs);
}

// ---------------- Launch ----------------
static inline void* symv(const void* s)
{
    void* p = nullptr;
    cudaGetSymbolAddress(&p, s);
    return p;
}

static inline int smem_b(int NT, bool transb, int prec)
{
    int a = (prec == 0) ? 128 * 36 : 128 * 40;
    int b = transb ? ((prec == 0) ? NT * 32 * 36 : NT * 32 * 40)
                   : 32 * (NT * 32 + 8);
    return 2 * (a + b) * 4;
}
#define SMEM_HGEMM (2 * (128 * 20 + 128 * 20) * 4)
#define SMEM_QK    (SMEM_HGEMM + 4096)

extern "C" void kernel_launch(void* const* d_in, const int* in_sizes, int n_in,
                              void* d_out, int out_size)
{
    const float* hq    = (const float*)d_in[0];
    const float* hkv   = (const float*)d_in[1];
    const float* W_qa  = (const float*)d_in[2];
    const float* gqa   = (const float*)d_in[3];
    const float* W_qb  = (const float*)d_in[4];
    const float* W_kva = (const float*)d_in[5];
    const float* gkva  = (const float*)d_in[6];
    const float* W_kvb = (const float*)d_in[7];
    const float* W_o   = (const float*)d_in[8];
    const int*   qpos  = (const int*)d_in[9];
    const int*   kvpos = (const int*)d_in[10];
    float*       out   = (float*)d_out;

    float*  qa     = (float*) symv(g_qa_buf);
    float*  qfull  = (float*) symv(g_qfull);
    float*  ckvraw = (float*) symv(g_ckvraw);
    __half* Kch    = (__half*)symv(g_Kch);
    __half* ckvTh  = (__half*)symv(g_ckvTh);
    __half* Qch    = (__half*)symv(g_Qch);
    __half* P      = (__half*)symv(g_P);
    float*  oc     = (float*) symv(g_oc);
    float*  ao     = (float*) symv(g_ao);
    float*  part   = (float*) symv(g_part);
    float*  rowm   = (float*) symv(g_rowm);
    float*  rowis  = (float*) symv(g_rowis);
    float*  tmax   = (float*) symv(g_tmax);
    float*  tsum   = (float*) symv(g_tsum);

    const float scale = 1.0f / sqrtf(192.0f);

    static cudaStream_t s2 = nullptr;
    static cudaEvent_t evF = nullptr, evKV = nullptr;
    if (!s2) {
        cudaStreamCreateWithFlags(&s2, cudaStreamNonBlocking);
        cudaEventCreateWithFlags(&evF,  cudaEventDisableTiming);
        cudaEventCreateWithFlags(&evKV, cudaEventDisableTiming);
        cudaFuncSetAttribute(mma_gemm<4, false, 1, 0>, cudaFuncAttributeMaxDynamicSharedMemorySize, smem_b(4, false, 1));
        cudaFuncSetAttribute(mma_gemm<4, false, 1, 1>, cudaFuncAttributeMaxDynamicSharedMemorySize, smem_b(4, false, 1));
        cudaFuncSetAttribute(mma_gemm<3, false, 1, 0>, cudaFuncAttributeMaxDynamicSharedMemorySize, smem_b(3, false, 1));
        cudaFuncSetAttribute(mma_gemm<4, true,  1, 0>, cudaFuncAttributeMaxDynamicSharedMemorySize, smem_b(4, true, 1));
        cudaFuncSetAttribute(qk_gemm, cudaFuncAttributeMaxDynamicSharedMemorySize, SMEM_QK);
        cudaFuncSetAttribute(pv_gemm, cudaFuncAttributeMaxDynamicSharedMemorySize, SMEM_HGEMM);
    }

    // ---- fork: KV path on s2 ----
    cudaEventRecord(evF, 0);
    cudaStreamWaitEvent(s2, evF, 0);

    // 4) ckvraw = hkv @ W_kva  [NN bf16x3, BN=96] (s2)
    mma_gemm<3, false, 1, 0><<<dim3(DQK / 96, SLEN / 128, 1), 256, smem_b(3, false, 1), s2>>>(
        hkv, W_kva, ckvraw, HID, HID, DQK, DQK, 0, 0, 0);
    // 5) K_comb fp16; ckvTh = Kch[:, :512]^T  (s2)
    build_K<<<SLEN, 128, 0, s2>>>(ckvraw, gkva, kvpos, Kch);
    transpose_hh<<<dim3(RKV / 32, SLEN / 32), dim3(32, 8), 0, s2>>>(Kch, ckvTh, SLEN, DQK);
    cudaEventRecord(evKV, s2);

    // ---- Q path on default stream ----
    // 1) qa = hq @ W_qa : split-K 8
    mma_gemm<4, false, 1, 0><<<dim3(RQ / 128, 2, 8), 256, smem_b(4, false, 1)>>>(
        hq, W_qa, part, HID / 8, HID, RQ, RQ,
        (long)(HID / 8), (long)(HID / 8) * RQ, (long)QLEN * RQ);
    reduce_slices<<<(QLEN * RQ / 4 + 255) / 256, 256>>>((const float4*)part, (float4*)qa, QLEN * RQ / 4, 8);

    // 2) rmsnorm(qa)
    rmsnorm_rows<<<QLEN, 256>>>(qa, gqa, RQ);

    // 3) qfull = qa @ W_qb
    mma_gemm<4, false, 1, 0><<<dim3(QB_COLS / 128, 2, 1), 256, smem_b(4, false, 1)>>>(
        qa, W_qb, qfull, RQ, RQ, QB_COLS, QB_COLS, 0, 0, 0);

    // 6) Qch[h][:, :512] = q_nope[h] @ q_absorb[h]  [NN bf16x3, fp16 out]
    mma_gemm<4, false, 1, 1><<<dim3(RKV / 128, 2, NHEADS), 256, smem_b(4, false, 1)>>>(
        qfull, W_kvb, (float*)Qch, DNOPE,
        QB_COLS, RKV, DQK,
        (long)(DNOPE + DROPE), (long)(DNOPE + DNOPE) * RKV, (long)QLEN * DQK);

    // 7) rope q_pe -> Qch[..., 512:576)
    rope_Q<<<dim3(QLEN, NHEADS), 32>>>(qfull, qpos, Qch);

    // ---- join ----
    cudaStreamWaitEvent(0, evKV, 0);

    // 8) P = exp(Q@K^T*scale - tilemax) fp16 + tile stats  [fp16 QK]
    qk_gemm<<<dim3(SLEN / 128, QLEN / 128, NHEADS), 256, SMEM_QK>>>(
        Qch, Kch, P, scale, tmax, tsum);

    // 9) combine tile stats
    combine_stats<<<NHEADS * QLEN / 8, dim3(32, 8)>>>(tmax, tsum, rowm, rowis);

    // 10) oc[h] = softmax @ ckv  [fp16 PV]
    pv_gemm<<<dim3(RKV / 128, QLEN / 128, NHEADS), 256, SMEM_HGEMM>>>(
        P, ckvTh, oc, tmax, rowm, rowis);

    // 11) ao[:, h*128:] = oc[h] @ out_absorb[h]^T  [NT bf16x3]
    mma_gemm<4, true, 1, 0><<<dim3(1, 2, NHEADS), 256, smem_b(4, true, 1)>>>(
        oc, W_kvb + (long)DNOPE * RKV, ao, RKV,
        RKV, RKV, AO_COLS,
        (long)QLEN * RKV, (long)(DNOPE + DNOPE) * RKV, (long)DNOPE);

    // 12) out = ao @ W_o : split-K 4
    mma_gemm<4, false, 1, 0><<<dim3(HID / 128, 2, 4), 256, smem_b(4, false, 1)>>>(
        ao, W_o, part, AO_COLS / 4, AO_COLS, HID, HID,
        (long)(AO_COLS / 4), (long)(AO_COLS / 4) * HID, (long)QLEN * HID);
    reduce_slices<<<(QLEN * HID / 4 + 255) / 256, 256>>>((const float4*)part, (float4*)out, QLEN * HID / 4, 4);
}

// round 11
// speedup vs baseline: 2.1719x; 1.1153x over previous
#include <cuda_runtime.h>
#include <cuda_fp16.h>
#include <math.h>
#include <stdint.h>

// ---------------- Problem constants ----------------
#define NHEADS   128
#define DNOPE    128
#define DROPE    64
#define DQK      576
#define RKV      512
#define RQ       1536
#define HID      5120
#define QLEN     256
#define SLEN     4096
#define QB_COLS  24576
#define AO_COLS  16384
#define EPSF     1e-6f
#define NTILES_S (SLEN / 128)    // 32
#define HGRP     (NHEADS / 2)    // 64 heads per group

// ---------------- Scratch (device globals) ----------------
__device__ __align__(128) float  g_qa_buf [QLEN * RQ];
__device__ __align__(128) float  g_qfull  [QLEN * QB_COLS];
__device__ __align__(128) float  g_ckvraw [SLEN * DQK];
__device__ __align__(128) __half g_Kch    [SLEN * DQK];
__device__ __align__(128) __half g_ckvTh  [(size_t)RKV * SLEN];
__device__ __align__(128) __half g_Qch    [(size_t)NHEADS * QLEN * DQK];
__device__ __align__(128) __half g_P      [(size_t)NHEADS * QLEN * SLEN];  // 256 MB
__device__ __align__(128) __half g_och    [(size_t)NHEADS * QLEN * RKV];
__device__ __align__(128) float  g_ao     [QLEN * AO_COLS];
__device__ __align__(128) float  g_part   [8 * QLEN * HID];
__device__ __align__(128) float  g_rowm   [NHEADS * QLEN];
__device__ __align__(128) float  g_rowis  [NHEADS * QLEN];
__device__ __align__(128) float  g_tmax   [(size_t)NHEADS * QLEN * NTILES_S];
__device__ __align__(128) float  g_tsum   [(size_t)NHEADS * QLEN * NTILES_S];

// ---------------- helpers ----------------
__device__ __forceinline__ uint32_t smem_u32(const void* p) {
    uint32_t a;
    asm("{ .reg .u64 t; cvta.to.shared.u64 t, %1; cvt.u32.u64 %0, t; }" : "=r"(a) : "l"(p));
    return a;
}
__device__ __forceinline__ uint32_t f2tf(float x) {
    uint32_t r;
    asm("cvt.rna.tf32.f32 %0, %1;" : "=r"(r) : "f"(x));
    return r;
}
__device__ __forceinline__ uint32_t pack_bf16(float lo, float hi) {
    uint32_t r;
    asm("cvt.rn.bf16x2.f32 %0, %1, %2;" : "=r"(r) : "f"(hi), "f"(lo));
    return r;
}
__device__ __forceinline__ float bflo(uint32_t p) { return __uint_as_float(p << 16); }
__device__ __forceinline__ float bfhi(uint32_t p) { return __uint_as_float(p & 0xffff0000u); }

__device__ __forceinline__ void mma8(float* d, const uint32_t* a, uint32_t b0, uint32_t b1) {
    asm volatile(
        "mma.sync.aligned.m16n8k8.row.col.f32.tf32.tf32.f32 "
        "{%0,%1,%2,%3},{%4,%5,%6,%7},{%8,%9},{%0,%1,%2,%3};"
        : "+f"(d[0]), "+f"(d[1]), "+f"(d[2]), "+f"(d[3])
        : "r"(a[0]), "r"(a[1]), "r"(a[2]), "r"(a[3]), "r"(b0), "r"(b1));
}
__device__ __forceinline__ void mma16b(float* d, const uint32_t* a, uint32_t b0, uint32_t b1) {
    asm volatile(
        "mma.sync.aligned.m16n8k16.row.col.f32.bf16.bf16.f32 "
        "{%0,%1,%2,%3},{%4,%5,%6,%7},{%8,%9},{%0,%1,%2,%3};"
        : "+f"(d[0]), "+f"(d[1]), "+f"(d[2]), "+f"(d[3])
        : "r"(a[0]), "r"(a[1]), "r"(a[2]), "r"(a[3]), "r"(b0), "r"(b1));
}
__device__ __forceinline__ void mma16h(float* d, const uint32_t* a, uint32_t b0, uint32_t b1) {
    asm volatile(
        "mma.sync.aligned.m16n8k16.row.col.f32.f16.f16.f32 "
        "{%0,%1,%2,%3},{%4,%5,%6,%7},{%8,%9},{%0,%1,%2,%3};"
        : "+f"(d[0]), "+f"(d[1]), "+f"(d[2]), "+f"(d[3])
        : "r"(a[0]), "r"(a[1]), "r"(a[2]), "r"(a[3]), "r"(b0), "r"(b1));
}
__device__ __forceinline__ void ldm_x4(uint32_t* r, uint32_t addr) {
    asm volatile("ldmatrix.sync.aligned.m8n8.x4.shared.b16 {%0,%1,%2,%3}, [%4];"
                 : "=r"(r[0]), "=r"(r[1]), "=r"(r[2]), "=r"(r[3]) : "r"(addr));
}
__device__ __forceinline__ void cp16(uint32_t dst, const void* src) {
    asm volatile("cp.async.cg.shared.global [%0], [%1], 16;" :: "r"(dst), "l"(src) : "memory");
}
#define CP_COMMIT() asm volatile("cp.async.commit_group;" ::: "memory")
#define CP_WAIT(n)  asm volatile("cp.async.wait_group %0;" :: "n"(n) : "memory")

// ---------------- generic mma.sync GEMM (projections) ----------------
// TRANSB=1: C = A @ B^T, B:[N,K] K-major. TRANSB=0: C = A @ B, B:[K,N] N-major.
// PREC=0: tf32 single. PREC=1: bf16 3-term hi/lo split. HOUT=1: C is __half*.
template<int NT, bool TRANSB, int PREC, int HOUT>
__global__ void __launch_bounds__(256, 2)
mma_gemm(const float* __restrict__ A, const float* __restrict__ B, float* __restrict__ C,
         int K, int lda, int ldb, int ldc, long sA, long sB, long sC)
{
    constexpr int BN   = NT * 32;
    constexpr int A_ST = (PREC == 0) ? 128 * 36 : 128 * 20 * 2;
    constexpr int B_ST = TRANSB ? ((PREC == 0) ? BN * 36 : BN * 20 * 2)
                                : ((PREC == 0) ? 32 * (BN + 8) : 16 * (BN + 8) * 2);
    constexpr int STG  = A_ST + B_ST;
    constexpr int BQ   = BN / 4;

    extern __shared__ uint32_t smu[];
    const uint32_t smem_base = smem_u32(smu);

    const int tid  = threadIdx.x;
    const int warp = tid >> 5;
    const int lane = tid & 31;
    const int wm = (warp >> 2) * 64;
    const int wn = (warp & 3) * (BN / 4);
    const int g  = lane >> 2;
    const int tq = lane & 3;

    const int bm = blockIdx.y * 128;
    const int bn = blockIdx.x * BN;
    A += (long)blockIdx.z * sA + (long)bm * lda;
    if (TRANSB) B += (long)blockIdx.z * sB + (long)bn * ldb;
    else        B += (long)blockIdx.z * sB + bn;
    const long coff = (long)blockIdx.z * sC + (long)bm * ldc + bn;

    const int NC = K >> 5;

    float acc[4][NT][4];
#pragma unroll
    for (int i = 0; i < 4; i++)
#pragma unroll
        for (int j = 0; j < NT; j++)
#pragma unroll
            for (int l = 0; l < 4; l++) acc[i][j][l] = 0.f;

    float4 rA[4];
    float4 rB[4];

    auto ldg_chunk = [&](int c) {
        const float* ga = A + c * 32;
#pragma unroll
        for (int i = 0; i < 4; i++) {
            int idx = tid + i * 256;
            int r = idx >> 3, c4 = (idx & 7) << 2;
            rA[i] = *(const float4*)(ga + (long)r * lda + c4);
        }
        if (TRANSB) {
            const float* gb = B + c * 32;
#pragma unroll
            for (int i = 0; i < NT; i++) {
                int idx = tid + i * 256;
                int r = idx >> 3, c4 = (idx & 7) << 2;
                rB[i] = *(const float4*)(gb + (long)r * ldb + c4);
            }
        } else if (PREC == 0) {
            const float* gb = B + (long)(c * 32) * ldb;
#pragma unroll
            for (int i = 0; i < NT; i++) {
                int idx = tid + i * 256;
                int r = idx / BQ, c4 = (idx % BQ) << 2;
                rB[i] = *(const float4*)(gb + (long)r * ldb + c4);
            }
        } else {
            const float* gb = B + (long)(c * 32) * ldb;
#pragma unroll
            for (int i = 0; i < 2; i++) {
                int u = tid + i * 256;
                if (u < 16 * BQ) {
                    int kp = u / BQ, c4 = (u % BQ) << 2;
                    rB[2 * i]     = *(const float4*)(gb + (long)(2 * kp) * ldb + c4);
                    rB[2 * i + 1] = *(const float4*)(gb + (long)(2 * kp + 1) * ldb + c4);
                }
            }
        }
    };

    auto sts_chunk = [&](int sbase) {
        uint32_t* sa = smu + sbase;
        uint32_t* sb = smu + sbase + A_ST;
        if (PREC == 0) {
#pragma unroll
            for (int i = 0; i < 4; i++) {
                int idx = tid + i * 256;
                int r = idx >> 3, c4 = (idx & 7) << 2;
                float4 v = rA[i];
                uint4 w = { f2tf(v.x), f2tf(v.y), f2tf(v.z), f2tf(v.w) };
                *(uint4*)&sa[r * 36 + c4] = w;
            }
            if (TRANSB) {
#pragma unroll
                for (int i = 0; i < NT; i++) {
                    int idx = tid + i * 256;
                    int r = idx >> 3, c4 = (idx & 7) << 2;
                    uint4 w = { f2tf(rB[i].x), f2tf(rB[i].y), f2tf(rB[i].z), f2tf(rB[i].w) };
                    *(uint4*)&sb[r * 36 + c4] = w;
                }
            } else {
#pragma unroll
                for (int i = 0; i < NT; i++) {
                    int idx = tid + i * 256;
                    int r = idx / BQ, c4 = (idx % BQ) << 2;
                    uint4 w = { f2tf(rB[i].x), f2tf(rB[i].y), f2tf(rB[i].z), f2tf(rB[i].w) };
                    *(uint4*)&sb[r * (BN + 8) + c4] = w;
                }
            }
        } else {
#pragma unroll
            for (int i = 0; i < 4; i++) {
                int idx = tid + i * 256;
                int r = idx >> 3, cu = (idx & 7) << 1;
                float4 v = rA[i];
                uint32_t h0 = pack_bf16(v.x, v.y), h1 = pack_bf16(v.z, v.w);
                uint32_t l0 = pack_bf16(v.x - bflo(h0), v.y - bfhi(h0));
                uint32_t l1 = pack_bf16(v.z - bflo(h1), v.w - bfhi(h1));
                *(uint2*)&sa[r * 20 + cu]            = make_uint2(h0, h1);
                *(uint2*)&sa[128 * 20 + r * 20 + cu] = make_uint2(l0, l1);
            }
            if (TRANSB) {
#pragma unroll
                for (int i = 0; i < NT; i++) {
                    int idx = tid + i * 256;
                    int r = idx >> 3, cu = (idx & 7) << 1;
                    float4 v = rB[i];
                    uint32_t h0 = pack_bf16(v.x, v.y), h1 = pack_bf16(v.z, v.w);
                    uint32_t l0 = pack_bf16(v.x - bflo(h0), v.y - bfhi(h0));
                    uint32_t l1 = pack_bf16(v.z - bflo(h1), v.w - bfhi(h1));
                    *(uint2*)&sb[r * 20 + cu]           = make_uint2(h0, h1);
                    *(uint2*)&sb[BN * 20 + r * 20 + cu] = make_uint2(l0, l1);
                }
            } else {
#pragma unroll
                for (int i = 0; i < 2; i++) {
                    int u = tid + i * 256;
                    if (u < 16 * BQ) {
                        int kp = u / BQ, c4 = (u % BQ) << 2;
                        float4 v0 = rB[2 * i], v1 = rB[2 * i + 1];
                        uint4 h = { pack_bf16(v0.x, v1.x), pack_bf16(v0.y, v1.y),
                                    pack_bf16(v0.z, v1.z), pack_bf16(v0.w, v1.w) };
                        uint4 l = { pack_bf16(v0.x - bflo(h.x), v1.x - bfhi(h.x)),
                                    pack_bf16(v0.y - bflo(h.y), v1.y - bfhi(h.y)),
                                    pack_bf16(v0.z - bflo(h.z), v1.z - bfhi(h.z)),
                                    pack_bf16(v0.w - bflo(h.w), v1.w - bfhi(h.w)) };
                        *(uint4*)&sb[kp * (BN + 8) + c4]                 = h;
                        *(uint4*)&sb[16 * (BN + 8) + kp * (BN + 8) + c4] = l;
                    }
                }
            }
        }
    };

    auto compute = [&](int sbase) {
        const uint32_t aB = smem_base + (uint32_t)sbase * 4;
        const uint32_t bB = smem_base + (uint32_t)(sbase + A_ST) * 4;
        const int mat = lane >> 3;
        if (PREC == 0) {
#pragma unroll
            for (int kk = 0; kk < 4; kk++) {
                const int kcu = kk * 8;
                uint32_t af[4][4];
#pragma unroll
                for (int mt = 0; mt < 4; mt++) {
                    int row = wm + mt * 16 + ((mat & 1) << 3) + (lane & 7);
                    int col = kcu + ((mat >> 1) << 2);
                    ldm_x4(af[mt], aB + (uint32_t)(row * 36 + col) * 4);
                }
                if (TRANSB) {
#pragma unroll
                    for (int np = 0; np < NT / 2; np++) {
                        uint32_t bf[4];
                        int row = wn + (2 * np + (mat >> 1)) * 8 + (lane & 7);
                        int col = kcu + ((mat & 1) << 2);
                        ldm_x4(bf, bB + (uint32_t)(row * 36 + col) * 4);
#pragma unroll
                        for (int mt = 0; mt < 4; mt++) {
                            mma8(acc[mt][2 * np],     af[mt], bf[0], bf[1]);
                            mma8(acc[mt][2 * np + 1], af[mt], bf[2], bf[3]);
                        }
                    }
                } else {
                    const uint32_t* sb = smu + sbase + A_ST;
#pragma unroll
                    for (int nt = 0; nt < NT; nt++) {
                        int n0 = wn + nt * 8 + g;
                        uint32_t b0 = sb[(kcu + tq) * (BN + 8) + n0];
                        uint32_t b1 = sb[(kcu + tq + 4) * (BN + 8) + n0];
#pragma unroll
                        for (int mt = 0; mt < 4; mt++)
                            mma8(acc[mt][nt], af[mt], b0, b1);
                    }
                }
            }
        } else {
#pragma unroll
            for (int kk = 0; kk < 2; kk++) {
                const int kcu = kk * 8;
                uint32_t ah[4][4], al[4][4];
#pragma unroll
                for (int mt = 0; mt < 4; mt++) {
                    int row = wm + mt * 16 + ((mat & 1) << 3) + (lane & 7);
                    int col = kcu + ((mat >> 1) << 2);
                    ldm_x4(ah[mt], aB + (uint32_t)(row * 20 + col) * 4);
                    ldm_x4(al[mt], aB + (uint32_t)(128 * 20 + row * 20 + col) * 4);
                }
                if (TRANSB) {
#pragma unroll
                    for (int np = 0; np < NT / 2; np++) {
                        uint32_t bh[4], bl[4];
                        int row = wn + (2 * np + (mat >> 1)) * 8 + (lane & 7);
                        int col = kcu + ((mat & 1) << 2);
                        ldm_x4(bh, bB + (uint32_t)(row * 20 + col) * 4);
                        ldm_x4(bl, bB + (uint32_t)(BN * 20 + row * 20 + col) * 4);
#pragma unroll
                        for (int mt = 0; mt < 4; mt++) {
                            mma16b(acc[mt][2 * np], ah[mt], bh[0], bh[1]);
                            mma16b(acc[mt][2 * np], al[mt], bh[0], bh[1]);
                            mma16b(acc[mt][2 * np], ah[mt], bl[0], bl[1]);
                            mma16b(acc[mt][2 * np + 1], ah[mt], bh[2], bh[3]);
                            mma16b(acc[mt][2 * np + 1], al[mt], bh[2], bh[3]);
                            mma16b(acc[mt][2 * np + 1], ah[mt], bl[2], bl[3]);
                        }
                    }
                } else {
                    const uint32_t* sbh = smu + sbase + A_ST;
                    const uint32_t* sbl = sbh + 16 * (BN + 8);
#pragma unroll
                    for (int nt = 0; nt < NT; nt++) {
                        int n0 = wn + nt * 8 + g;
                        uint32_t b0h = sbh[(kcu + tq) * (BN + 8) + n0];
                        uint32_t b1h = sbh[(kcu + tq + 4) * (BN + 8) + n0];
                        uint32_t b0l = sbl[(kcu + tq) * (BN + 8) + n0];
                        uint32_t b1l = sbl[(kcu + tq + 4) * (BN + 8) + n0];
#pragma unroll
                        for (int mt = 0; mt < 4; mt++) {
                            mma16b(acc[mt][nt], ah[mt], b0h, b1h);
                            mma16b(acc[mt][nt], al[mt], b0h, b1h);
                            mma16b(acc[mt][nt], ah[mt], b0l, b1l);
                        }
                    }
                }
            }
        }
    };

    ldg_chunk(0);
    sts_chunk(0);
    __syncthreads();
    for (int c = 0; c < NC; c++) {
        if (c + 1 < NC) ldg_chunk(c + 1);
        compute((c & 1) * STG);
        if (c + 1 < NC) {
            sts_chunk(((c + 1) & 1) * STG);
            __syncthreads();
        }
    }

    if (!HOUT) {
        float* Cf = C + coff;
#pragma unroll
        for (int mt = 0; mt < 4; mt++) {
            const int r0 = wm + mt * 16 + g;
#pragma unroll
            for (int nt = 0; nt < NT; nt++) {
                const int c0 = wn + nt * 8 + tq * 2;
                *(float2*)&Cf[(long)r0 * ldc + c0]       = make_float2(acc[mt][nt][0], acc[mt][nt][1]);
                *(float2*)&Cf[(long)(r0 + 8) * ldc + c0] = make_float2(acc[mt][nt][2], acc[mt][nt][3]);
            }
        }
    } else {
        __half* Ch = ((__half*)C) + coff;
#pragma unroll
        for (int mt = 0; mt < 4; mt++) {
            const int r0 = wm + mt * 16 + g;
#pragma unroll
            for (int nt = 0; nt < NT; nt++) {
                const int c0 = wn + nt * 8 + tq * 2;
                *(__half2*)&Ch[(long)r0 * ldc + c0]       = __floats2half2_rn(acc[mt][nt][0], acc[mt][nt][1]);
                *(__half2*)&Ch[(long)(r0 + 8) * ldc + c0] = __floats2half2_rn(acc[mt][nt][2], acc[mt][nt][3]);
            }
        }
    }
}

// ---------------- fp16 QK^T GEMM, cp.async 3-stage, fused exp + tile stats ----------------
__global__ void __launch_bounds__(256, 2)
qk_gemm(const __half* __restrict__ A, const __half* __restrict__ B, __half* __restrict__ Ph,
        float escale, float* __restrict__ gtmax, float* __restrict__ gtsum)
{
    constexpr int A_ST = 128 * 20;
    constexpr int B_ST = 128 * 20;
    constexpr int STG  = A_ST + B_ST;
    constexpr int NC   = DQK / 32;   // 18

    extern __shared__ uint32_t smu[];
    const uint32_t smem_base = smem_u32(smu);

    const int tid  = threadIdx.x;
    const int warp = tid >> 5;
    const int lane = tid & 31;
    const int wm = (warp >> 2) * 64;
    const int wn = (warp & 3) * 32;
    const int g  = lane >> 2;
    const int tq = lane & 3;
    const int mat = lane >> 3;

    const int bm = blockIdx.y * 128;
    const int bn = blockIdx.x * 128;
    const int z  = blockIdx.z;
    A  += (long)z * QLEN * DQK + (long)bm * DQK;
    B  += (long)bn * DQK;
    Ph += (long)z * QLEN * SLEN + (long)bm * SLEN + bn;

    float acc[4][4][4];
#pragma unroll
    for (int i = 0; i < 4; i++)
#pragma unroll
        for (int j = 0; j < 4; j++)
#pragma unroll
            for (int l = 0; l < 4; l++) acc[i][j][l] = 0.f;

    auto cp_chunk = [&](int c, int stg) {
        const uint32_t sa = smem_base + (uint32_t)(stg * STG) * 4;
        const uint32_t sb = sa + A_ST * 4;
        const __half* ga = A + c * 32;
        const __half* gb = B + c * 32;
#pragma unroll
        for (int i = 0; i < 2; i++) {
            int o = tid + i * 256;          // 0..511
            int r = o >> 2, cu = (o & 3) * 4;
            cp16(sa + (uint32_t)(r * 20 + cu) * 4, ga + (long)r * DQK + cu * 2);
            cp16(sb + (uint32_t)(r * 20 + cu) * 4, gb + (long)r * DQK + cu * 2);
        }
    };

    auto compute = [&](int stg) {
        const uint32_t aB = smem_base + (uint32_t)(stg * STG) * 4;
        const uint32_t bB = aB + A_ST * 4;
#pragma unroll
        for (int kk = 0; kk < 2; kk++) {
            const int kcu = kk * 8;
            uint32_t af[4][4];
#pragma unroll
            for (int mt = 0; mt < 4; mt++) {
                int row = wm + mt * 16 + ((mat & 1) << 3) + (lane & 7);
                int col = kcu + ((mat >> 1) << 2);
                ldm_x4(af[mt], aB + (uint32_t)(row * 20 + col) * 4);
            }
#pragma unroll
            for (int np = 0; np < 2; np++) {
                uint32_t bf[4];
                int row = wn + (2 * np + (mat >> 1)) * 8 + (lane & 7);
                int col = kcu + ((mat & 1) << 2);
                ldm_x4(bf, bB + (uint32_t)(row * 20 + col) * 4);
#pragma unroll
                for (int mt = 0; mt < 4; mt++) {
                    mma16h(acc[mt][2 * np],     af[mt], bf[0], bf[1]);
                    mma16h(acc[mt][2 * np + 1], af[mt], bf[2], bf[3]);
                }
            }
        }
    };

    cp_chunk(0, 0); CP_COMMIT();
    cp_chunk(1, 1); CP_COMMIT();
    for (int c = 0; c < NC; c++) {
        CP_WAIT(1);
        __syncthreads();
        if (c + 2 < NC) cp_chunk(c + 2, (c + 2) % 3);
        CP_COMMIT();
        compute(c % 3);
    }

    // fused: per-tile row max, P=exp fp16 store, per-tile sum
    float* st_max = (float*)(smu + 3 * STG);
    float* st_sum = st_max + 512;
    const int nw = warp & 3;
    __syncthreads();
#pragma unroll
    for (int mt = 0; mt < 4; mt++) {
#pragma unroll
        for (int h = 0; h < 2; h++) {
            float mx = -INFINITY;
#pragma unroll
            for (int nt = 0; nt < 4; nt++) {
                mx = fmaxf(mx, acc[mt][nt][2 * h]);
                mx = fmaxf(mx, acc[mt][nt][2 * h + 1]);
            }
            mx = fmaxf(mx, __shfl_xor_sync(0xffffffffu, mx, 1));
            mx = fmaxf(mx, __shfl_xor_sync(0xffffffffu, mx, 2));
            if (tq == 0) st_max[(wm + mt * 16 + h * 8 + g) * 4 + nw] = mx * escale;
        }
    }
    __syncthreads();
#pragma unroll
    for (int mt = 0; mt < 4; mt++) {
#pragma unroll
        for (int h = 0; h < 2; h++) {
            const int row = wm + mt * 16 + h * 8 + g;
            float rm = fmaxf(fmaxf(st_max[row * 4 + 0], st_max[row * 4 + 1]),
                             fmaxf(st_max[row * 4 + 2], st_max[row * 4 + 3]));
            float s = 0.f;
#pragma unroll
            for (int nt = 0; nt < 4; nt++) {
                float p0 = __expf(fmaf(acc[mt][nt][2 * h],     escale, -rm));
                float p1 = __expf(fmaf(acc[mt][nt][2 * h + 1], escale, -rm));
                s += p0 + p1;
                *(__half2*)&Ph[(long)row * SLEN + wn + nt * 8 + tq * 2] =
                    __floats2half2_rn(p0, p1);
            }
            s += __shfl_xor_sync(0xffffffffu, s, 1);
            s += __shfl_xor_sync(0xffffffffu, s, 2);
            if (tq == 0) st_sum[row * 4 + nw] = s;
        }
    }
    __syncthreads();
    if (tid < 128) {
        float m = fmaxf(fmaxf(st_max[tid * 4 + 0], st_max[tid * 4 + 1]),
                        fmaxf(st_max[tid * 4 + 2], st_max[tid * 4 + 3]));
        float s = st_sum[tid * 4 + 0] + st_sum[tid * 4 + 1]
                + st_sum[tid * 4 + 2] + st_sum[tid * 4 + 3];
        long grow = (long)z * QLEN + bm + tid;
        gtmax[grow * NTILES_S + blockIdx.x] = m;
        gtsum[grow * NTILES_S + blockIdx.x] = s;
    }
}

// ---------------- fp16 PV GEMM: och[h] = softmax(P)[h] @ ckv (fp16 out) ----------------
__global__ void __launch_bounds__(256, 2)
pv_gemm(const __half* __restrict__ A, const __half* __restrict__ B, __half* __restrict__ C,
        const float* __restrict__ tmax, const float* __restrict__ rowm,
        const float* __restrict__ rowis)
{
    constexpr int A_ST = 128 * 20;
    constexpr int B_ST = 128 * 20;
    constexpr int STG  = A_ST + B_ST;

    extern __shared__ uint32_t smu[];
    const uint32_t smem_base = smem_u32(smu);

    const int tid  = threadIdx.x;
    const int warp = tid >> 5;
    const int lane = tid & 31;
    const int wm = (warp >> 2) * 64;
    const int wn = (warp & 3) * 32;
    const int g  = lane >> 2;
    const int tq = lane & 3;
    const int mat = lane >> 3;

    const int bm = blockIdx.y * 128;
    const int bn = blockIdx.x * 128;
    const int z  = blockIdx.z;
    A += (long)z * QLEN * SLEN + (long)bm * SLEN;
    B += (long)bn * SLEN;
    C += (long)z * QLEN * RKV + (long)bm * RKV + bn;

    const int ar  = tid >> 1;
    const int ahc = (tid & 1) * 16;
    const long grow = (long)z * QLEN + bm + ar;
    const float m_r  = rowm[grow];
    const float is_r = rowis[grow];
    const float* tmax_r = tmax + grow * NTILES_S;

    float acc[4][4][4];
#pragma unroll
    for (int i = 0; i < 4; i++)
#pragma unroll
        for (int j = 0; j < 4; j++)
#pragma unroll
            for (int l = 0; l < 4; l++) acc[i][j][l] = 0.f;

    uint4 ra0, ra1, rb0, rb1;

    auto ldg_chunk = [&](int c) {
        const __half* ga = A + (long)ar * SLEN + c * 32 + ahc;
        ra0 = *(const uint4*)(ga);
        ra1 = *(const uint4*)(ga + 8);
        const __half* gb = B + (long)ar * SLEN + c * 32 + ahc;
        rb0 = *(const uint4*)(gb);
        rb1 = *(const uint4*)(gb + 8);
    };

    auto sts_chunk = [&](int c, int sbase) {
        const float f = __expf(tmax_r[c >> 2] - m_r) * is_r;
        uint32_t* sa = smu + sbase;
        uint32_t* sb = smu + sbase + A_ST;
        const int cu = ahc >> 1;
        uint32_t aw[8] = { ra0.x, ra0.y, ra0.z, ra0.w, ra1.x, ra1.y, ra1.z, ra1.w };
#pragma unroll
        for (int i = 0; i < 8; i++) {
            float2 v = __half22float2(*(__half2*)&aw[i]);
            v.x *= f; v.y *= f;
            __half2 h = __floats2half2_rn(v.x, v.y);
            aw[i] = *(uint32_t*)&h;
        }
        *(uint4*)&sa[ar * 20 + cu]     = make_uint4(aw[0], aw[1], aw[2], aw[3]);
        *(uint4*)&sa[ar * 20 + cu + 4] = make_uint4(aw[4], aw[5], aw[6], aw[7]);
        *(uint4*)&sb[ar * 20 + cu]     = rb0;
        *(uint4*)&sb[ar * 20 + cu + 4] = rb1;
    };

    auto compute = [&](int sbase) {
        const uint32_t aB = smem_base + (uint32_t)sbase * 4;
        const uint32_t bB = smem_base + (uint32_t)(sbase + A_ST) * 4;
#pragma unroll
        for (int kk = 0; kk < 2; kk++) {
            const int kcu = kk * 8;
            uint32_t af[4][4];
#pragma unroll
            for (int mt = 0; mt < 4; mt++) {
                int row = wm + mt * 16 + ((mat & 1) << 3) + (lane & 7);
                int col = kcu + ((mat >> 1) << 2);
                ldm_x4(af[mt], aB + (uint32_t)(row * 20 + col) * 4);
            }
#pragma unroll
            for (int np = 0; np < 2; np++) {
                uint32_t bf[4];
                int row = wn + (2 * np + (mat >> 1)) * 8 + (lane & 7);
                int col = kcu + ((mat & 1) << 2);
                ldm_x4(bf, bB + (uint32_t)(row * 20 + col) * 4);
#pragma unroll
                for (int mt = 0; mt < 4; mt++) {
                    mma16h(acc[mt][2 * np],     af[mt], bf[0], bf[1]);
                    mma16h(acc[mt][2 * np + 1], af[mt], bf[2], bf[3]);
                }
            }
        }
    };

    ldg_chunk(0);
    sts_chunk(0, 0);
    __syncthreads();
    const int NC = SLEN / 32;
    for (int c = 0; c < NC; c++) {
        if (c + 1 < NC) ldg_chunk(c + 1);
        compute((c & 1) * STG);
        if (c + 1 < NC) {
            sts_chunk(c + 1, ((c + 1) & 1) * STG);
            __syncthreads();
        }
    }

#pragma unroll
    for (int mt = 0; mt < 4; mt++) {
        const int r0 = wm + mt * 16 + g;
#pragma unroll
        for (int nt = 0; nt < 4; nt++) {
            const int c0 = wn + nt * 8 + tq * 2;
            *(__half2*)&C[(long)r0 * RKV + c0]       = __floats2half2_rn(acc[mt][nt][0], acc[mt][nt][1]);
            *(__half2*)&C[(long)(r0 + 8) * RKV + c0] = __floats2half2_rn(acc[mt][nt][2], acc[mt][nt][3]);
        }
    }
}

// ---------------- OV GEMM: ao[:, h*128:] = och[h] @ outabsorb[h]^T ----------------
// A: och fp16 [256][512] (exact fp16 => lo term of A is 0). B: f32 [128][512] K-major,
// split to fp16 hi/lo at staging -> 2 mma terms per k16. A via cp.async.
__global__ void __launch_bounds__(256, 2)
ov_gemm(const __half* __restrict__ A, const float* __restrict__ B, float* __restrict__ C,
        long sB)
{
    constexpr int A_ST = 128 * 20;
    constexpr int B_ST = 2 * 128 * 20;   // hi + lo
    constexpr int STG  = A_ST + B_ST;
    constexpr int NC   = RKV / 32;       // 16

    extern __shared__ uint32_t smu[];
    const uint32_t smem_base = smem_u32(smu);

    const int tid  = threadIdx.x;
    const int warp = tid >> 5;
    const int lane = tid & 31;
    const int wm = (warp >> 2) * 64;
    const int wn = (warp & 3) * 32;
    const int g  = lane >> 2;
    const int tq = lane & 3;
    const int mat = lane >> 3;

    const int bm = blockIdx.y * 128;
    const int z  = blockIdx.z;
    A += (long)z * QLEN * RKV + (long)bm * RKV;
    B += (long)z * sB;
    C += (long)z * DNOPE + (long)bm * AO_COLS;

    float acc[4][4][4];
#pragma unroll
    for (int i = 0; i < 4; i++)
#pragma unroll
        for (int j = 0; j < 4; j++)
#pragma unroll
            for (int l = 0; l < 4; l++) acc[i][j][l] = 0.f;

    float4 rB[4];

    auto cpA_chunk = [&](int c, int stg) {
        const uint32_t sa = smem_base + (uint32_t)(stg * STG) * 4;
        const __half* ga = A + c * 32;
#pragma unroll
        for (int i = 0; i < 2; i++) {
            int o = tid + i * 256;
            int r = o >> 2, cu = (o & 3) * 4;
            cp16(sa + (uint32_t)(r * 20 + cu) * 4, ga + (long)r * RKV + cu * 2);
        }
    };

    auto ldgB_chunk = [&](int c) {
        const float* gb = B + c * 32;
#pragma unroll
        for (int i = 0; i < 4; i++) {
            int o = tid + i * 256;
            int r = o >> 3, c4 = (o & 7) << 2;
            rB[i] = *(const float4*)(gb + (long)r * RKV + c4);
        }
    };

    auto stsB_chunk = [&](int stg) {
        uint32_t* sbh = smu + stg * STG + A_ST;
        uint32_t* sbl = sbh + 128 * 20;
#pragma unroll
        for (int i = 0; i < 4; i++) {
            int o = tid + i * 256;
            int r = o >> 3, cu = (o & 7) << 1;
            float4 v = rB[i];
            __half2 h0 = __floats2half2_rn(v.x, v.y);
            __half2 h1 = __floats2half2_rn(v.z, v.w);
            __half2 l0 = __floats2half2_rn(v.x - __half2float(h0.x), v.y - __half2float(h0.y));
            __half2 l1 = __floats2half2_rn(v.z - __half2float(h1.x), v.w - __half2float(h1.y));
            *(uint2*)&sbh[r * 20 + cu] = make_uint2(*(uint32_t*)&h0, *(uint32_t*)&h1);
            *(uint2*)&sbl[r * 20 + cu] = make_uint2(*(uint32_t*)&l0, *(uint32_t*)&l1);
        }
    };

    auto compute = [&](int stg) {
        const uint32_t aB  = smem_base + (uint32_t)(stg * STG) * 4;
        const uint32_t bBh = aB + A_ST * 4;
        const uint32_t bBl = bBh + 128 * 20 * 4;
#pragma unroll
        for (int kk = 0; kk < 2; kk++) {
            const int kcu = kk * 8;
            uint32_t af[4][4];
#pragma unroll
            for (int mt = 0; mt < 4; mt++) {
                int row = wm + mt * 16 + ((mat & 1) << 3) + (lane & 7);
                int col = kcu + ((mat >> 1) << 2);
                ldm_x4(af[mt], aB + (uint32_t)(row * 20 + col) * 4);
            }
#pragma unroll
            for (int np = 0; np < 2; np++) {
                uint32_t bh[4], bl[4];
                int row = wn + (2 * np + (mat >> 1)) * 8 + (lane & 7);
                int col = kcu + ((mat & 1) << 2);
                ldm_x4(bh, bBh + (uint32_t)(row * 20 + col) * 4);
                ldm_x4(bl, bBl + (uint32_t)(row * 20 + col) * 4);
#pragma unroll
                for (int mt = 0; mt < 4; mt++) {
                    mma16h(acc[mt][2 * np],     af[mt], bh[0], bh[1]);
                    mma16h(acc[mt][2 * np],     af[mt], bl[0], bl[1]);
                    mma16h(acc[mt][2 * np + 1], af[mt], bh[2], bh[3]);
                    mma16h(acc[mt][2 * np + 1], af[mt], bl[2], bl[3]);
                }
            }
        }
    };

    ldgB_chunk(0);
    cpA_chunk(0, 0); CP_COMMIT();
    stsB_chunk(0);
    CP_WAIT(0);
    __syncthreads();
    for (int c = 0; c < NC; c++) {
        if (c + 1 < NC) { ldgB_chunk(c + 1); cpA_chunk(c + 1, (c + 1) & 1); }
        CP_COMMIT();
        compute(c & 1);
        if (c + 1 < NC) {
            stsB_chunk((c + 1) & 1);
            CP_WAIT(0);
            __syncthreads();
        }
    }

#pragma unroll
    for (int mt = 0; mt < 4; mt++) {
        const int r0 = wm + mt * 16 + g;
#pragma unroll
        for (int nt = 0; nt < 4; nt++) {
            const int c0 = wn + nt * 8 + tq * 2;
            *(float2*)&C[(long)r0 * AO_COLS + c0]       = make_float2(acc[mt][nt][0], acc[mt][nt][1]);
            *(float2*)&C[(long)(r0 + 8) * AO_COLS + c0] = make_float2(acc[mt][nt][2], acc[mt][nt][3]);
        }
    }
}

// ---------------- Combine tile stats ----------------
__global__ void combine_stats(const float* __restrict__ tmax, const float* __restrict__ tsum,
                              float* __restrict__ rm, float* __restrict__ ris)
{
    const int row = blockIdx.x * 8 + threadIdx.y;
    const int t = threadIdx.x;
    float mv = tmax[(long)row * NTILES_S + t];
    float m = mv;
#pragma unroll
    for (int o = 16; o > 0; o >>= 1) m = fmaxf(m, __shfl_xor_sync(0xffffffffu, m, o));
    float s = tsum[(long)row * NTILES_S + t] * __expf(mv - m);
#pragma unroll
    for (int o = 16; o > 0; o >>= 1) s += __shfl_xor_sync(0xffffffffu, s, o);
    if (t == 0) { rm[row] = m; ris[row] = 1.f / s; }
}

// ---------------- Transpose half->half ----------------
__global__ void transpose_hh(const __half* __restrict__ in, __half* __restrict__ out,
                             int R, int ldin)
{
    __shared__ __half t[32][40];
    const int c0 = blockIdx.x * 32, r0 = blockIdx.y * 32;
    const int x = threadIdx.x, y0 = threadIdx.y;
    #pragma unroll
    for (int i = y0; i < 32; i += 8) t[i][x] = in[(long)(r0 + i) * ldin + c0 + x];
    __syncthreads();
    #pragma unroll
    for (int i = y0; i < 32; i += 8) out[(long)(c0 + i) * R + r0 + x] = t[x][i];
}

// ---------------- Split-K reduction ----------------
__global__ void reduce_slices(const float4* __restrict__ in, float4* __restrict__ out,
                              int n4, int S)
{
    int i = blockIdx.x * 256 + threadIdx.x;
    if (i >= n4) return;
    float4 a = in[i];
    for (int s = 1; s < S; s++) {
        float4 b = in[i + (long)s * n4];
        a.x += b.x; a.y += b.y; a.z += b.z; a.w += b.w;
    }
    out[i] = a;
}

// ---------------- RMSNorm (in place) ----------------
__global__ void rmsnorm_rows(float* __restrict__ X, const float* __restrict__ g, int cols)
{
    const long row = blockIdx.x;
    float* x = X + row * (long)cols;
    const int tid = threadIdx.x;
    const int n4 = cols >> 2;
    float ss = 0.f;
    for (int c = tid; c < n4; c += blockDim.x) {
        float4 v = ((const float4*)x)[c];
        ss += v.x * v.x + v.y * v.y + v.z * v.z + v.w * v.w;
    }
    __shared__ float red[256];
    red[tid] = ss; __syncthreads();
    for (int s = 128; s > 0; s >>= 1) { if (tid < s) red[tid] += red[tid + s]; __syncthreads(); }
    const float inv = rsqrtf(red[0] / (float)cols + EPSF);
    for (int c = tid; c < n4; c += blockDim.x) {
        float4 v = ((const float4*)x)[c];
        float4 w = ((const float4*)g)[c];
        v.x *= inv * w.x; v.y *= inv * w.y; v.z *= inv * w.z; v.w *= inv * w.w;
        ((float4*)x)[c] = v;
    }
}

// ---------------- Build K_comb -> fp16 ----------------
__global__ void build_K(const float* __restrict__ raw, const float* __restrict__ g,
                        const int* __restrict__ kvpos, __half* __restrict__ Kh)
{
    const int s = blockIdx.x;
    const float* r = raw + (long)s * DQK;
    __half* k = Kh + (long)s * DQK;
    const int tid = threadIdx.x;

    float ss = 0.f;
    for (int c = tid; c < RKV / 4; c += 128) {
        float4 v = ((const float4*)r)[c];
        ss += v.x * v.x + v.y * v.y + v.z * v.z + v.w * v.w;
    }
    __shared__ float red[128];
    red[tid] = ss; __syncthreads();
    for (int st = 64; st > 0; st >>= 1) { if (tid < st) red[tid] += red[tid + st]; __syncthreads(); }
    const float inv = rsqrtf(red[0] / (float)RKV + EPSF);
    for (int c = tid; c < RKV / 4; c += 128) {
        float4 v = ((const float4*)r)[c];
        float4 w = ((const float4*)g)[c];
        __half2 h0 = __floats2half2_rn(v.x * inv * w.x, v.y * inv * w.y);
        __half2 h1 = __floats2half2_rn(v.z * inv * w.z, v.w * inv * w.w);
        *(__half2*)&k[c * 4]     = h0;
        *(__half2*)&k[c * 4 + 2] = h1;
    }

    if (tid < 32) {
        const int j = tid;
        const float x0 = r[RKV + 2 * j];
        const float x1 = r[RKV + 2 * j + 1];
        const float pos = (float)kvpos[s];
        const float invf = powf(10000.f, -(float)j / 32.f);
        float cs, sn; sincosf(pos * invf, &sn, &cs);
        k[RKV + j]      = __float2half_rn(x0 * cs - x1 * sn);
        k[RKV + 32 + j] = __float2half_rn(x0 * sn + x1 * cs);
    }
}

// ---------------- RoPE for q_pe -> fp16 ----------------
__global__ void rope_Q(const float* __restrict__ qfull, const int* __restrict__ qpos,
                       __half* __restrict__ Qh)
{
    const int t = blockIdx.x;
    const int h = blockIdx.y;
    const int j = threadIdx.x;
    const float* src = qfull + (long)t * QB_COLS + h * (DNOPE + DROPE) + DNOPE;
    const float x0 = src[2 * j];
    const float x1 = src[2 * j + 1];
    const float pos = (float)qpos[t];
    const float invf = powf(10000.f, -(float)j / 32.f);
    float cs, sn; sincosf(pos * invf, &sn, &cs);
    __half* dst = Qh + ((long)h * QLEN + t) * DQK + RKV;
    dst[j]      = __float2half_rn(x0 * cs - x1 * sn);
    dst[32 + j] = __float2half_rn(x0 * sn + x1 * cs);
}

// ---------------- Launch ----------------
static inline void* symv(const void* s)
{
    void* p = nullptr;
    cudaGetSymbolAddress(&p, s);
    return p;
}

static inline int smem_b(int NT, bool transb, int prec)
{
    int a = (prec == 0) ? 128 * 36 : 128 * 40;
    int b = transb ? ((prec == 0) ? NT * 32 * 36 : NT * 32 * 40)
                   : 32 * (NT * 32 + 8);
    return 2 * (a + b) * 4;
}
#define SMEM_PV (2 * (128 * 20 + 128 * 20) * 4)
#define SMEM_QK (3 * (128 * 20 + 128 * 20) * 4 + 4096)
#define SMEM_OV (2 * (128 * 20 + 2 * 128 * 20) * 4)

extern "C" void kernel_launch(void* const* d_in, const int* in_sizes, int n_in,
                              void* d_out, int out_size)
{
    const float* hq    = (const float*)d_in[0];
    const float* hkv   = (const float*)d_in[1];
    const float* W_qa  = (const float*)d_in[2];
    const float* gqa   = (const float*)d_in[3];
    const float* W_qb  = (const float*)d_in[4];
    const float* W_kva = (const float*)d_in[5];
    const float* gkva  = (const float*)d_in[6];
    const float* W_kvb = (const float*)d_in[7];
    const float* W_o   = (const float*)d_in[8];
    const int*   qpos  = (const int*)d_in[9];
    const int*   kvpos = (const int*)d_in[10];
    float*       out   = (float*)d_out;

    float*  qa     = (float*) symv(g_qa_buf);
    float*  qfull  = (float*) symv(g_qfull);
    float*  ckvraw = (float*) symv(g_ckvraw);
    __half* Kch    = (__half*)symv(g_Kch);
    __half* ckvTh  = (__half*)symv(g_ckvTh);
    __half* Qch    = (__half*)symv(g_Qch);
    __half* P      = (__half*)symv(g_P);
    __half* och    = (__half*)symv(g_och);
    float*  ao     = (float*) symv(g_ao);
    float*  part   = (float*) symv(g_part);
    float*  rowm   = (float*) symv(g_rowm);
    float*  rowis  = (float*) symv(g_rowis);
    float*  tmax   = (float*) symv(g_tmax);
    float*  tsum   = (float*) symv(g_tsum);

    const float scale = 1.0f / sqrtf(192.0f);

    static cudaStream_t s2 = nullptr, s3 = nullptr;
    static cudaEvent_t evF = nullptr, evKV = nullptr, evQF = nullptr, evG1 = nullptr;
    if (!s2) {
        cudaStreamCreateWithFlags(&s2, cudaStreamNonBlocking);
        cudaStreamCreateWithFlags(&s3, cudaStreamNonBlocking);
        cudaEventCreateWithFlags(&evF,  cudaEventDisableTiming);
        cudaEventCreateWithFlags(&evKV, cudaEventDisableTiming);
        cudaEventCreateWithFlags(&evQF, cudaEventDisableTiming);
        cudaEventCreateWithFlags(&evG1, cudaEventDisableTiming);
        cudaFuncSetAttribute(mma_gemm<4, false, 1, 0>, cudaFuncAttributeMaxDynamicSharedMemorySize, smem_b(4, false, 1));
        cudaFuncSetAttribute(mma_gemm<4, false, 1, 1>, cudaFuncAttributeMaxDynamicSharedMemorySize, smem_b(4, false, 1));
        cudaFuncSetAttribute(mma_gemm<3, false, 1, 0>, cudaFuncAttributeMaxDynamicSharedMemorySize, smem_b(3, false, 1));
        cudaFuncSetAttribute(qk_gemm, cudaFuncAttributeMaxDynamicSharedMemorySize, SMEM_QK);
        cudaFuncSetAttribute(pv_gemm, cudaFuncAttributeMaxDynamicSharedMemorySize, SMEM_PV);
        cudaFuncSetAttribute(ov_gemm, cudaFuncAttributeMaxDynamicSharedMemorySize, SMEM_OV);
    }

    // ---- fork: KV path on s2 ----
    cudaEventRecord(evF, 0);
    cudaStreamWaitEvent(s2, evF, 0);

    mma_gemm<3, false, 1, 0><<<dim3(DQK / 96, SLEN / 128, 1), 256, smem_b(3, false, 1), s2>>>(
        hkv, W_kva, ckvraw, HID, HID, DQK, DQK, 0, 0, 0);
    build_K<<<SLEN, 128, 0, s2>>>(ckvraw, gkva, kvpos, Kch);
    transpose_hh<<<dim3(RKV / 32, SLEN / 32), dim3(32, 8), 0, s2>>>(Kch, ckvTh, SLEN, DQK);
    cudaEventRecord(evKV, s2);

    // ---- Q path on default stream ----
    mma_gemm<4, false, 1, 0><<<dim3(RQ / 128, 2, 8), 256, smem_b(4, false, 1)>>>(
        hq, W_qa, part, HID / 8, HID, RQ, RQ,
        (long)(HID / 8), (long)(HID / 8) * RQ, (long)QLEN * RQ);
    reduce_slices<<<(QLEN * RQ / 4 + 255) / 256, 256>>>((const float4*)part, (float4*)qa, QLEN * RQ / 4, 8);
    rmsnorm_rows<<<QLEN, 256>>>(qa, gqa, RQ);
    mma_gemm<4, false, 1, 0><<<dim3(QB_COLS / 128, 2, 1), 256, smem_b(4, false, 1)>>>(
        qa, W_qb, qfull, RQ, RQ, QB_COLS, QB_COLS, 0, 0, 0);
    cudaEventRecord(evQF, 0);
    cudaStreamWaitEvent(s3, evQF, 0);

    // ---- per-head-group attention chains (g0 on stream 0, g1 on s3) ----
    const long zb[2] = { 0, HGRP };
    cudaStream_t gs[2] = { (cudaStream_t)0, s3 };
    for (int grp = 0; grp < 2; grp++) {
        cudaStream_t st = gs[grp];
        const long z0 = zb[grp];
        const long qko = z0 * QLEN * DQK;       // Qch offset (half)
        const long po  = z0 * QLEN * SLEN;      // P offset (half)
        const long to  = z0 * QLEN * NTILES_S;  // tile stats offset
        const long ro  = z0 * QLEN;             // row stats offset
        const long oo  = z0 * QLEN * RKV;       // och offset

        // 6) Qch[:, :512] = q_nope @ q_absorb  [NN bf16x3, fp16 out]
        mma_gemm<4, false, 1, 1><<<dim3(RKV / 128, 2, HGRP), 256, smem_b(4, false, 1), st>>>(
            qfull + z0 * (DNOPE + DROPE), W_kvb + z0 * (long)(DNOPE + DNOPE) * RKV,
            (float*)(Qch + qko), DNOPE,
            QB_COLS, RKV, DQK,
            (long)(DNOPE + DROPE), (long)(DNOPE + DNOPE) * RKV, (long)QLEN * DQK);

        // 7) rope q_pe
        rope_Q<<<dim3(QLEN, HGRP), 32, 0, st>>>(
            qfull + z0 * (DNOPE + DROPE), qpos, Qch + qko);

        cudaStreamWaitEvent(st, evKV, 0);

        // 8) qk (cp.async 3-stage)
        qk_gemm<<<dim3(SLEN / 128, QLEN / 128, HGRP), 256, SMEM_QK, st>>>(
            Qch + qko, Kch, P + po, scale, tmax + to, tsum + to);

        // 9) combine
        combine_stats<<<HGRP * QLEN / 8, dim3(32, 8), 0, st>>>(
            tmax + to, tsum + to, rowm + ro, rowis + ro);

        // 10) pv (fp16 out)
        pv_gemm<<<dim3(RKV / 128, QLEN / 128, HGRP), 256, SMEM_PV, st>>>(
            P + po, ckvTh, och + oo, tmax + to, rowm + ro, rowis + ro);

        // 11) ov: ao[:, h*128:] = och[h] @ outabsorb[h]^T
        ov_gemm<<<dim3(1, 2, HGRP), 256, SMEM_OV, st>>>(
            och + oo, W_kvb + (long)DNOPE * RKV + z0 * (long)(DNOPE + DNOPE) * RKV,
            ao + z0 * DNOPE, (long)(DNOPE + DNOPE) * RKV);
    }
    cudaEventRecord(evG1, s3);
    cudaStreamWaitEvent(0, evG1, 0);

    // 12) out = ao @ W_o : split-K 4
    mma_gemm<4, false, 1, 0><<<dim3(HID / 128, 2, 4), 256, smem_b(4, false, 1)>>>(
        ao, W_o, part, AO_COLS / 4, AO_COLS, HID, HID,
        (long)(AO_COLS / 4), (long)(AO_COLS / 4) * HID, (long)QLEN * HID);
    reduce_slices<<<(QLEN * HID / 4 + 255) / 256, 256>>>((const float4*)part, (float4*)out, QLEN * HID / 4, 4);
}

// round 12
// speedup vs baseline: 2.3132x; 1.0651x over previous
#include <cuda_runtime.h>
#include <cuda_fp16.h>
#include <math.h>
#include <stdint.h>

// ---------------- Problem constants ----------------
#define NHEADS   128
#define DNOPE    128
#define DROPE    64
#define DQK      576
#define RKV      512
#define RQ       1536
#define HID      5120
#define QLEN     256
#define SLEN     4096
#define QB_COLS  24576
#define AO_COLS  16384
#define EPSF     1e-6f
#define NTILES_S (SLEN / 128)    // 32
#define HGRP     (NHEADS / 2)    // 64 heads per group

// ---------------- Scratch (device globals) ----------------
__device__ __align__(128) float  g_qa_buf [QLEN * RQ];
__device__ __align__(128) float  g_qfull  [QLEN * QB_COLS];
__device__ __align__(128) float  g_ckvraw [SLEN * DQK];
__device__ __align__(128) __half g_Kch    [SLEN * DQK];
__device__ __align__(128) __half g_ckvTh  [(size_t)RKV * SLEN];
__device__ __align__(128) __half g_Qch    [(size_t)NHEADS * QLEN * DQK];
__device__ __align__(128) __half g_P      [(size_t)NHEADS * QLEN * SLEN];  // 256 MB
__device__ __align__(128) __half g_och    [(size_t)NHEADS * QLEN * RKV];
__device__ __align__(128) float  g_ao     [QLEN * AO_COLS];
__device__ __align__(128) float  g_part   [8 * QLEN * HID];
__device__ __align__(128) float  g_rowm   [NHEADS * QLEN];
__device__ __align__(128) float  g_rowis  [NHEADS * QLEN];
__device__ __align__(128) float  g_tmax   [(size_t)NHEADS * QLEN * NTILES_S];
__device__ __align__(128) float  g_tsum   [(size_t)NHEADS * QLEN * NTILES_S];

// ---------------- helpers ----------------
__device__ __forceinline__ uint32_t smem_u32(const void* p) {
    uint32_t a;
    asm("{ .reg .u64 t; cvta.to.shared.u64 t, %1; cvt.u32.u64 %0, t; }" : "=r"(a) : "l"(p));
    return a;
}
__device__ __forceinline__ uint32_t f2tf(float x) {
    uint32_t r;
    asm("cvt.rna.tf32.f32 %0, %1;" : "=r"(r) : "f"(x));
    return r;
}
__device__ __forceinline__ uint32_t pack_bf16(float lo, float hi) {
    uint32_t r;
    asm("cvt.rn.bf16x2.f32 %0, %1, %2;" : "=r"(r) : "f"(hi), "f"(lo));
    return r;
}
__device__ __forceinline__ float bflo(uint32_t p) { return __uint_as_float(p << 16); }
__device__ __forceinline__ float bfhi(uint32_t p) { return __uint_as_float(p & 0xffff0000u); }

__device__ __forceinline__ void mma8(float* d, const uint32_t* a, uint32_t b0, uint32_t b1) {
    asm volatile(
        "mma.sync.aligned.m16n8k8.row.col.f32.tf32.tf32.f32 "
        "{%0,%1,%2,%3},{%4,%5,%6,%7},{%8,%9},{%0,%1,%2,%3};"
        : "+f"(d[0]), "+f"(d[1]), "+f"(d[2]), "+f"(d[3])
        : "r"(a[0]), "r"(a[1]), "r"(a[2]), "r"(a[3]), "r"(b0), "r"(b1));
}
__device__ __forceinline__ void mma16b(float* d, const uint32_t* a, uint32_t b0, uint32_t b1) {
    asm volatile(
        "mma.sync.aligned.m16n8k16.row.col.f32.bf16.bf16.f32 "
        "{%0,%1,%2,%3},{%4,%5,%6,%7},{%8,%9},{%0,%1,%2,%3};"
        : "+f"(d[0]), "+f"(d[1]), "+f"(d[2]), "+f"(d[3])
        : "r"(a[0]), "r"(a[1]), "r"(a[2]), "r"(a[3]), "r"(b0), "r"(b1));
}
__device__ __forceinline__ void mma16h(float* d, const uint32_t* a, uint32_t b0, uint32_t b1) {
    asm volatile(
        "mma.sync.aligned.m16n8k16.row.col.f32.f16.f16.f32 "
        "{%0,%1,%2,%3},{%4,%5,%6,%7},{%8,%9},{%0,%1,%2,%3};"
        : "+f"(d[0]), "+f"(d[1]), "+f"(d[2]), "+f"(d[3])
        : "r"(a[0]), "r"(a[1]), "r"(a[2]), "r"(a[3]), "r"(b0), "r"(b1));
}
__device__ __forceinline__ void ldm_x4(uint32_t* r, uint32_t addr) {
    asm volatile("ldmatrix.sync.aligned.m8n8.x4.shared.b16 {%0,%1,%2,%3}, [%4];"
                 : "=r"(r[0]), "=r"(r[1]), "=r"(r[2]), "=r"(r[3]) : "r"(addr));
}
__device__ __forceinline__ void cp16(uint32_t dst, const void* src) {
    asm volatile("cp.async.cg.shared.global [%0], [%1], 16;" :: "r"(dst), "l"(src) : "memory");
}
#define CP_COMMIT() asm volatile("cp.async.commit_group;" ::: "memory")
#define CP_WAIT(n)  asm volatile("cp.async.wait_group %0;" :: "n"(n) : "memory")

// ---------------- generic mma.sync GEMM (projections) ----------------
template<int NT, bool TRANSB, int PREC, int HOUT>
__global__ void __launch_bounds__(256, 2)
mma_gemm(const float* __restrict__ A, const float* __restrict__ B, float* __restrict__ C,
         int K, int lda, int ldb, int ldc, long sA, long sB, long sC)
{
    constexpr int BN   = NT * 32;
    constexpr int A_ST = (PREC == 0) ? 128 * 36 : 128 * 20 * 2;
    constexpr int B_ST = TRANSB ? ((PREC == 0) ? BN * 36 : BN * 20 * 2)
                                : ((PREC == 0) ? 32 * (BN + 8) : 16 * (BN + 8) * 2);
    constexpr int STG  = A_ST + B_ST;
    constexpr int BQ   = BN / 4;

    extern __shared__ uint32_t smu[];
    const uint32_t smem_base = smem_u32(smu);

    const int tid  = threadIdx.x;
    const int warp = tid >> 5;
    const int lane = tid & 31;
    const int wm = (warp >> 2) * 64;
    const int wn = (warp & 3) * (BN / 4);
    const int g  = lane >> 2;
    const int tq = lane & 3;

    const int bm = blockIdx.y * 128;
    const int bn = blockIdx.x * BN;
    A += (long)blockIdx.z * sA + (long)bm * lda;
    if (TRANSB) B += (long)blockIdx.z * sB + (long)bn * ldb;
    else        B += (long)blockIdx.z * sB + bn;
    const long coff = (long)blockIdx.z * sC + (long)bm * ldc + bn;

    const int NC = K >> 5;

    float acc[4][NT][4];
#pragma unroll
    for (int i = 0; i < 4; i++)
#pragma unroll
        for (int j = 0; j < NT; j++)
#pragma unroll
            for (int l = 0; l < 4; l++) acc[i][j][l] = 0.f;

    float4 rA[4];
    float4 rB[4];

    auto ldg_chunk = [&](int c) {
        const float* ga = A + c * 32;
#pragma unroll
        for (int i = 0; i < 4; i++) {
            int idx = tid + i * 256;
            int r = idx >> 3, c4 = (idx & 7) << 2;
            rA[i] = *(const float4*)(ga + (long)r * lda + c4);
        }
        if (TRANSB) {
            const float* gb = B + c * 32;
#pragma unroll
            for (int i = 0; i < NT; i++) {
                int idx = tid + i * 256;
                int r = idx >> 3, c4 = (idx & 7) << 2;
                rB[i] = *(const float4*)(gb + (long)r * ldb + c4);
            }
        } else if (PREC == 0) {
            const float* gb = B + (long)(c * 32) * ldb;
#pragma unroll
            for (int i = 0; i < NT; i++) {
                int idx = tid + i * 256;
                int r = idx / BQ, c4 = (idx % BQ) << 2;
                rB[i] = *(const float4*)(gb + (long)r * ldb + c4);
            }
        } else {
            const float* gb = B + (long)(c * 32) * ldb;
#pragma unroll
            for (int i = 0; i < 2; i++) {
                int u = tid + i * 256;
                if (u < 16 * BQ) {
                    int kp = u / BQ, c4 = (u % BQ) << 2;
                    rB[2 * i]     = *(const float4*)(gb + (long)(2 * kp) * ldb + c4);
                    rB[2 * i + 1] = *(const float4*)(gb + (long)(2 * kp + 1) * ldb + c4);
                }
            }
        }
    };

    auto sts_chunk = [&](int sbase) {
        uint32_t* sa = smu + sbase;
        uint32_t* sb = smu + sbase + A_ST;
        if (PREC == 0) {
#pragma unroll
            for (int i = 0; i < 4; i++) {
                int idx = tid + i * 256;
                int r = idx >> 3, c4 = (idx & 7) << 2;
                float4 v = rA[i];
                uint4 w = { f2tf(v.x), f2tf(v.y), f2tf(v.z), f2tf(v.w) };
                *(uint4*)&sa[r * 36 + c4] = w;
            }
            if (TRANSB) {
#pragma unroll
                for (int i = 0; i < NT; i++) {
                    int idx = tid + i * 256;
                    int r = idx >> 3, c4 = (idx & 7) << 2;
                    uint4 w = { f2tf(rB[i].x), f2tf(rB[i].y), f2tf(rB[i].z), f2tf(rB[i].w) };
                    *(uint4*)&sb[r * 36 + c4] = w;
                }
            } else {
#pragma unroll
                for (int i = 0; i < NT; i++) {
                    int idx = tid + i * 256;
                    int r = idx / BQ, c4 = (idx % BQ) << 2;
                    uint4 w = { f2tf(rB[i].x), f2tf(rB[i].y), f2tf(rB[i].z), f2tf(rB[i].w) };
                    *(uint4*)&sb[r * (BN + 8) + c4] = w;
                }
            }
        } else {
#pragma unroll
            for (int i = 0; i < 4; i++) {
                int idx = tid + i * 256;
                int r = idx >> 3, cu = (idx & 7) << 1;
                float4 v = rA[i];
                uint32_t h0 = pack_bf16(v.x, v.y), h1 = pack_bf16(v.z, v.w);
                uint32_t l0 = pack_bf16(v.x - bflo(h0), v.y - bfhi(h0));
                uint32_t l1 = pack_bf16(v.z - bflo(h1), v.w - bfhi(h1));
                *(uint2*)&sa[r * 20 + cu]            = make_uint2(h0, h1);
                *(uint2*)&sa[128 * 20 + r * 20 + cu] = make_uint2(l0, l1);
            }
            if (TRANSB) {
#pragma unroll
                for (int i = 0; i < NT; i++) {
                    int idx = tid + i * 256;
                    int r = idx >> 3, cu = (idx & 7) << 1;
                    float4 v = rB[i];
                    uint32_t h0 = pack_bf16(v.x, v.y), h1 = pack_bf16(v.z, v.w);
                    uint32_t l0 = pack_bf16(v.x - bflo(h0), v.y - bfhi(h0));
                    uint32_t l1 = pack_bf16(v.z - bflo(h1), v.w - bfhi(h1));
                    *(uint2*)&sb[r * 20 + cu]           = make_uint2(h0, h1);
                    *(uint2*)&sb[BN * 20 + r * 20 + cu] = make_uint2(l0, l1);
                }
            } else {
#pragma unroll
                for (int i = 0; i < 2; i++) {
                    int u = tid + i * 256;
                    if (u < 16 * BQ) {
                        int kp = u / BQ, c4 = (u % BQ) << 2;
                        float4 v0 = rB[2 * i], v1 = rB[2 * i + 1];
                        uint4 h = { pack_bf16(v0.x, v1.x), pack_bf16(v0.y, v1.y),
                                    pack_bf16(v0.z, v1.z), pack_bf16(v0.w, v1.w) };
                        uint4 l = { pack_bf16(v0.x - bflo(h.x), v1.x - bfhi(h.x)),
                                    pack_bf16(v0.y - bflo(h.y), v1.y - bfhi(h.y)),
                                    pack_bf16(v0.z - bflo(h.z), v1.z - bfhi(h.z)),
                                    pack_bf16(v0.w - bflo(h.w), v1.w - bfhi(h.w)) };
                        *(uint4*)&sb[kp * (BN + 8) + c4]                 = h;
                        *(uint4*)&sb[16 * (BN + 8) + kp * (BN + 8) + c4] = l;
                    }
                }
            }
        }
    };

    auto compute = [&](int sbase) {
        const uint32_t aB = smem_base + (uint32_t)sbase * 4;
        const uint32_t bB = smem_base + (uint32_t)(sbase + A_ST) * 4;
        const int mat = lane >> 3;
        if (PREC == 0) {
#pragma unroll
            for (int kk = 0; kk < 4; kk++) {
                const int kcu = kk * 8;
                uint32_t af[4][4];
#pragma unroll
                for (int mt = 0; mt < 4; mt++) {
                    int row = wm + mt * 16 + ((mat & 1) << 3) + (lane & 7);
                    int col = kcu + ((mat >> 1) << 2);
                    ldm_x4(af[mt], aB + (uint32_t)(row * 36 + col) * 4);
                }
                if (TRANSB) {
#pragma unroll
                    for (int np = 0; np < NT / 2; np++) {
                        uint32_t bf[4];
                        int row = wn + (2 * np + (mat >> 1)) * 8 + (lane & 7);
                        int col = kcu + ((mat & 1) << 2);
                        ldm_x4(bf, bB + (uint32_t)(row * 36 + col) * 4);
#pragma unroll
                        for (int mt = 0; mt < 4; mt++) {
                            mma8(acc[mt][2 * np],     af[mt], bf[0], bf[1]);
                            mma8(acc[mt][2 * np + 1], af[mt], bf[2], bf[3]);
                        }
                    }
                } else {
                    const uint32_t* sb = smu + sbase + A_ST;
#pragma unroll
                    for (int nt = 0; nt < NT; nt++) {
                        int n0 = wn + nt * 8 + g;
                        uint32_t b0 = sb[(kcu + tq) * (BN + 8) + n0];
                        uint32_t b1 = sb[(kcu + tq + 4) * (BN + 8) + n0];
#pragma unroll
                        for (int mt = 0; mt < 4; mt++)
                            mma8(acc[mt][nt], af[mt], b0, b1);
                    }
                }
            }
        } else {
#pragma unroll
            for (int kk = 0; kk < 2; kk++) {
                const int kcu = kk * 8;
                uint32_t ah[4][4], al[4][4];
#pragma unroll
                for (int mt = 0; mt < 4; mt++) {
                    int row = wm + mt * 16 + ((mat & 1) << 3) + (lane & 7);
                    int col = kcu + ((mat >> 1) << 2);
                    ldm_x4(ah[mt], aB + (uint32_t)(row * 20 + col) * 4);
                    ldm_x4(al[mt], aB + (uint32_t)(128 * 20 + row * 20 + col) * 4);
                }
                if (TRANSB) {
#pragma unroll
                    for (int np = 0; np < NT / 2; np++) {
                        uint32_t bh[4], bl[4];
                        int row = wn + (2 * np + (mat >> 1)) * 8 + (lane & 7);
                        int col = kcu + ((mat & 1) << 2);
                        ldm_x4(bh, bB + (uint32_t)(row * 20 + col) * 4);
                        ldm_x4(bl, bB + (uint32_t)(BN * 20 + row * 20 + col) * 4);
#pragma unroll
                        for (int mt = 0; mt < 4; mt++) {
                            mma16b(acc[mt][2 * np], ah[mt], bh[0], bh[1]);
                            mma16b(acc[mt][2 * np], al[mt], bh[0], bh[1]);
                            mma16b(acc[mt][2 * np], ah[mt], bl[0], bl[1]);
                            mma16b(acc[mt][2 * np + 1], ah[mt], bh[2], bh[3]);
                            mma16b(acc[mt][2 * np + 1], al[mt], bh[2], bh[3]);
                            mma16b(acc[mt][2 * np + 1], ah[mt], bl[2], bl[3]);
                        }
                    }
                } else {
                    const uint32_t* sbh = smu + sbase + A_ST;
                    const uint32_t* sbl = sbh + 16 * (BN + 8);
#pragma unroll
                    for (int nt = 0; nt < NT; nt++) {
                        int n0 = wn + nt * 8 + g;
                        uint32_t b0h = sbh[(kcu + tq) * (BN + 8) + n0];
                        uint32_t b1h = sbh[(kcu + tq + 4) * (BN + 8) + n0];
                        uint32_t b0l = sbl[(kcu + tq) * (BN + 8) + n0];
                        uint32_t b1l = sbl[(kcu + tq + 4) * (BN + 8) + n0];
#pragma unroll
                        for (int mt = 0; mt < 4; mt++) {
                            mma16b(acc[mt][nt], ah[mt], b0h, b1h);
                            mma16b(acc[mt][nt], al[mt], b0h, b1h);
                            mma16b(acc[mt][nt], ah[mt], b0l, b1l);
                        }
                    }
                }
            }
        }
    };

    ldg_chunk(0);
    sts_chunk(0);
    __syncthreads();
    for (int c = 0; c < NC; c++) {
        if (c + 1 < NC) ldg_chunk(c + 1);
        compute((c & 1) * STG);
        if (c + 1 < NC) {
            sts_chunk(((c + 1) & 1) * STG);
            __syncthreads();
        }
    }

    if (!HOUT) {
        float* Cf = C + coff;
#pragma unroll
        for (int mt = 0; mt < 4; mt++) {
            const int r0 = wm + mt * 16 + g;
#pragma unroll
            for (int nt = 0; nt < NT; nt++) {
                const int c0 = wn + nt * 8 + tq * 2;
                *(float2*)&Cf[(long)r0 * ldc + c0]       = make_float2(acc[mt][nt][0], acc[mt][nt][1]);
                *(float2*)&Cf[(long)(r0 + 8) * ldc + c0] = make_float2(acc[mt][nt][2], acc[mt][nt][3]);
            }
        }
    } else {
        __half* Ch = ((__half*)C) + coff;
#pragma unroll
        for (int mt = 0; mt < 4; mt++) {
            const int r0 = wm + mt * 16 + g;
#pragma unroll
            for (int nt = 0; nt < NT; nt++) {
                const int c0 = wn + nt * 8 + tq * 2;
                *(__half2*)&Ch[(long)r0 * ldc + c0]       = __floats2half2_rn(acc[mt][nt][0], acc[mt][nt][1]);
                *(__half2*)&Ch[(long)(r0 + 8) * ldc + c0] = __floats2half2_rn(acc[mt][nt][2], acc[mt][nt][3]);
            }
        }
    }
}

// ---------------- fp16 QK^T GEMM, cp.async 3-stage, fused exp + tile stats ----------------
__global__ void __launch_bounds__(256, 2)
qk_gemm(const __half* __restrict__ A, const __half* __restrict__ B, __half* __restrict__ Ph,
        float escale, float* __restrict__ gtmax, float* __restrict__ gtsum)
{
    constexpr int A_ST = 128 * 20;
    constexpr int B_ST = 128 * 20;
    constexpr int STG  = A_ST + B_ST;
    constexpr int NC   = DQK / 32;   // 18

    extern __shared__ uint32_t smu[];
    const uint32_t smem_base = smem_u32(smu);

    const int tid  = threadIdx.x;
    const int warp = tid >> 5;
    const int lane = tid & 31;
    const int wm = (warp >> 2) * 64;
    const int wn = (warp & 3) * 32;
    const int g  = lane >> 2;
    const int tq = lane & 3;
    const int mat = lane >> 3;

    const int bm = blockIdx.y * 128;
    const int bn = blockIdx.x * 128;
    const int z  = blockIdx.z;
    A  += (long)z * QLEN * DQK + (long)bm * DQK;
    B  += (long)bn * DQK;
    Ph += (long)z * QLEN * SLEN + (long)bm * SLEN + bn;

    float acc[4][4][4];
#pragma unroll
    for (int i = 0; i < 4; i++)
#pragma unroll
        for (int j = 0; j < 4; j++)
#pragma unroll
            for (int l = 0; l < 4; l++) acc[i][j][l] = 0.f;

    auto cp_chunk = [&](int c, int stg) {
        const uint32_t sa = smem_base + (uint32_t)(stg * STG) * 4;
        const uint32_t sb = sa + A_ST * 4;
        const __half* ga = A + c * 32;
        const __half* gb = B + c * 32;
#pragma unroll
        for (int i = 0; i < 2; i++) {
            int o = tid + i * 256;
            int r = o >> 2, cu = (o & 3) * 4;
            cp16(sa + (uint32_t)(r * 20 + cu) * 4, ga + (long)r * DQK + cu * 2);
            cp16(sb + (uint32_t)(r * 20 + cu) * 4, gb + (long)r * DQK + cu * 2);
        }
    };

    auto compute = [&](int stg) {
        const uint32_t aB = smem_base + (uint32_t)(stg * STG) * 4;
        const uint32_t bB = aB + A_ST * 4;
#pragma unroll
        for (int kk = 0; kk < 2; kk++) {
            const int kcu = kk * 8;
            uint32_t af[4][4];
#pragma unroll
            for (int mt = 0; mt < 4; mt++) {
                int row = wm + mt * 16 + ((mat & 1) << 3) + (lane & 7);
                int col = kcu + ((mat >> 1) << 2);
                ldm_x4(af[mt], aB + (uint32_t)(row * 20 + col) * 4);
            }
#pragma unroll
            for (int np = 0; np < 2; np++) {
                uint32_t bf[4];
                int row = wn + (2 * np + (mat >> 1)) * 8 + (lane & 7);
                int col = kcu + ((mat & 1) << 2);
                ldm_x4(bf, bB + (uint32_t)(row * 20 + col) * 4);
#pragma unroll
                for (int mt = 0; mt < 4; mt++) {
                    mma16h(acc[mt][2 * np],     af[mt], bf[0], bf[1]);
                    mma16h(acc[mt][2 * np + 1], af[mt], bf[2], bf[3]);
                }
            }
        }
    };

    cp_chunk(0, 0); CP_COMMIT();
    cp_chunk(1, 1); CP_COMMIT();
    for (int c = 0; c < NC; c++) {
        CP_WAIT(1);
        __syncthreads();
        if (c + 2 < NC) cp_chunk(c + 2, (c + 2) % 3);
        CP_COMMIT();
        compute(c % 3);
    }

    float* st_max = (float*)(smu + 3 * STG);
    float* st_sum = st_max + 512;
    const int nw = warp & 3;
    __syncthreads();
#pragma unroll
    for (int mt = 0; mt < 4; mt++) {
#pragma unroll
        for (int h = 0; h < 2; h++) {
            float mx = -INFINITY;
#pragma unroll
            for (int nt = 0; nt < 4; nt++) {
                mx = fmaxf(mx, acc[mt][nt][2 * h]);
                mx = fmaxf(mx, acc[mt][nt][2 * h + 1]);
            }
            mx = fmaxf(mx, __shfl_xor_sync(0xffffffffu, mx, 1));
            mx = fmaxf(mx, __shfl_xor_sync(0xffffffffu, mx, 2));
            if (tq == 0) st_max[(wm + mt * 16 + h * 8 + g) * 4 + nw] = mx * escale;
        }
    }
    __syncthreads();
#pragma unroll
    for (int mt = 0; mt < 4; mt++) {
#pragma unroll
        for (int h = 0; h < 2; h++) {
            const int row = wm + mt * 16 + h * 8 + g;
            float rm = fmaxf(fmaxf(st_max[row * 4 + 0], st_max[row * 4 + 1]),
                             fmaxf(st_max[row * 4 + 2], st_max[row * 4 + 3]));
            float s = 0.f;
#pragma unroll
            for (int nt = 0; nt < 4; nt++) {
                float p0 = __expf(fmaf(acc[mt][nt][2 * h],     escale, -rm));
                float p1 = __expf(fmaf(acc[mt][nt][2 * h + 1], escale, -rm));
                s += p0 + p1;
                *(__half2*)&Ph[(long)row * SLEN + wn + nt * 8 + tq * 2] =
                    __floats2half2_rn(p0, p1);
            }
            s += __shfl_xor_sync(0xffffffffu, s, 1);
            s += __shfl_xor_sync(0xffffffffu, s, 2);
            if (tq == 0) st_sum[row * 4 + nw] = s;
        }
    }
    __syncthreads();
    if (tid < 128) {
        float m = fmaxf(fmaxf(st_max[tid * 4 + 0], st_max[tid * 4 + 1]),
                        fmaxf(st_max[tid * 4 + 2], st_max[tid * 4 + 3]));
        float s = st_sum[tid * 4 + 0] + st_sum[tid * 4 + 1]
                + st_sum[tid * 4 + 2] + st_sum[tid * 4 + 3];
        long grow = (long)z * QLEN + bm + tid;
        gtmax[grow * NTILES_S + blockIdx.x] = m;
        gtsum[grow * NTILES_S + blockIdx.x] = s;
    }
}

// ---------------- fp16 PV GEMM, cp.async 3-stage, in-register rescale ----------------
__global__ void __launch_bounds__(256, 2)
pv_gemm(const __half* __restrict__ A, const __half* __restrict__ B, __half* __restrict__ C,
        const float* __restrict__ tmax, const float* __restrict__ rowm,
        const float* __restrict__ rowis)
{
    constexpr int A_ST = 128 * 20;
    constexpr int B_ST = 128 * 20;
    constexpr int STG  = A_ST + B_ST;
    constexpr int NC   = SLEN / 32;   // 128

    extern __shared__ uint32_t smu[];
    const uint32_t smem_base = smem_u32(smu);

    const int tid  = threadIdx.x;
    const int warp = tid >> 5;
    const int lane = tid & 31;
    const int wm = (warp >> 2) * 64;
    const int wn = (warp & 3) * 32;
    const int g  = lane >> 2;
    const int tq = lane & 3;
    const int mat = lane >> 3;

    const int bm = blockIdx.y * 128;
    const int bn = blockIdx.x * 128;
    const int z  = blockIdx.z;
    A += (long)z * QLEN * SLEN + (long)bm * SLEN;
    B += (long)bn * SLEN;
    C += (long)z * QLEN * RKV + (long)bm * RKV + bn;

    // per-thread row stats for its 8 accumulator rows
    const long gbase = (long)z * QLEN + bm;
    float rm_[4][2], ris_[4][2];
#pragma unroll
    for (int mt = 0; mt < 4; mt++) {
        int r0 = wm + mt * 16 + g;
        rm_[mt][0]  = rowm[gbase + r0];
        rm_[mt][1]  = rowm[gbase + r0 + 8];
        ris_[mt][0] = rowis[gbase + r0];
        ris_[mt][1] = rowis[gbase + r0 + 8];
    }
    const float* tmax_b = tmax + gbase * NTILES_S;

    float acc[4][4][4];
#pragma unroll
    for (int i = 0; i < 4; i++)
#pragma unroll
        for (int j = 0; j < 4; j++)
#pragma unroll
            for (int l = 0; l < 4; l++) acc[i][j][l] = 0.f;

    uint32_t fac[4][2];   // half2-packed rescale factors per mt, rows {r0, r0+8}

    auto upd_fac = [&](int tile) {
#pragma unroll
        for (int mt = 0; mt < 4; mt++) {
            int r0 = wm + mt * 16 + g;
            float f0 = __expf(tmax_b[(long)r0 * NTILES_S + tile] - rm_[mt][0]) * ris_[mt][0];
            float f1 = __expf(tmax_b[(long)(r0 + 8) * NTILES_S + tile] - rm_[mt][1]) * ris_[mt][1];
            __half2 h0 = __half2half2(__float2half_rn(f0));
            __half2 h1 = __half2half2(__float2half_rn(f1));
            fac[mt][0] = *(uint32_t*)&h0;
            fac[mt][1] = *(uint32_t*)&h1;
        }
    };

    auto cp_chunk = [&](int c, int stg) {
        const uint32_t sa = smem_base + (uint32_t)(stg * STG) * 4;
        const uint32_t sb = sa + A_ST * 4;
        const __half* ga = A + c * 32;
        const __half* gb = B + c * 32;
#pragma unroll
        for (int i = 0; i < 2; i++) {
            int o = tid + i * 256;
            int r = o >> 2, cu = (o & 3) * 4;
            cp16(sa + (uint32_t)(r * 20 + cu) * 4, ga + (long)r * SLEN + cu * 2);
            cp16(sb + (uint32_t)(r * 20 + cu) * 4, gb + (long)r * SLEN + cu * 2);
        }
    };

    auto compute = [&](int stg) {
        const uint32_t aB = smem_base + (uint32_t)(stg * STG) * 4;
        const uint32_t bB = aB + A_ST * 4;
#pragma unroll
        for (int kk = 0; kk < 2; kk++) {
            const int kcu = kk * 8;
            uint32_t af[4][4];
#pragma unroll
            for (int mt = 0; mt < 4; mt++) {
                int row = wm + mt * 16 + ((mat & 1) << 3) + (lane & 7);
                int col = kcu + ((mat >> 1) << 2);
                ldm_x4(af[mt], aB + (uint32_t)(row * 20 + col) * 4);
                // rescale: regs 0/2 -> row g, regs 1/3 -> row g+8
                __half2 f0 = *(__half2*)&fac[mt][0];
                __half2 f1 = *(__half2*)&fac[mt][1];
                *(__half2*)&af[mt][0] = __hmul2(*(__half2*)&af[mt][0], f0);
                *(__half2*)&af[mt][2] = __hmul2(*(__half2*)&af[mt][2], f0);
                *(__half2*)&af[mt][1] = __hmul2(*(__half2*)&af[mt][1], f1);
                *(__half2*)&af[mt][3] = __hmul2(*(__half2*)&af[mt][3], f1);
            }
#pragma unroll
            for (int np = 0; np < 2; np++) {
                uint32_t bf[4];
                int row = wn + (2 * np + (mat >> 1)) * 8 + (lane & 7);
                int col = kcu + ((mat & 1) << 2);
                ldm_x4(bf, bB + (uint32_t)(row * 20 + col) * 4);
#pragma unroll
                for (int mt = 0; mt < 4; mt++) {
                    mma16h(acc[mt][2 * np],     af[mt], bf[0], bf[1]);
                    mma16h(acc[mt][2 * np + 1], af[mt], bf[2], bf[3]);
                }
            }
        }
    };

    cp_chunk(0, 0); CP_COMMIT();
    cp_chunk(1, 1); CP_COMMIT();
    for (int c = 0; c < NC; c++) {
        CP_WAIT(1);
        __syncthreads();
        if (c + 2 < NC) cp_chunk(c + 2, (c + 2) % 3);
        CP_COMMIT();
        if ((c & 3) == 0) upd_fac(c >> 2);
        compute(c % 3);
    }

#pragma unroll
    for (int mt = 0; mt < 4; mt++) {
        const int r0 = wm + mt * 16 + g;
#pragma unroll
        for (int nt = 0; nt < 4; nt++) {
            const int c0 = wn + nt * 8 + tq * 2;
            *(__half2*)&C[(long)r0 * RKV + c0]       = __floats2half2_rn(acc[mt][nt][0], acc[mt][nt][1]);
            *(__half2*)&C[(long)(r0 + 8) * RKV + c0] = __floats2half2_rn(acc[mt][nt][2], acc[mt][nt][3]);
        }
    }
}

// ---------------- OV GEMM: ao[:, h*128:] = och[h] @ outabsorb[h]^T ----------------
__global__ void __launch_bounds__(256, 2)
ov_gemm(const __half* __restrict__ A, const float* __restrict__ B, float* __restrict__ C,
        long sB)
{
    constexpr int A_ST = 128 * 20;
    constexpr int B_ST = 2 * 128 * 20;
    constexpr int STG  = A_ST + B_ST;
    constexpr int NC   = RKV / 32;

    extern __shared__ uint32_t smu[];
    const uint32_t smem_base = smem_u32(smu);

    const int tid  = threadIdx.x;
    const int warp = tid >> 5;
    const int lane = tid & 31;
    const int wm = (warp >> 2) * 64;
    const int wn = (warp & 3) * 32;
    const int g  = lane >> 2;
    const int tq = lane & 3;
    const int mat = lane >> 3;

    const int bm = blockIdx.y * 128;
    const int z  = blockIdx.z;
    A += (long)z * QLEN * RKV + (long)bm * RKV;
    B += (long)z * sB;
    C += (long)z * DNOPE + (long)bm * AO_COLS;

    float acc[4][4][4];
#pragma unroll
    for (int i = 0; i < 4; i++)
#pragma unroll
        for (int j = 0; j < 4; j++)
#pragma unroll
            for (int l = 0; l < 4; l++) acc[i][j][l] = 0.f;

    float4 rB[4];

    auto cpA_chunk = [&](int c, int stg) {
        const uint32_t sa = smem_base + (uint32_t)(stg * STG) * 4;
        const __half* ga = A + c * 32;
#pragma unroll
        for (int i = 0; i < 2; i++) {
            int o = tid + i * 256;
            int r = o >> 2, cu = (o & 3) * 4;
            cp16(sa + (uint32_t)(r * 20 + cu) * 4, ga + (long)r * RKV + cu * 2);
        }
    };

    auto ldgB_chunk = [&](int c) {
        const float* gb = B + c * 32;
#pragma unroll
        for (int i = 0; i < 4; i++) {
            int o = tid + i * 256;
            int r = o >> 3, c4 = (o & 7) << 2;
            rB[i] = *(const float4*)(gb + (long)r * RKV + c4);
        }
    };

    auto stsB_chunk = [&](int stg) {
        uint32_t* sbh = smu + stg * STG + A_ST;
        uint32_t* sbl = sbh + 128 * 20;
#pragma unroll
        for (int i = 0; i < 4; i++) {
            int o = tid + i * 256;
            int r = o >> 3, cu = (o & 7) << 1;
            float4 v = rB[i];
            __half2 h0 = __floats2half2_rn(v.x, v.y);
            __half2 h1 = __floats2half2_rn(v.z, v.w);
            __half2 l0 = __floats2half2_rn(v.x - __half2float(h0.x), v.y - __half2float(h0.y));
            __half2 l1 = __floats2half2_rn(v.z - __half2float(h1.x), v.w - __half2float(h1.y));
            *(uint2*)&sbh[r * 20 + cu] = make_uint2(*(uint32_t*)&h0, *(uint32_t*)&h1);
            *(uint2*)&sbl[r * 20 + cu] = make_uint2(*(uint32_t*)&l0, *(uint32_t*)&l1);
        }
    };

    auto compute = [&](int stg) {
        const uint32_t aB  = smem_base + (uint32_t)(stg * STG) * 4;
        const uint32_t bBh = aB + A_ST * 4;
        const uint32_t bBl = bBh + 128 * 20 * 4;
#pragma unroll
        for (int kk = 0; kk < 2; kk++) {
            const int kcu = kk * 8;
            uint32_t af[4][4];
#pragma unroll
            for (int mt = 0; mt < 4; mt++) {
                int row = wm + mt * 16 + ((mat & 1) << 3) + (lane & 7);
                int col = kcu + ((mat >> 1) << 2);
                ldm_x4(af[mt], aB + (uint32_t)(row * 20 + col) * 4);
            }
#pragma unroll
            for (int np = 0; np < 2; np++) {
                uint32_t bh[4], bl[4];
                int row = wn + (2 * np + (mat >> 1)) * 8 + (lane & 7);
                int col = kcu + ((mat & 1) << 2);
                ldm_x4(bh, bBh + (uint32_t)(row * 20 + col) * 4);
                ldm_x4(bl, bBl + (uint32_t)(row * 20 + col) * 4);
#pragma unroll
                for (int mt = 0; mt < 4; mt++) {
                    mma16h(acc[mt][2 * np],     af[mt], bh[0], bh[1]);
                    mma16h(acc[mt][2 * np],     af[mt], bl[0], bl[1]);
                    mma16h(acc[mt][2 * np + 1], af[mt], bh[2], bh[3]);
                    mma16h(acc[mt][2 * np + 1], af[mt], bl[2], bl[3]);
                }
            }
        }
    };

    ldgB_chunk(0);
    cpA_chunk(0, 0); CP_COMMIT();
    stsB_chunk(0);
    CP_WAIT(0);
    __syncthreads();
    for (int c = 0; c < NC; c++) {
        if (c + 1 < NC) { ldgB_chunk(c + 1); cpA_chunk(c + 1, (c + 1) & 1); }
        CP_COMMIT();
        compute(c & 1);
        if (c + 1 < NC) {
            stsB_chunk((c + 1) & 1);
            CP_WAIT(0);
            __syncthreads();
        }
    }

#pragma unroll
    for (int mt = 0; mt < 4; mt++) {
        const int r0 = wm + mt * 16 + g;
#pragma unroll
        for (int nt = 0; nt < 4; nt++) {
            const int c0 = wn + nt * 8 + tq * 2;
            *(float2*)&C[(long)r0 * AO_COLS + c0]       = make_float2(acc[mt][nt][0], acc[mt][nt][1]);
            *(float2*)&C[(long)(r0 + 8) * AO_COLS + c0] = make_float2(acc[mt][nt][2], acc[mt][nt][3]);
        }
    }
}

// ---------------- Combine tile stats ----------------
__global__ void combine_stats(const float* __restrict__ tmax, const float* __restrict__ tsum,
                              float* __restrict__ rm, float* __restrict__ ris)
{
    const int row = blockIdx.x * 8 + threadIdx.y;
    const int t = threadIdx.x;
    float mv = tmax[(long)row * NTILES_S + t];
    float m = mv;
#pragma unroll
    for (int o = 16; o > 0; o >>= 1) m = fmaxf(m, __shfl_xor_sync(0xffffffffu, m, o));
    float s = tsum[(long)row * NTILES_S + t] * __expf(mv - m);
#pragma unroll
    for (int o = 16; o > 0; o >>= 1) s += __shfl_xor_sync(0xffffffffu, s, o);
    if (t == 0) { rm[row] = m; ris[row] = 1.f / s; }
}

// ---------------- Transpose half->half ----------------
__global__ void transpose_hh(const __half* __restrict__ in, __half* __restrict__ out,
                             int R, int ldin)
{
    __shared__ __half t[32][40];
    const int c0 = blockIdx.x * 32, r0 = blockIdx.y * 32;
    const int x = threadIdx.x, y0 = threadIdx.y;
    #pragma unroll
    for (int i = y0; i < 32; i += 8) t[i][x] = in[(long)(r0 + i) * ldin + c0 + x];
    __syncthreads();
    #pragma unroll
    for (int i = y0; i < 32; i += 8) out[(long)(c0 + i) * R + r0 + x] = t[x][i];
}

// ---------------- Split-K reduction ----------------
__global__ void reduce_slices(const float4* __restrict__ in, float4* __restrict__ out,
                              int n4, int S)
{
    int i = blockIdx.x * 256 + threadIdx.x;
    if (i >= n4) return;
    float4 a = in[i];
    for (int s = 1; s < S; s++) {
        float4 b = in[i + (long)s * n4];
        a.x += b.x; a.y += b.y; a.z += b.z; a.w += b.w;
    }
    out[i] = a;
}

// ---------------- RMSNorm (in place) ----------------
__global__ void rmsnorm_rows(float* __restrict__ X, const float* __restrict__ g, int cols)
{
    const long row = blockIdx.x;
    float* x = X + row * (long)cols;
    const int tid = threadIdx.x;
    const int n4 = cols >> 2;
    float ss = 0.f;
    for (int c = tid; c < n4; c += blockDim.x) {
        float4 v = ((const float4*)x)[c];
        ss += v.x * v.x + v.y * v.y + v.z * v.z + v.w * v.w;
    }
    __shared__ float red[256];
    red[tid] = ss; __syncthreads();
    for (int s = 128; s > 0; s >>= 1) { if (tid < s) red[tid] += red[tid + s]; __syncthreads(); }
    const float inv = rsqrtf(red[0] / (float)cols + EPSF);
    for (int c = tid; c < n4; c += blockDim.x) {
        float4 v = ((const float4*)x)[c];
        float4 w = ((const float4*)g)[c];
        v.x *= inv * w.x; v.y *= inv * w.y; v.z *= inv * w.z; v.w *= inv * w.w;
        ((float4*)x)[c] = v;
    }
}

// ---------------- Build K_comb -> fp16 ----------------
__global__ void build_K(const float* __restrict__ raw, const float* __restrict__ g,
                        const int* __restrict__ kvpos, __half* __restrict__ Kh)
{
    const int s = blockIdx.x;
    const float* r = raw + (long)s * DQK;
    __half* k = Kh + (long)s * DQK;
    const int tid = threadIdx.x;

    float ss = 0.f;
    for (int c = tid; c < RKV / 4; c += 128) {
        float4 v = ((const float4*)r)[c];
        ss += v.x * v.x + v.y * v.y + v.z * v.z + v.w * v.w;
    }
    __shared__ float red[128];
    red[tid] = ss; __syncthreads();
    for (int st = 64; st > 0; st >>= 1) { if (tid < st) red[tid] += red[tid + st]; __syncthreads(); }
    const float inv = rsqrtf(red[0] / (float)RKV + EPSF);
    for (int c = tid; c < RKV / 4; c += 128) {
        float4 v = ((const float4*)r)[c];
        float4 w = ((const float4*)g)[c];
        __half2 h0 = __floats2half2_rn(v.x * inv * w.x, v.y * inv * w.y);
        __half2 h1 = __floats2half2_rn(v.z * inv * w.z, v.w * inv * w.w);
        *(__half2*)&k[c * 4]     = h0;
        *(__half2*)&k[c * 4 + 2] = h1;
    }

    if (tid < 32) {
        const int j = tid;
        const float x0 = r[RKV + 2 * j];
        const float x1 = r[RKV + 2 * j + 1];
        const float pos = (float)kvpos[s];
        const float invf = powf(10000.f, -(float)j / 32.f);
        float cs, sn; sincosf(pos * invf, &sn, &cs);
        k[RKV + j]      = __float2half_rn(x0 * cs - x1 * sn);
        k[RKV + 32 + j] = __float2half_rn(x0 * sn + x1 * cs);
    }
}

// ---------------- RoPE for q_pe -> fp16 ----------------
__global__ void rope_Q(const float* __restrict__ qfull, const int* __restrict__ qpos,
                       __half* __restrict__ Qh)
{
    const int t = blockIdx.x;
    const int h = blockIdx.y;
    const int j = threadIdx.x;
    const float* src = qfull + (long)t * QB_COLS + h * (DNOPE + DROPE) + DNOPE;
    const float x0 = src[2 * j];
    const float x1 = src[2 * j + 1];
    const float pos = (float)qpos[t];
    const float invf = powf(10000.f, -(float)j / 32.f);
    float cs, sn; sincosf(pos * invf, &sn, &cs);
    __half* dst = Qh + ((long)h * QLEN + t) * DQK + RKV;
    dst[j]      = __float2half_rn(x0 * cs - x1 * sn);
    dst[32 + j] = __float2half_rn(x0 * sn + x1 * cs);
}

// ---------------- Launch ----------------
static inline void* symv(const void* s)
{
    void* p = nullptr;
    cudaGetSymbolAddress(&p, s);
    return p;
}

static inline int smem_b(int NT, bool transb, int prec)
{
    int a = (prec == 0) ? 128 * 36 : 128 * 40;
    int b = transb ? ((prec == 0) ? NT * 32 * 36 : NT * 32 * 40)
                   : 32 * (NT * 32 + 8);
    return 2 * (a + b) * 4;
}
#define SMEM_PV (3 * (128 * 20 + 128 * 20) * 4)
#define SMEM_QK (3 * (128 * 20 + 128 * 20) * 4 + 4096)
#define SMEM_OV (2 * (128 * 20 + 2 * 128 * 20) * 4)

extern "C" void kernel_launch(void* const* d_in, const int* in_sizes, int n_in,
                              void* d_out, int out_size)
{
    const float* hq    = (const float*)d_in[0];
    const float* hkv   = (const float*)d_in[1];
    const float* W_qa  = (const float*)d_in[2];
    const float* gqa   = (const float*)d_in[3];
    const float* W_qb  = (const float*)d_in[4];
    const float* W_kva = (const float*)d_in[5];
    const float* gkva  = (const float*)d_in[6];
    const float* W_kvb = (const float*)d_in[7];
    const float* W_o   = (const float*)d_in[8];
    const int*   qpos  = (const int*)d_in[9];
    const int*   kvpos = (const int*)d_in[10];
    float*       out   = (float*)d_out;

    float*  qa     = (float*) symv(g_qa_buf);
    float*  qfull  = (float*) symv(g_qfull);
    float*  ckvraw = (float*) symv(g_ckvraw);
    __half* Kch    = (__half*)symv(g_Kch);
    __half* ckvTh  = (__half*)symv(g_ckvTh);
    __half* Qch    = (__half*)symv(g_Qch);
    __half* P      = (__half*)symv(g_P);
    __half* och    = (__half*)symv(g_och);
    float*  ao     = (float*) symv(g_ao);
    float*  part   = (float*) symv(g_part);
    float*  rowm   = (float*) symv(g_rowm);
    float*  rowis  = (float*) symv(g_rowis);
    float*  tmax   = (float*) symv(g_tmax);
    float*  tsum   = (float*) symv(g_tsum);

    const float scale = 1.0f / sqrtf(192.0f);

    static cudaStream_t s2 = nullptr, s3 = nullptr;
    static cudaEvent_t evF = nullptr, evKV = nullptr, evQF = nullptr, evG1 = nullptr;
    if (!s2) {
        cudaStreamCreateWithFlags(&s2, cudaStreamNonBlocking);
        cudaStreamCreateWithFlags(&s3, cudaStreamNonBlocking);
        cudaEventCreateWithFlags(&evF,  cudaEventDisableTiming);
        cudaEventCreateWithFlags(&evKV, cudaEventDisableTiming);
        cudaEventCreateWithFlags(&evQF, cudaEventDisableTiming);
        cudaEventCreateWithFlags(&evG1, cudaEventDisableTiming);
        cudaFuncSetAttribute(mma_gemm<4, false, 1, 0>, cudaFuncAttributeMaxDynamicSharedMemorySize, smem_b(4, false, 1));
        cudaFuncSetAttribute(mma_gemm<4, false, 1, 1>, cudaFuncAttributeMaxDynamicSharedMemorySize, smem_b(4, false, 1));
        cudaFuncSetAttribute(mma_gemm<3, false, 1, 0>, cudaFuncAttributeMaxDynamicSharedMemorySize, smem_b(3, false, 1));
        cudaFuncSetAttribute(qk_gemm, cudaFuncAttributeMaxDynamicSharedMemorySize, SMEM_QK);
        cudaFuncSetAttribute(pv_gemm, cudaFuncAttributeMaxDynamicSharedMemorySize, SMEM_PV);
        cudaFuncSetAttribute(ov_gemm, cudaFuncAttributeMaxDynamicSharedMemorySize, SMEM_OV);
    }

    // ---- fork: KV path on s2 ----
    cudaEventRecord(evF, 0);
    cudaStreamWaitEvent(s2, evF, 0);

    mma_gemm<3, false, 1, 0><<<dim3(DQK / 96, SLEN / 128, 1), 256, smem_b(3, false, 1), s2>>>(
        hkv, W_kva, ckvraw, HID, HID, DQK, DQK, 0, 0, 0);
    build_K<<<SLEN, 128, 0, s2>>>(ckvraw, gkva, kvpos, Kch);
    transpose_hh<<<dim3(RKV / 32, SLEN / 32), dim3(32, 8), 0, s2>>>(Kch, ckvTh, SLEN, DQK);
    cudaEventRecord(evKV, s2);

    // ---- Q path on default stream ----
    mma_gemm<4, false, 1, 0><<<dim3(RQ / 128, 2, 8), 256, smem_b(4, false, 1)>>>(
        hq, W_qa, part, HID / 8, HID, RQ, RQ,
        (long)(HID / 8), (long)(HID / 8) * RQ, (long)QLEN * RQ);
    reduce_slices<<<(QLEN * RQ / 4 + 255) / 256, 256>>>((const float4*)part, (float4*)qa, QLEN * RQ / 4, 8);
    rmsnorm_rows<<<QLEN, 256>>>(qa, gqa, RQ);
    mma_gemm<4, false, 1, 0><<<dim3(QB_COLS / 128, 2, 1), 256, smem_b(4, false, 1)>>>(
        qa, W_qb, qfull, RQ, RQ, QB_COLS, QB_COLS, 0, 0, 0);
    cudaEventRecord(evQF, 0);
    cudaStreamWaitEvent(s3, evQF, 0);

    // ---- per-head-group attention chains (g0 on stream 0, g1 on s3) ----
    const long zb[2] = { 0, HGRP };
    cudaStream_t gs[2] = { (cudaStream_t)0, s3 };
    for (int grp = 0; grp < 2; grp++) {
        cudaStream_t st = gs[grp];
        const long z0 = zb[grp];
        const long qko = z0 * QLEN * DQK;
        const long po  = z0 * QLEN * SLEN;
        const long to  = z0 * QLEN * NTILES_S;
        const long ro  = z0 * QLEN;
        const long oo  = z0 * QLEN * RKV;

        // 6) Qch[:, :512] = q_nope @ q_absorb
        mma_gemm<4, false, 1, 1><<<dim3(RKV / 128, 2, HGRP), 256, smem_b(4, false, 1), st>>>(
            qfull + z0 * (DNOPE + DROPE), W_kvb + z0 * (long)(DNOPE + DNOPE) * RKV,
            (float*)(Qch + qko), DNOPE,
            QB_COLS, RKV, DQK,
            (long)(DNOPE + DROPE), (long)(DNOPE + DNOPE) * RKV, (long)QLEN * DQK);

        // 7) rope q_pe
        rope_Q<<<dim3(QLEN, HGRP), 32, 0, st>>>(
            qfull + z0 * (DNOPE + DROPE), qpos, Qch + qko);

        cudaStreamWaitEvent(st, evKV, 0);

        // 8) qk
        qk_gemm<<<dim3(SLEN / 128, QLEN / 128, HGRP), 256, SMEM_QK, st>>>(
            Qch + qko, Kch, P + po, scale, tmax + to, tsum + to);

        // 9) combine
        combine_stats<<<HGRP * QLEN / 8, dim3(32, 8), 0, st>>>(
            tmax + to, tsum + to, rowm + ro, rowis + ro);

        // 10) pv (cp.async + in-register rescale)
        pv_gemm<<<dim3(RKV / 128, QLEN / 128, HGRP), 256, SMEM_PV, st>>>(
            P + po, ckvTh, och + oo, tmax + to, rowm + ro, rowis + ro);

        // 11) ov
        ov_gemm<<<dim3(1, 2, HGRP), 256, SMEM_OV, st>>>(
            och + oo, W_kvb + (long)DNOPE * RKV + z0 * (long)(DNOPE + DNOPE) * RKV,
            ao + z0 * DNOPE, (long)(DNOPE + DNOPE) * RKV);

        // 12a) partial out: ao[:, grp half] @ W_o[grp rows], split-K 2
        mma_gemm<4, false, 1, 0><<<dim3(HID / 128, 2, 2), 256, smem_b(4, false, 1), st>>>(
            ao + z0 * DNOPE, W_o + z0 * DNOPE * (long)HID, part + grp * 2 * (long)QLEN * HID,
            AO_COLS / 4, AO_COLS, HID, HID,
            (long)(AO_COLS / 4), (long)(AO_COLS / 4) * HID, (long)QLEN * HID);
    }
    cudaEventRecord(evG1, s3);
    cudaStreamWaitEvent(0, evG1, 0);

    // 12b) reduce 4 partial slices -> out
    reduce_slices<<<(QLEN * HID / 4 + 255) / 256, 256>>>((const float4*)part, (float4*)out, QLEN * HID / 4, 4);
}

// round 13
// speedup vs baseline: 2.4891x; 1.0760x over previous
#include <cuda_runtime.h>
#include <cuda_fp16.h>
#include <math.h>
#include <stdint.h>

// ---------------- Problem constants ----------------
#define NHEADS   128
#define DNOPE    128
#define DROPE    64
#define DQK      576
#define RKV      512
#define RQ       1536
#define HID      5120
#define QLEN     256
#define SLEN     4096
#define QB_COLS  24576
#define AO_COLS  16384
#define EPSF     1e-6f
#define NTILES_S (SLEN / 128)    // 32
#define HGRP     (NHEADS / 2)    // 64 heads per group

// ---------------- Scratch (device globals) ----------------
__device__ __align__(128) float  g_qa_buf [QLEN * RQ];
__device__ __align__(128) float  g_qfull  [QLEN * QB_COLS];
__device__ __align__(128) float  g_ckvraw [SLEN * DQK];
__device__ __align__(128) __half g_Kch    [SLEN * DQK];
__device__ __align__(128) __half g_ckvTh  [(size_t)RKV * SLEN];
__device__ __align__(128) __half g_Qch    [(size_t)NHEADS * QLEN * DQK];
__device__ __align__(128) __half g_P      [(size_t)NHEADS * QLEN * SLEN];  // 256 MB
__device__ __align__(128) __half g_och    [(size_t)NHEADS * QLEN * RKV];
__device__ __align__(128) float  g_ao     [QLEN * AO_COLS];
__device__ __align__(128) float  g_part   [8 * QLEN * HID];
__device__ __align__(128) float  g_rowm   [NHEADS * QLEN];
__device__ __align__(128) float  g_rowis  [NHEADS * QLEN];
__device__ __align__(128) float  g_tmax   [(size_t)NHEADS * QLEN * NTILES_S];
__device__ __align__(128) float  g_tsum   [(size_t)NHEADS * QLEN * NTILES_S];

// ---------------- helpers ----------------
__device__ __forceinline__ uint32_t smem_u32(const void* p) {
    uint32_t a;
    asm("{ .reg .u64 t; cvta.to.shared.u64 t, %1; cvt.u32.u64 %0, t; }" : "=r"(a) : "l"(p));
    return a;
}
__device__ __forceinline__ uint32_t f2tf(float x) {
    uint32_t r;
    asm("cvt.rna.tf32.f32 %0, %1;" : "=r"(r) : "f"(x));
    return r;
}
__device__ __forceinline__ uint32_t pack_bf16(float lo, float hi) {
    uint32_t r;
    asm("cvt.rn.bf16x2.f32 %0, %1, %2;" : "=r"(r) : "f"(hi), "f"(lo));
    return r;
}
__device__ __forceinline__ float bflo(uint32_t p) { return __uint_as_float(p << 16); }
__device__ __forceinline__ float bfhi(uint32_t p) { return __uint_as_float(p & 0xffff0000u); }

__device__ __forceinline__ void mma8(float* d, const uint32_t* a, uint32_t b0, uint32_t b1) {
    asm volatile(
        "mma.sync.aligned.m16n8k8.row.col.f32.tf32.tf32.f32 "
        "{%0,%1,%2,%3},{%4,%5,%6,%7},{%8,%9},{%0,%1,%2,%3};"
        : "+f"(d[0]), "+f"(d[1]), "+f"(d[2]), "+f"(d[3])
        : "r"(a[0]), "r"(a[1]), "r"(a[2]), "r"(a[3]), "r"(b0), "r"(b1));
}
__device__ __forceinline__ void mma16b(float* d, const uint32_t* a, uint32_t b0, uint32_t b1) {
    asm volatile(
        "mma.sync.aligned.m16n8k16.row.col.f32.bf16.bf16.f32 "
        "{%0,%1,%2,%3},{%4,%5,%6,%7},{%8,%9},{%0,%1,%2,%3};"
        : "+f"(d[0]), "+f"(d[1]), "+f"(d[2]), "+f"(d[3])
        : "r"(a[0]), "r"(a[1]), "r"(a[2]), "r"(a[3]), "r"(b0), "r"(b1));
}
__device__ __forceinline__ void mma16h(float* d, const uint32_t* a, uint32_t b0, uint32_t b1) {
    asm volatile(
        "mma.sync.aligned.m16n8k16.row.col.f32.f16.f16.f32 "
        "{%0,%1,%2,%3},{%4,%5,%6,%7},{%8,%9},{%0,%1,%2,%3};"
        : "+f"(d[0]), "+f"(d[1]), "+f"(d[2]), "+f"(d[3])
        : "r"(a[0]), "r"(a[1]), "r"(a[2]), "r"(a[3]), "r"(b0), "r"(b1));
}
__device__ __forceinline__ void ldm_x4(uint32_t* r, uint32_t addr) {
    asm volatile("ldmatrix.sync.aligned.m8n8.x4.shared.b16 {%0,%1,%2,%3}, [%4];"
                 : "=r"(r[0]), "=r"(r[1]), "=r"(r[2]), "=r"(r[3]) : "r"(addr));
}
__device__ __forceinline__ void cp16(uint32_t dst, const void* src) {
    asm volatile("cp.async.cg.shared.global [%0], [%1], 16;" :: "r"(dst), "l"(src) : "memory");
}
#define CP_COMMIT() asm volatile("cp.async.commit_group;" ::: "memory")
#define CP_WAIT(n)  asm volatile("cp.async.wait_group %0;" :: "n"(n) : "memory")

// ---------------- generic mma.sync GEMM (projections) ----------------
template<int NT, bool TRANSB, int PREC, int HOUT>
__global__ void __launch_bounds__(256, 2)
mma_gemm(const float* __restrict__ A, const float* __restrict__ B, float* __restrict__ C,
         int K, int lda, int ldb, int ldc, long sA, long sB, long sC)
{
    constexpr int BN   = NT * 32;
    constexpr int A_ST = (PREC == 0) ? 128 * 36 : 128 * 20 * 2;
    constexpr int B_ST = TRANSB ? ((PREC == 0) ? BN * 36 : BN * 20 * 2)
                                : ((PREC == 0) ? 32 * (BN + 8) : 16 * (BN + 8) * 2);
    constexpr int STG  = A_ST + B_ST;
    constexpr int BQ   = BN / 4;

    extern __shared__ uint32_t smu[];
    const uint32_t smem_base = smem_u32(smu);

    const int tid  = threadIdx.x;
    const int warp = tid >> 5;
    const int lane = tid & 31;
    const int wm = (warp >> 2) * 64;
    const int wn = (warp & 3) * (BN / 4);
    const int g  = lane >> 2;
    const int tq = lane & 3;

    const int bm = blockIdx.y * 128;
    const int bn = blockIdx.x * BN;
    A += (long)blockIdx.z * sA + (long)bm * lda;
    if (TRANSB) B += (long)blockIdx.z * sB + (long)bn * ldb;
    else        B += (long)blockIdx.z * sB + bn;
    const long coff = (long)blockIdx.z * sC + (long)bm * ldc + bn;

    const int NC = K >> 5;

    float acc[4][NT][4];
#pragma unroll
    for (int i = 0; i < 4; i++)
#pragma unroll
        for (int j = 0; j < NT; j++)
#pragma unroll
            for (int l = 0; l < 4; l++) acc[i][j][l] = 0.f;

    float4 rA[4];
    float4 rB[4];

    auto ldg_chunk = [&](int c) {
        const float* ga = A + c * 32;
#pragma unroll
        for (int i = 0; i < 4; i++) {
            int idx = tid + i * 256;
            int r = idx >> 3, c4 = (idx & 7) << 2;
            rA[i] = *(const float4*)(ga + (long)r * lda + c4);
        }
        if (TRANSB) {
            const float* gb = B + c * 32;
#pragma unroll
            for (int i = 0; i < NT; i++) {
                int idx = tid + i * 256;
                int r = idx >> 3, c4 = (idx & 7) << 2;
                rB[i] = *(const float4*)(gb + (long)r * ldb + c4);
            }
        } else if (PREC == 0) {
            const float* gb = B + (long)(c * 32) * ldb;
#pragma unroll
            for (int i = 0; i < NT; i++) {
                int idx = tid + i * 256;
                int r = idx / BQ, c4 = (idx % BQ) << 2;
                rB[i] = *(const float4*)(gb + (long)r * ldb + c4);
            }
        } else {
            const float* gb = B + (long)(c * 32) * ldb;
#pragma unroll
            for (int i = 0; i < 2; i++) {
                int u = tid + i * 256;
                if (u < 16 * BQ) {
                    int kp = u / BQ, c4 = (u % BQ) << 2;
                    rB[2 * i]     = *(const float4*)(gb + (long)(2 * kp) * ldb + c4);
                    rB[2 * i + 1] = *(const float4*)(gb + (long)(2 * kp + 1) * ldb + c4);
                }
            }
        }
    };

    auto sts_chunk = [&](int sbase) {
        uint32_t* sa = smu + sbase;
        uint32_t* sb = smu + sbase + A_ST;
        if (PREC == 0) {
#pragma unroll
            for (int i = 0; i < 4; i++) {
                int idx = tid + i * 256;
                int r = idx >> 3, c4 = (idx & 7) << 2;
                float4 v = rA[i];
                uint4 w = { f2tf(v.x), f2tf(v.y), f2tf(v.z), f2tf(v.w) };
                *(uint4*)&sa[r * 36 + c4] = w;
            }
            if (TRANSB) {
#pragma unroll
                for (int i = 0; i < NT; i++) {
                    int idx = tid + i * 256;
                    int r = idx >> 3, c4 = (idx & 7) << 2;
                    uint4 w = { f2tf(rB[i].x), f2tf(rB[i].y), f2tf(rB[i].z), f2tf(rB[i].w) };
                    *(uint4*)&sb[r * 36 + c4] = w;
                }
            } else {
#pragma unroll
                for (int i = 0; i < NT; i++) {
                    int idx = tid + i * 256;
                    int r = idx / BQ, c4 = (idx % BQ) << 2;
                    uint4 w = { f2tf(rB[i].x), f2tf(rB[i].y), f2tf(rB[i].z), f2tf(rB[i].w) };
                    *(uint4*)&sb[r * (BN + 8) + c4] = w;
                }
            }
        } else {
#pragma unroll
            for (int i = 0; i < 4; i++) {
                int idx = tid + i * 256;
                int r = idx >> 3, cu = (idx & 7) << 1;
                float4 v = rA[i];
                uint32_t h0 = pack_bf16(v.x, v.y), h1 = pack_bf16(v.z, v.w);
                uint32_t l0 = pack_bf16(v.x - bflo(h0), v.y - bfhi(h0));
                uint32_t l1 = pack_bf16(v.z - bflo(h1), v.w - bfhi(h1));
                *(uint2*)&sa[r * 20 + cu]            = make_uint2(h0, h1);
                *(uint2*)&sa[128 * 20 + r * 20 + cu] = make_uint2(l0, l1);
            }
            if (TRANSB) {
#pragma unroll
                for (int i = 0; i < NT; i++) {
                    int idx = tid + i * 256;
                    int r = idx >> 3, cu = (idx & 7) << 1;
                    float4 v = rB[i];
                    uint32_t h0 = pack_bf16(v.x, v.y), h1 = pack_bf16(v.z, v.w);
                    uint32_t l0 = pack_bf16(v.x - bflo(h0), v.y - bfhi(h0));
                    uint32_t l1 = pack_bf16(v.z - bflo(h1), v.w - bfhi(h1));
                    *(uint2*)&sb[r * 20 + cu]           = make_uint2(h0, h1);
                    *(uint2*)&sb[BN * 20 + r * 20 + cu] = make_uint2(l0, l1);
                }
            } else {
#pragma unroll
                for (int i = 0; i < 2; i++) {
                    int u = tid + i * 256;
                    if (u < 16 * BQ) {
                        int kp = u / BQ, c4 = (u % BQ) << 2;
                        float4 v0 = rB[2 * i], v1 = rB[2 * i + 1];
                        uint4 h = { pack_bf16(v0.x, v1.x), pack_bf16(v0.y, v1.y),
                                    pack_bf16(v0.z, v1.z), pack_bf16(v0.w, v1.w) };
                        uint4 l = { pack_bf16(v0.x - bflo(h.x), v1.x - bfhi(h.x)),
                                    pack_bf16(v0.y - bflo(h.y), v1.y - bfhi(h.y)),
                                    pack_bf16(v0.z - bflo(h.z), v1.z - bfhi(h.z)),
                                    pack_bf16(v0.w - bflo(h.w), v1.w - bfhi(h.w)) };
                        *(uint4*)&sb[kp * (BN + 8) + c4]                 = h;
                        *(uint4*)&sb[16 * (BN + 8) + kp * (BN + 8) + c4] = l;
                    }
                }
            }
        }
    };

    auto compute = [&](int sbase) {
        const uint32_t aB = smem_base + (uint32_t)sbase * 4;
        const uint32_t bB = smem_base + (uint32_t)(sbase + A_ST) * 4;
        const int mat = lane >> 3;
        if (PREC == 0) {
#pragma unroll
            for (int kk = 0; kk < 4; kk++) {
                const int kcu = kk * 8;
                uint32_t af[4][4];
#pragma unroll
                for (int mt = 0; mt < 4; mt++) {
                    int row = wm + mt * 16 + ((mat & 1) << 3) + (lane & 7);
                    int col = kcu + ((mat >> 1) << 2);
                    ldm_x4(af[mt], aB + (uint32_t)(row * 36 + col) * 4);
                }
                if (TRANSB) {
#pragma unroll
                    for (int np = 0; np < NT / 2; np++) {
                        uint32_t bf[4];
                        int row = wn + (2 * np + (mat >> 1)) * 8 + (lane & 7);
                        int col = kcu + ((mat & 1) << 2);
                        ldm_x4(bf, bB + (uint32_t)(row * 36 + col) * 4);
#pragma unroll
                        for (int mt = 0; mt < 4; mt++) {
                            mma8(acc[mt][2 * np],     af[mt], bf[0], bf[1]);
                            mma8(acc[mt][2 * np + 1], af[mt], bf[2], bf[3]);
                        }
                    }
                } else {
                    const uint32_t* sb = smu + sbase + A_ST;
#pragma unroll
                    for (int nt = 0; nt < NT; nt++) {
                        int n0 = wn + nt * 8 + g;
                        uint32_t b0 = sb[(kcu + tq) * (BN + 8) + n0];
                        uint32_t b1 = sb[(kcu + tq + 4) * (BN + 8) + n0];
#pragma unroll
                        for (int mt = 0; mt < 4; mt++)
                            mma8(acc[mt][nt], af[mt], b0, b1);
                    }
                }
            }
        } else {
#pragma unroll
            for (int kk = 0; kk < 2; kk++) {
                const int kcu = kk * 8;
                uint32_t ah[4][4], al[4][4];
#pragma unroll
                for (int mt = 0; mt < 4; mt++) {
                    int row = wm + mt * 16 + ((mat & 1) << 3) + (lane & 7);
                    int col = kcu + ((mat >> 1) << 2);
                    ldm_x4(ah[mt], aB + (uint32_t)(row * 20 + col) * 4);
                    ldm_x4(al[mt], aB + (uint32_t)(128 * 20 + row * 20 + col) * 4);
                }
                if (TRANSB) {
#pragma unroll
                    for (int np = 0; np < NT / 2; np++) {
                        uint32_t bh[4], bl[4];
                        int row = wn + (2 * np + (mat >> 1)) * 8 + (lane & 7);
                        int col = kcu + ((mat & 1) << 2);
                        ldm_x4(bh, bB + (uint32_t)(row * 20 + col) * 4);
                        ldm_x4(bl, bB + (uint32_t)(BN * 20 + row * 20 + col) * 4);
#pragma unroll
                        for (int mt = 0; mt < 4; mt++) {
                            mma16b(acc[mt][2 * np], ah[mt], bh[0], bh[1]);
                            mma16b(acc[mt][2 * np], al[mt], bh[0], bh[1]);
                            mma16b(acc[mt][2 * np], ah[mt], bl[0], bl[1]);
                            mma16b(acc[mt][2 * np + 1], ah[mt], bh[2], bh[3]);
                            mma16b(acc[mt][2 * np + 1], al[mt], bh[2], bh[3]);
                            mma16b(acc[mt][2 * np + 1], ah[mt], bl[2], bl[3]);
                        }
                    }
                } else {
                    const uint32_t* sbh = smu + sbase + A_ST;
                    const uint32_t* sbl = sbh + 16 * (BN + 8);
#pragma unroll
                    for (int nt = 0; nt < NT; nt++) {
                        int n0 = wn + nt * 8 + g;
                        uint32_t b0h = sbh[(kcu + tq) * (BN + 8) + n0];
                        uint32_t b1h = sbh[(kcu + tq + 4) * (BN + 8) + n0];
                        uint32_t b0l = sbl[(kcu + tq) * (BN + 8) + n0];
                        uint32_t b1l = sbl[(kcu + tq + 4) * (BN + 8) + n0];
#pragma unroll
                        for (int mt = 0; mt < 4; mt++) {
                            mma16b(acc[mt][nt], ah[mt], b0h, b1h);
                            mma16b(acc[mt][nt], al[mt], b0h, b1h);
                            mma16b(acc[mt][nt], ah[mt], b0l, b1l);
                        }
                    }
                }
            }
        }
    };

    ldg_chunk(0);
    sts_chunk(0);
    __syncthreads();
    for (int c = 0; c < NC; c++) {
        if (c + 1 < NC) ldg_chunk(c + 1);
        compute((c & 1) * STG);
        if (c + 1 < NC) {
            sts_chunk(((c + 1) & 1) * STG);
            __syncthreads();
        }
    }

    if (!HOUT) {
        float* Cf = C + coff;
#pragma unroll
        for (int mt = 0; mt < 4; mt++) {
            const int r0 = wm + mt * 16 + g;
#pragma unroll
            for (int nt = 0; nt < NT; nt++) {
                const int c0 = wn + nt * 8 + tq * 2;
                *(float2*)&Cf[(long)r0 * ldc + c0]       = make_float2(acc[mt][nt][0], acc[mt][nt][1]);
                *(float2*)&Cf[(long)(r0 + 8) * ldc + c0] = make_float2(acc[mt][nt][2], acc[mt][nt][3]);
            }
        }
    } else {
        __half* Ch = ((__half*)C) + coff;
#pragma unroll
        for (int mt = 0; mt < 4; mt++) {
            const int r0 = wm + mt * 16 + g;
#pragma unroll
            for (int nt = 0; nt < NT; nt++) {
                const int c0 = wn + nt * 8 + tq * 2;
                *(__half2*)&Ch[(long)r0 * ldc + c0]       = __floats2half2_rn(acc[mt][nt][0], acc[mt][nt][1]);
                *(__half2*)&Ch[(long)(r0 + 8) * ldc + c0] = __floats2half2_rn(acc[mt][nt][2], acc[mt][nt][3]);
            }
        }
    }
}

// ---------------- fp16 QK^T GEMM, cp.async 3-stage, fused exp + tile stats ----------------
__global__ void __launch_bounds__(256, 2)
qk_gemm(const __half* __restrict__ A, const __half* __restrict__ B, __half* __restrict__ Ph,
        float escale, float* __restrict__ gtmax, float* __restrict__ gtsum)
{
    constexpr int A_ST = 128 * 20;
    constexpr int B_ST = 128 * 20;
    constexpr int STG  = A_ST + B_ST;
    constexpr int NC   = DQK / 32;   // 18

    extern __shared__ uint32_t smu[];
    const uint32_t smem_base = smem_u32(smu);

    const int tid  = threadIdx.x;
    const int warp = tid >> 5;
    const int lane = tid & 31;
    const int wm = (warp >> 2) * 64;
    const int wn = (warp & 3) * 32;
    const int g  = lane >> 2;
    const int tq = lane & 3;
    const int mat = lane >> 3;

    const int bm = blockIdx.y * 128;
    const int bn = blockIdx.x * 128;
    const int z  = blockIdx.z;
    A  += (long)z * QLEN * DQK + (long)bm * DQK;
    B  += (long)bn * DQK;
    Ph += (long)z * QLEN * SLEN + (long)bm * SLEN + bn;

    float acc[4][4][4];
#pragma unroll
    for (int i = 0; i < 4; i++)
#pragma unroll
        for (int j = 0; j < 4; j++)
#pragma unroll
            for (int l = 0; l < 4; l++) acc[i][j][l] = 0.f;

    auto cp_chunk = [&](int c, int stg) {
        const uint32_t sa = smem_base + (uint32_t)(stg * STG) * 4;
        const uint32_t sb = sa + A_ST * 4;
        const __half* ga = A + c * 32;
        const __half* gb = B + c * 32;
#pragma unroll
        for (int i = 0; i < 2; i++) {
            int o = tid + i * 256;
            int r = o >> 2, cu = (o & 3) * 4;
            cp16(sa + (uint32_t)(r * 20 + cu) * 4, ga + (long)r * DQK + cu * 2);
            cp16(sb + (uint32_t)(r * 20 + cu) * 4, gb + (long)r * DQK + cu * 2);
        }
    };

    auto compute = [&](int stg) {
        const uint32_t aB = smem_base + (uint32_t)(stg * STG) * 4;
        const uint32_t bB = aB + A_ST * 4;
#pragma unroll
        for (int kk = 0; kk < 2; kk++) {
            const int kcu = kk * 8;
            uint32_t af[4][4];
#pragma unroll
            for (int mt = 0; mt < 4; mt++) {
                int row = wm + mt * 16 + ((mat & 1) << 3) + (lane & 7);
                int col = kcu + ((mat >> 1) << 2);
                ldm_x4(af[mt], aB + (uint32_t)(row * 20 + col) * 4);
            }
#pragma unroll
            for (int np = 0; np < 2; np++) {
                uint32_t bf[4];
                int row = wn + (2 * np + (mat >> 1)) * 8 + (lane & 7);
                int col = kcu + ((mat & 1) << 2);
                ldm_x4(bf, bB + (uint32_t)(row * 20 + col) * 4);
#pragma unroll
                for (int mt = 0; mt < 4; mt++) {
                    mma16h(acc[mt][2 * np],     af[mt], bf[0], bf[1]);
                    mma16h(acc[mt][2 * np + 1], af[mt], bf[2], bf[3]);
                }
            }
        }
    };

    cp_chunk(0, 0); CP_COMMIT();
    cp_chunk(1, 1); CP_COMMIT();
    for (int c = 0; c < NC; c++) {
        CP_WAIT(1);
        __syncthreads();
        if (c + 2 < NC) cp_chunk(c + 2, (c + 2) % 3);
        CP_COMMIT();
        compute(c % 3);
    }

    float* st_max = (float*)(smu + 3 * STG);
    float* st_sum = st_max + 512;
    const int nw = warp & 3;
    __syncthreads();
#pragma unroll
    for (int mt = 0; mt < 4; mt++) {
#pragma unroll
        for (int h = 0; h < 2; h++) {
            float mx = -INFINITY;
#pragma unroll
            for (int nt = 0; nt < 4; nt++) {
                mx = fmaxf(mx, acc[mt][nt][2 * h]);
                mx = fmaxf(mx, acc[mt][nt][2 * h + 1]);
            }
            mx = fmaxf(mx, __shfl_xor_sync(0xffffffffu, mx, 1));
            mx = fmaxf(mx, __shfl_xor_sync(0xffffffffu, mx, 2));
            if (tq == 0) st_max[(wm + mt * 16 + h * 8 + g) * 4 + nw] = mx * escale;
        }
    }
    __syncthreads();
#pragma unroll
    for (int mt = 0; mt < 4; mt++) {
#pragma unroll
        for (int h = 0; h < 2; h++) {
            const int row = wm + mt * 16 + h * 8 + g;
            float rm = fmaxf(fmaxf(st_max[row * 4 + 0], st_max[row * 4 + 1]),
                             fmaxf(st_max[row * 4 + 2], st_max[row * 4 + 3]));
            float s = 0.f;
#pragma unroll
            for (int nt = 0; nt < 4; nt++) {
                float p0 = __expf(fmaf(acc[mt][nt][2 * h],     escale, -rm));
                float p1 = __expf(fmaf(acc[mt][nt][2 * h + 1], escale, -rm));
                s += p0 + p1;
                *(__half2*)&Ph[(long)row * SLEN + wn + nt * 8 + tq * 2] =
                    __floats2half2_rn(p0, p1);
            }
            s += __shfl_xor_sync(0xffffffffu, s, 1);
            s += __shfl_xor_sync(0xffffffffu, s, 2);
            if (tq == 0) st_sum[row * 4 + nw] = s;
        }
    }
    __syncthreads();
    if (tid < 128) {
        float m = fmaxf(fmaxf(st_max[tid * 4 + 0], st_max[tid * 4 + 1]),
                        fmaxf(st_max[tid * 4 + 2], st_max[tid * 4 + 3]));
        float s = st_sum[tid * 4 + 0] + st_sum[tid * 4 + 1]
                + st_sum[tid * 4 + 2] + st_sum[tid * 4 + 3];
        long grow = (long)z * QLEN + bm + tid;
        gtmax[grow * NTILES_S + blockIdx.x] = m;
        gtsum[grow * NTILES_S + blockIdx.x] = s;
    }
}

// ---------------- fp16 PV GEMM, cp.async 3-stage k64 chunks, in-register rescale ----------------
__global__ void __launch_bounds__(256, 2)
pv_gemm(const __half* __restrict__ A, const __half* __restrict__ B, __half* __restrict__ C,
        const float* __restrict__ tmax, const float* __restrict__ rowm,
        const float* __restrict__ rowis)
{
    constexpr int A_ST = 128 * 36;    // k64 chunk: 32 u32 data + 4 pad per row
    constexpr int B_ST = 128 * 36;
    constexpr int STG  = A_ST + B_ST;
    constexpr int NC   = SLEN / 64;   // 64 chunks

    extern __shared__ uint32_t smu[];
    const uint32_t smem_base = smem_u32(smu);

    const int tid  = threadIdx.x;
    const int warp = tid >> 5;
    const int lane = tid & 31;
    const int wm = (warp >> 2) * 64;
    const int wn = (warp & 3) * 32;
    const int g  = lane >> 2;
    const int tq = lane & 3;
    const int mat = lane >> 3;

    const int bm = blockIdx.y * 128;
    const int bn = blockIdx.x * 128;
    const int z  = blockIdx.z;
    A += (long)z * QLEN * SLEN + (long)bm * SLEN;
    B += (long)bn * SLEN;
    C += (long)z * QLEN * RKV + (long)bm * RKV + bn;

    const long gbase = (long)z * QLEN + bm;
    float rm_[4][2], ris_[4][2];
#pragma unroll
    for (int mt = 0; mt < 4; mt++) {
        int r0 = wm + mt * 16 + g;
        rm_[mt][0]  = rowm[gbase + r0];
        rm_[mt][1]  = rowm[gbase + r0 + 8];
        ris_[mt][0] = rowis[gbase + r0];
        ris_[mt][1] = rowis[gbase + r0 + 8];
    }
    const float* tmax_b = tmax + gbase * NTILES_S;

    float acc[4][4][4];
#pragma unroll
    for (int i = 0; i < 4; i++)
#pragma unroll
        for (int j = 0; j < 4; j++)
#pragma unroll
            for (int l = 0; l < 4; l++) acc[i][j][l] = 0.f;

    uint32_t fac[4][2];

    auto upd_fac = [&](int tile) {
#pragma unroll
        for (int mt = 0; mt < 4; mt++) {
            int r0 = wm + mt * 16 + g;
            float f0 = __expf(tmax_b[(long)r0 * NTILES_S + tile] - rm_[mt][0]) * ris_[mt][0];
            float f1 = __expf(tmax_b[(long)(r0 + 8) * NTILES_S + tile] - rm_[mt][1]) * ris_[mt][1];
            __half2 h0 = __half2half2(__float2half_rn(f0));
            __half2 h1 = __half2half2(__float2half_rn(f1));
            fac[mt][0] = *(uint32_t*)&h0;
            fac[mt][1] = *(uint32_t*)&h1;
        }
    };

    auto cp_chunk = [&](int c, int stg) {
        const uint32_t sa = smem_base + (uint32_t)(stg * STG) * 4;
        const uint32_t sb = sa + A_ST * 4;
        const __half* ga = A + c * 64;
        const __half* gb = B + c * 64;
#pragma unroll
        for (int i = 0; i < 4; i++) {
            int o = tid + i * 256;           // 0..1023
            int r = o >> 3, cu = (o & 7) * 4;
            cp16(sa + (uint32_t)(r * 36 + cu) * 4, ga + (long)r * SLEN + cu * 2);
            cp16(sb + (uint32_t)(r * 36 + cu) * 4, gb + (long)r * SLEN + cu * 2);
        }
    };

    auto compute = [&](int stg) {
        const uint32_t aB = smem_base + (uint32_t)(stg * STG) * 4;
        const uint32_t bB = aB + A_ST * 4;
#pragma unroll
        for (int kk = 0; kk < 4; kk++) {
            const int kcu = kk * 8;
            uint32_t af[4][4];
#pragma unroll
            for (int mt = 0; mt < 4; mt++) {
                int row = wm + mt * 16 + ((mat & 1) << 3) + (lane & 7);
                int col = kcu + ((mat >> 1) << 2);
                ldm_x4(af[mt], aB + (uint32_t)(row * 36 + col) * 4);
                __half2 f0 = *(__half2*)&fac[mt][0];
                __half2 f1 = *(__half2*)&fac[mt][1];
                *(__half2*)&af[mt][0] = __hmul2(*(__half2*)&af[mt][0], f0);
                *(__half2*)&af[mt][2] = __hmul2(*(__half2*)&af[mt][2], f0);
                *(__half2*)&af[mt][1] = __hmul2(*(__half2*)&af[mt][1], f1);
                *(__half2*)&af[mt][3] = __hmul2(*(__half2*)&af[mt][3], f1);
            }
#pragma unroll
            for (int np = 0; np < 2; np++) {
                uint32_t bf[4];
                int row = wn + (2 * np + (mat >> 1)) * 8 + (lane & 7);
                int col = kcu + ((mat & 1) << 2);
                ldm_x4(bf, bB + (uint32_t)(row * 36 + col) * 4);
#pragma unroll
                for (int mt = 0; mt < 4; mt++) {
                    mma16h(acc[mt][2 * np],     af[mt], bf[0], bf[1]);
                    mma16h(acc[mt][2 * np + 1], af[mt], bf[2], bf[3]);
                }
            }
        }
    };

    cp_chunk(0, 0); CP_COMMIT();
    cp_chunk(1, 1); CP_COMMIT();
    for (int c = 0; c < NC; c++) {
        CP_WAIT(1);
        __syncthreads();
        if (c + 2 < NC) cp_chunk(c + 2, (c + 2) % 3);
        CP_COMMIT();
        if ((c & 1) == 0) upd_fac(c >> 1);   // tile = 128 k = 2 chunks
        compute(c % 3);
    }

#pragma unroll
    for (int mt = 0; mt < 4; mt++) {
        const int r0 = wm + mt * 16 + g;
#pragma unroll
        for (int nt = 0; nt < 4; nt++) {
            const int c0 = wn + nt * 8 + tq * 2;
            *(__half2*)&C[(long)r0 * RKV + c0]       = __floats2half2_rn(acc[mt][nt][0], acc[mt][nt][1]);
            *(__half2*)&C[(long)(r0 + 8) * RKV + c0] = __floats2half2_rn(acc[mt][nt][2], acc[mt][nt][3]);
        }
    }
}

// ---------------- OV GEMM: ao[:, h*128:] = och[h] @ outabsorb[h]^T ----------------
__global__ void __launch_bounds__(256, 2)
ov_gemm(const __half* __restrict__ A, const float* __restrict__ B, float* __restrict__ C,
        long sB)
{
    constexpr int A_ST = 128 * 20;
    constexpr int B_ST = 2 * 128 * 20;
    constexpr int STG  = A_ST + B_ST;
    constexpr int NC   = RKV / 32;

    extern __shared__ uint32_t smu[];
    const uint32_t smem_base = smem_u32(smu);

    const int tid  = threadIdx.x;
    const int warp = tid >> 5;
    const int lane = tid & 31;
    const int wm = (warp >> 2) * 64;
    const int wn = (warp & 3) * 32;
    const int g  = lane >> 2;
    const int tq = lane & 3;
    const int mat = lane >> 3;

    const int bm = blockIdx.y * 128;
    const int z  = blockIdx.z;
    A += (long)z * QLEN * RKV + (long)bm * RKV;
    B += (long)z * sB;
    C += (long)z * DNOPE + (long)bm * AO_COLS;

    float acc[4][4][4];
#pragma unroll
    for (int i = 0; i < 4; i++)
#pragma unroll
        for (int j = 0; j < 4; j++)
#pragma unroll
            for (int l = 0; l < 4; l++) acc[i][j][l] = 0.f;

    float4 rB[4];

    auto cpA_chunk = [&](int c, int stg) {
        const uint32_t sa = smem_base + (uint32_t)(stg * STG) * 4;
        const __half* ga = A + c * 32;
#pragma unroll
        for (int i = 0; i < 2; i++) {
            int o = tid + i * 256;
            int r = o >> 2, cu = (o & 3) * 4;
            cp16(sa + (uint32_t)(r * 20 + cu) * 4, ga + (long)r * RKV + cu * 2);
        }
    };

    auto ldgB_chunk = [&](int c) {
        const float* gb = B + c * 32;
#pragma unroll
        for (int i = 0; i < 4; i++) {
            int o = tid + i * 256;
            int r = o >> 3, c4 = (o & 7) << 2;
            rB[i] = *(const float4*)(gb + (long)r * RKV + c4);
        }
    };

    auto stsB_chunk = [&](int stg) {
        uint32_t* sbh = smu + stg * STG + A_ST;
        uint32_t* sbl = sbh + 128 * 20;
#pragma unroll
        for (int i = 0; i < 4; i++) {
            int o = tid + i * 256;
            int r = o >> 3, cu = (o & 7) << 1;
            float4 v = rB[i];
            __half2 h0 = __floats2half2_rn(v.x, v.y);
            __half2 h1 = __floats2half2_rn(v.z, v.w);
            __half2 l0 = __floats2half2_rn(v.x - __half2float(h0.x), v.y - __half2float(h0.y));
            __half2 l1 = __floats2half2_rn(v.z - __half2float(h1.x), v.w - __half2float(h1.y));
            *(uint2*)&sbh[r * 20 + cu] = make_uint2(*(uint32_t*)&h0, *(uint32_t*)&h1);
            *(uint2*)&sbl[r * 20 + cu] = make_uint2(*(uint32_t*)&l0, *(uint32_t*)&l1);
        }
    };

    auto compute = [&](int stg) {
        const uint32_t aB  = smem_base + (uint32_t)(stg * STG) * 4;
        const uint32_t bBh = aB + A_ST * 4;
        const uint32_t bBl = bBh + 128 * 20 * 4;
#pragma unroll
        for (int kk = 0; kk < 2; kk++) {
            const int kcu = kk * 8;
            uint32_t af[4][4];
#pragma unroll
            for (int mt = 0; mt < 4; mt++) {
                int row = wm + mt * 16 + ((mat & 1) << 3) + (lane & 7);
                int col = kcu + ((mat >> 1) << 2);
                ldm_x4(af[mt], aB + (uint32_t)(row * 20 + col) * 4);
            }
#pragma unroll
            for (int np = 0; np < 2; np++) {
                uint32_t bh[4], bl[4];
                int row = wn + (2 * np + (mat >> 1)) * 8 + (lane & 7);
                int col = kcu + ((mat & 1) << 2);
                ldm_x4(bh, bBh + (uint32_t)(row * 20 + col) * 4);
                ldm_x4(bl, bBl + (uint32_t)(row * 20 + col) * 4);
#pragma unroll
                for (int mt = 0; mt < 4; mt++) {
                    mma16h(acc[mt][2 * np],     af[mt], bh[0], bh[1]);
                    mma16h(acc[mt][2 * np],     af[mt], bl[0], bl[1]);
                    mma16h(acc[mt][2 * np + 1], af[mt], bh[2], bh[3]);
                    mma16h(acc[mt][2 * np + 1], af[mt], bl[2], bl[3]);
                }
            }
        }
    };

    ldgB_chunk(0);
    cpA_chunk(0, 0); CP_COMMIT();
    stsB_chunk(0);
    CP_WAIT(0);
    __syncthreads();
    for (int c = 0; c < NC; c++) {
        if (c + 1 < NC) { ldgB_chunk(c + 1); cpA_chunk(c + 1, (c + 1) & 1); }
        CP_COMMIT();
        compute(c & 1);
        if (c + 1 < NC) {
            stsB_chunk((c + 1) & 1);
            CP_WAIT(0);
            __syncthreads();
        }
    }

#pragma unroll
    for (int mt = 0; mt < 4; mt++) {
        const int r0 = wm + mt * 16 + g;
#pragma unroll
        for (int nt = 0; nt < 4; nt++) {
            const int c0 = wn + nt * 8 + tq * 2;
            *(float2*)&C[(long)r0 * AO_COLS + c0]       = make_float2(acc[mt][nt][0], acc[mt][nt][1]);
            *(float2*)&C[(long)(r0 + 8) * AO_COLS + c0] = make_float2(acc[mt][nt][2], acc[mt][nt][3]);
        }
    }
}

// ---------------- Combine tile stats ----------------
__global__ void combine_stats(const float* __restrict__ tmax, const float* __restrict__ tsum,
                              float* __restrict__ rm, float* __restrict__ ris)
{
    const int row = blockIdx.x * 8 + threadIdx.y;
    const int t = threadIdx.x;
    float mv = tmax[(long)row * NTILES_S + t];
    float m = mv;
#pragma unroll
    for (int o = 16; o > 0; o >>= 1) m = fmaxf(m, __shfl_xor_sync(0xffffffffu, m, o));
    float s = tsum[(long)row * NTILES_S + t] * __expf(mv - m);
#pragma unroll
    for (int o = 16; o > 0; o >>= 1) s += __shfl_xor_sync(0xffffffffu, s, o);
    if (t == 0) { rm[row] = m; ris[row] = 1.f / s; }
}

// ---------------- Transpose half->half ----------------
__global__ void transpose_hh(const __half* __restrict__ in, __half* __restrict__ out,
                             int R, int ldin)
{
    __shared__ __half t[32][40];
    const int c0 = blockIdx.x * 32, r0 = blockIdx.y * 32;
    const int x = threadIdx.x, y0 = threadIdx.y;
    #pragma unroll
    for (int i = y0; i < 32; i += 8) t[i][x] = in[(long)(r0 + i) * ldin + c0 + x];
    __syncthreads();
    #pragma unroll
    for (int i = y0; i < 32; i += 8) out[(long)(c0 + i) * R + r0 + x] = t[x][i];
}

// ---------------- Split-K reduction ----------------
__global__ void reduce_slices(const float4* __restrict__ in, float4* __restrict__ out,
                              int n4, int S)
{
    int i = blockIdx.x * 256 + threadIdx.x;
    if (i >= n4) return;
    float4 a = in[i];
    for (int s = 1; s < S; s++) {
        float4 b = in[i + (long)s * n4];
        a.x += b.x; a.y += b.y; a.z += b.z; a.w += b.w;
    }
    out[i] = a;
}

// ---------------- RMSNorm (in place) ----------------
__global__ void rmsnorm_rows(float* __restrict__ X, const float* __restrict__ g, int cols)
{
    const long row = blockIdx.x;
    float* x = X + row * (long)cols;
    const int tid = threadIdx.x;
    const int n4 = cols >> 2;
    float ss = 0.f;
    for (int c = tid; c < n4; c += blockDim.x) {
        float4 v = ((const float4*)x)[c];
        ss += v.x * v.x + v.y * v.y + v.z * v.z + v.w * v.w;
    }
    __shared__ float red[256];
    red[tid] = ss; __syncthreads();
    for (int s = 128; s > 0; s >>= 1) { if (tid < s) red[tid] += red[tid + s]; __syncthreads(); }
    const float inv = rsqrtf(red[0] / (float)cols + EPSF);
    for (int c = tid; c < n4; c += blockDim.x) {
        float4 v = ((const float4*)x)[c];
        float4 w = ((const float4*)g)[c];
        v.x *= inv * w.x; v.y *= inv * w.y; v.z *= inv * w.z; v.w *= inv * w.w;
        ((float4*)x)[c] = v;
    }
}

// ---------------- Build K_comb -> fp16 ----------------
__global__ void build_K(const float* __restrict__ raw, const float* __restrict__ g,
                        const int* __restrict__ kvpos, __half* __restrict__ Kh)
{
    const int s = blockIdx.x;
    const float* r = raw + (long)s * DQK;
    __half* k = Kh + (long)s * DQK;
    const int tid = threadIdx.x;

    float ss = 0.f;
    for (int c = tid; c < RKV / 4; c += 128) {
        float4 v = ((const float4*)r)[c];
        ss += v.x * v.x + v.y * v.y + v.z * v.z + v.w * v.w;
    }
    __shared__ float red[128];
    red[tid] = ss; __syncthreads();
    for (int st = 64; st > 0; st >>= 1) { if (tid < st) red[tid] += red[tid + st]; __syncthreads(); }
    const float inv = rsqrtf(red[0] / (float)RKV + EPSF);
    for (int c = tid; c < RKV / 4; c += 128) {
        float4 v = ((const float4*)r)[c];
        float4 w = ((const float4*)g)[c];
        __half2 h0 = __floats2half2_rn(v.x * inv * w.x, v.y * inv * w.y);
        __half2 h1 = __floats2half2_rn(v.z * inv * w.z, v.w * inv * w.w);
        *(__half2*)&k[c * 4]     = h0;
        *(__half2*)&k[c * 4 + 2] = h1;
    }

    if (tid < 32) {
        const int j = tid;
        const float x0 = r[RKV + 2 * j];
        const float x1 = r[RKV + 2 * j + 1];
        const float pos = (float)kvpos[s];
        const float invf = powf(10000.f, -(float)j / 32.f);
        float cs, sn; sincosf(pos * invf, &sn, &cs);
        k[RKV + j]      = __float2half_rn(x0 * cs - x1 * sn);
        k[RKV + 32 + j] = __float2half_rn(x0 * sn + x1 * cs);
    }
}

// ---------------- RoPE for q_pe -> fp16 ----------------
__global__ void rope_Q(const float* __restrict__ qfull, const int* __restrict__ qpos,
                       __half* __restrict__ Qh)
{
    const int t = blockIdx.x;
    const int h = blockIdx.y;
    const int j = threadIdx.x;
    const float* src = qfull + (long)t * QB_COLS + h * (DNOPE + DROPE) + DNOPE;
    const float x0 = src[2 * j];
    const float x1 = src[2 * j + 1];
    const float pos = (float)qpos[t];
    const float invf = powf(10000.f, -(float)j / 32.f);
    float cs, sn; sincosf(pos * invf, &sn, &cs);
    __half* dst = Qh + ((long)h * QLEN + t) * DQK + RKV;
    dst[j]      = __float2half_rn(x0 * cs - x1 * sn);
    dst[32 + j] = __float2half_rn(x0 * sn + x1 * cs);
}

// ---------------- Launch ----------------
static inline void* symv(const void* s)
{
    void* p = nullptr;
    cudaGetSymbolAddress(&p, s);
    return p;
}

static inline int smem_b(int NT, bool transb, int prec)
{
    int a = (prec == 0) ? 128 * 36 : 128 * 40;
    int b = transb ? ((prec == 0) ? NT * 32 * 36 : NT * 32 * 40)
                   : 32 * (NT * 32 + 8);
    return 2 * (a + b) * 4;
}
#define SMEM_PV (3 * (128 * 36 + 128 * 36) * 4)
#define SMEM_QK (3 * (128 * 20 + 128 * 20) * 4 + 4096)
#define SMEM_OV (2 * (128 * 20 + 2 * 128 * 20) * 4)

extern "C" void kernel_launch(void* const* d_in, const int* in_sizes, int n_in,
                              void* d_out, int out_size)
{
    const float* hq    = (const float*)d_in[0];
    const float* hkv   = (const float*)d_in[1];
    const float* W_qa  = (const float*)d_in[2];
    const float* gqa   = (const float*)d_in[3];
    const float* W_qb  = (const float*)d_in[4];
    const float* W_kva = (const float*)d_in[5];
    const float* gkva  = (const float*)d_in[6];
    const float* W_kvb = (const float*)d_in[7];
    const float* W_o   = (const float*)d_in[8];
    const int*   qpos  = (const int*)d_in[9];
    const int*   kvpos = (const int*)d_in[10];
    float*       out   = (float*)d_out;

    float*  qa     = (float*) symv(g_qa_buf);
    float*  qfull  = (float*) symv(g_qfull);
    float*  ckvraw = (float*) symv(g_ckvraw);
    __half* Kch    = (__half*)symv(g_Kch);
    __half* ckvTh  = (__half*)symv(g_ckvTh);
    __half* Qch    = (__half*)symv(g_Qch);
    __half* P      = (__half*)symv(g_P);
    __half* och    = (__half*)symv(g_och);
    float*  ao     = (float*) symv(g_ao);
    float*  part   = (float*) symv(g_part);
    float*  rowm   = (float*) symv(g_rowm);
    float*  rowis  = (float*) symv(g_rowis);
    float*  tmax   = (float*) symv(g_tmax);
    float*  tsum   = (float*) symv(g_tsum);

    const float scale = 1.0f / sqrtf(192.0f);

    static cudaStream_t s2 = nullptr, s3 = nullptr;
    static cudaEvent_t evF = nullptr, evKV = nullptr, evRN = nullptr, evG1 = nullptr;
    if (!s2) {
        cudaStreamCreateWithFlags(&s2, cudaStreamNonBlocking);
        cudaStreamCreateWithFlags(&s3, cudaStreamNonBlocking);
        cudaEventCreateWithFlags(&evF,  cudaEventDisableTiming);
        cudaEventCreateWithFlags(&evKV, cudaEventDisableTiming);
        cudaEventCreateWithFlags(&evRN, cudaEventDisableTiming);
        cudaEventCreateWithFlags(&evG1, cudaEventDisableTiming);
        cudaFuncSetAttribute(mma_gemm<4, false, 1, 0>, cudaFuncAttributeMaxDynamicSharedMemorySize, smem_b(4, false, 1));
        cudaFuncSetAttribute(mma_gemm<4, false, 1, 1>, cudaFuncAttributeMaxDynamicSharedMemorySize, smem_b(4, false, 1));
        cudaFuncSetAttribute(mma_gemm<3, false, 1, 0>, cudaFuncAttributeMaxDynamicSharedMemorySize, smem_b(3, false, 1));
        cudaFuncSetAttribute(qk_gemm, cudaFuncAttributeMaxDynamicSharedMemorySize, SMEM_QK);
        cudaFuncSetAttribute(pv_gemm, cudaFuncAttributeMaxDynamicSharedMemorySize, SMEM_PV);
        cudaFuncSetAttribute(ov_gemm, cudaFuncAttributeMaxDynamicSharedMemorySize, SMEM_OV);
    }

    // ---- fork: KV path on s2 ----
    cudaEventRecord(evF, 0);
    cudaStreamWaitEvent(s2, evF, 0);

    mma_gemm<3, false, 1, 0><<<dim3(DQK / 96, SLEN / 128, 1), 256, smem_b(3, false, 1), s2>>>(
        hkv, W_kva, ckvraw, HID, HID, DQK, DQK, 0, 0, 0);
    build_K<<<SLEN, 128, 0, s2>>>(ckvraw, gkva, kvpos, Kch);
    transpose_hh<<<dim3(RKV / 32, SLEN / 32), dim3(32, 8), 0, s2>>>(Kch, ckvTh, SLEN, DQK);
    cudaEventRecord(evKV, s2);

    // ---- Q path head on default stream ----
    mma_gemm<4, false, 1, 0><<<dim3(RQ / 128, 2, 8), 256, smem_b(4, false, 1)>>>(
        hq, W_qa, part, HID / 8, HID, RQ, RQ,
        (long)(HID / 8), (long)(HID / 8) * RQ, (long)QLEN * RQ);
    reduce_slices<<<(QLEN * RQ / 4 + 255) / 256, 256>>>((const float4*)part, (float4*)qa, QLEN * RQ / 4, 8);
    rmsnorm_rows<<<QLEN, 256>>>(qa, gqa, RQ);
    cudaEventRecord(evRN, 0);
    cudaStreamWaitEvent(s3, evRN, 0);

    // ---- per-head-group chains: step-3 half + attention (g0 stream 0, g1 s3) ----
    const long zb[2] = { 0, HGRP };
    cudaStream_t gs[2] = { (cudaStream_t)0, s3 };
    for (int grp = 0; grp < 2; grp++) {
        cudaStream_t st = gs[grp];
        const long z0 = zb[grp];
        const long qcol = z0 * (DNOPE + DROPE);     // qfull column offset for group
        const long qko = z0 * QLEN * DQK;
        const long po  = z0 * QLEN * SLEN;
        const long to  = z0 * QLEN * NTILES_S;
        const long ro  = z0 * QLEN;
        const long oo  = z0 * QLEN * RKV;

        // 3g) qfull[:, group cols] = qa @ W_qb[:, group cols]
        mma_gemm<4, false, 1, 0><<<dim3(HGRP * (DNOPE + DROPE) / 128, 2, 1), 256, smem_b(4, false, 1), st>>>(
            qa, W_qb + qcol, qfull + qcol, RQ, RQ, QB_COLS, QB_COLS, 0, 0, 0);

        // 6) Qch[:, :512] = q_nope @ q_absorb
        mma_gemm<4, false, 1, 1><<<dim3(RKV / 128, 2, HGRP), 256, smem_b(4, false, 1), st>>>(
            qfull + qcol, W_kvb + z0 * (long)(DNOPE + DNOPE) * RKV,
            (float*)(Qch + qko), DNOPE,
            QB_COLS, RKV, DQK,
            (long)(DNOPE + DROPE), (long)(DNOPE + DNOPE) * RKV, (long)QLEN * DQK);

        // 7) rope q_pe
        rope_Q<<<dim3(QLEN, HGRP), 32, 0, st>>>(
            qfull + qcol, qpos, Qch + qko);

        cudaStreamWaitEvent(st, evKV, 0);

        // 8) qk
        qk_gemm<<<dim3(SLEN / 128, QLEN / 128, HGRP), 256, SMEM_QK, st>>>(
            Qch + qko, Kch, P + po, scale, tmax + to, tsum + to);

        // 9) combine
        combine_stats<<<HGRP * QLEN / 8, dim3(32, 8), 0, st>>>(
            tmax + to, tsum + to, rowm + ro, rowis + ro);

        // 10) pv (cp.async k64 + in-register rescale)
        pv_gemm<<<dim3(RKV / 128, QLEN / 128, HGRP), 256, SMEM_PV, st>>>(
            P + po, ckvTh, och + oo, tmax + to, rowm + ro, rowis + ro);

        // 11) ov
        ov_gemm<<<dim3(1, 2, HGRP), 256, SMEM_OV, st>>>(
            och + oo, W_kvb + (long)DNOPE * RKV + z0 * (long)(DNOPE + DNOPE) * RKV,
            ao + z0 * DNOPE, (long)(DNOPE + DNOPE) * RKV);

        // 12a) partial out: ao[:, grp half] @ W_o[grp rows], split-K 2
        mma_gemm<4, false, 1, 0><<<dim3(HID / 128, 2, 2), 256, smem_b(4, false, 1), st>>>(
            ao + z0 * DNOPE, W_o + z0 * DNOPE * (long)HID, part + grp * 2 * (long)QLEN * HID,
            AO_COLS / 4, AO_COLS, HID, HID,
            (long)(AO_COLS / 4), (long)(AO_COLS / 4) * HID, (long)QLEN * HID);
    }
    cudaEventRecord(evG1, s3);
    cudaStreamWaitEvent(0, evG1, 0);

    // 12b) reduce 4 partial slices -> out
    reduce_slices<<<(QLEN * HID / 4 + 255) / 256, 256>>>((const float4*)part, (float4*)out, QLEN * HID / 4, 4);
}